// round 2
// baseline (speedup 1.0000x reference)
#include <cuda_runtime.h>
#include <cuda_bf16.h>
#include <cstdint>

// Problem constants
#define BB 4
#define TT 2048
#define EE 1024
#define DD 128
#define HH 8
#define MM (BB * TT)   // 8192 rows

// ---------------- scratch (static device memory; no allocation) ----------------
__device__ float g_q[MM * EE];     // silu(x@wq)
__device__ float g_k[MM * EE];     // sigmoid(x@wk)
__device__ float g_v[MM * EE];     // x@wv
__device__ float g_att[MM * EE];   // scan output
__device__ float g_g1[MM * DD];    // x@wg1
__device__ float g_gate[MM * EE];  // sigmoid(g1@wg2)
__device__ float g_y[MM * EE];     // gated + layernormed

// ---------------- fp32 tiled GEMM: C = act(A[M,K] @ B[K,N]) ----------------
// BMt=128, BNt=128, BKt=16, 256 threads, 8x8 per thread. M,N%128==0, K%16==0.
#define BMt 128
#define BNt 128
#define BKt 16

template <int ACT>
__global__ void __launch_bounds__(256)
gemm_kernel(const float* __restrict__ A, const float* __restrict__ Bm,
            float* __restrict__ C, int M, int N, int K) {
    __shared__ float As[BKt][BMt + 4];
    __shared__ float Bs[BKt][BNt + 4];

    const int tid  = threadIdx.x;
    const int row0 = blockIdx.y * BMt;
    const int col0 = blockIdx.x * BNt;
    const int ty = tid >> 4;        // 0..15
    const int tx = tid & 15;        // 0..15

    const int arow = tid >> 2;          // 0..63
    const int acol = (tid & 3) << 2;    // 0,4,8,12
    const int brow = tid >> 5;          // 0..7
    const int bcol = (tid & 31) << 2;   // 0..124

    float acc[8][8];
#pragma unroll
    for (int i = 0; i < 8; i++)
#pragma unroll
        for (int j = 0; j < 8; j++) acc[i][j] = 0.0f;

    for (int k0 = 0; k0 < K; k0 += BKt) {
        // load A tile (BMt x BKt), store transposed As[k][m]
#pragma unroll
        for (int r = 0; r < BMt; r += 64) {
            float4 a4 = *(const float4*)&A[(size_t)(row0 + arow + r) * K + k0 + acol];
            As[acol + 0][arow + r] = a4.x;
            As[acol + 1][arow + r] = a4.y;
            As[acol + 2][arow + r] = a4.z;
            As[acol + 3][arow + r] = a4.w;
        }
        // load B tile (BKt x BNt)
#pragma unroll
        for (int r = 0; r < BKt; r += 8) {
            float4 b4 = *(const float4*)&Bm[(size_t)(k0 + brow + r) * N + col0 + bcol];
            *(float4*)&Bs[brow + r][bcol] = b4;
        }
        __syncthreads();

#pragma unroll
        for (int kk = 0; kk < BKt; kk++) {
            float a[8], b[8];
            *(float4*)&a[0] = *(float4*)&As[kk][ty * 8];
            *(float4*)&a[4] = *(float4*)&As[kk][ty * 8 + 4];
            *(float4*)&b[0] = *(float4*)&Bs[kk][tx * 8];
            *(float4*)&b[4] = *(float4*)&Bs[kk][tx * 8 + 4];
#pragma unroll
            for (int i = 0; i < 8; i++)
#pragma unroll
                for (int j = 0; j < 8; j++)
                    acc[i][j] = fmaf(a[i], b[j], acc[i][j]);
        }
        __syncthreads();
    }

    // epilogue with activation
#pragma unroll
    for (int i = 0; i < 8; i++) {
        float out[8];
#pragma unroll
        for (int j = 0; j < 8; j++) {
            float v = acc[i][j];
            if (ACT == 1) v = v / (1.0f + expf(-v));        // silu
            else if (ACT == 2) v = 1.0f / (1.0f + expf(-v)); // sigmoid
            out[j] = v;
        }
        float* cp = &C[(size_t)(row0 + ty * 8 + i) * N + col0 + tx * 8];
        *(float4*)&cp[0] = *(float4*)&out[0];
        *(float4*)&cp[4] = *(float4*)&out[4];
    }
}

// ---------------- GLA scan ----------------
// grid: (8 dv-blocks, H, B), block 128 threads (4 warps).
// Warp handles 4 dv columns; lane owns dk rows {4*lane..4*lane+3}.
// Recurrence (cos-half only, c_t = (-1)^(t+1)):
//   S[dk][dv] = f[dk]*S + (k[dk]*c)*v[dv];  o[dv] = (1/16)*sum_dk (q[dk]*c)*S
__global__ void __launch_bounds__(128)
scan_kernel(const float* __restrict__ q, const float* __restrict__ k,
            const float* __restrict__ v, float* __restrict__ att) {
    const int lane = threadIdx.x & 31;
    const int warp = threadIdx.x >> 5;
    const int dvb  = blockIdx.x;   // 0..7
    const int h    = blockIdx.y;
    const int b    = blockIdx.z;
    const int dv0  = dvb * 16 + warp * 4;

    const size_t base = ((size_t)b * TT * HH + h) * DD;  // [b][0][h][0]
    const int STR = EE / 4;                              // float4 stride per t

    const float4* qp = (const float4*)(q + base) + lane;
    const float4* kp = (const float4*)(k + base) + lane;
    const float4* vp = (const float4*)(v + base) + (dv0 >> 2);
    float4*       op = (float4*)(att + base) + (dv0 >> 2);

    float s[4][4];
#pragma unroll
    for (int i = 0; i < 4; i++)
#pragma unroll
        for (int j = 0; j < 4; j++) s[i][j] = 0.0f;

    // 1-step register prefetch
    float4 qn = qp[0], kn = kp[0], vn = vp[0];

    for (int t = 0; t < TT; ++t) {
        float4 qc = qn, kc = kn, vv = vn;
        int tn = (t + 1 < TT) ? t + 1 : t;
        qn = qp[(size_t)tn * STR];
        kn = kp[(size_t)tn * STR];
        vn = vp[(size_t)tn * STR];

        const float c  = (t & 1) ? 1.0f : -1.0f;   // (-1)^(t+1)
        const float qs = c * 0.0625f;              // scale = (2d)^(-1/2) = 1/16

        float f[4]  = {1.0f - kc.x, 1.0f - kc.y, 1.0f - kc.z, 1.0f - kc.w};
        float kk4[4] = {kc.x * c, kc.y * c, kc.z * c, kc.w * c};
        float qq[4]  = {qc.x * qs, qc.y * qs, qc.z * qs, qc.w * qs};
        float vj[4]  = {vv.x, vv.y, vv.z, vv.w};

        float acc[4] = {0.0f, 0.0f, 0.0f, 0.0f};
#pragma unroll
        for (int i = 0; i < 4; i++) {
#pragma unroll
            for (int j = 0; j < 4; j++) {
                s[i][j] = fmaf(f[i], s[i][j], kk4[i] * vj[j]);
                acc[j]  = fmaf(qq[i], s[i][j], acc[j]);
            }
        }
        // reduce over 32 lanes (all 128 dk rows)
#pragma unroll
        for (int j = 0; j < 4; j++) {
#pragma unroll
            for (int m = 16; m; m >>= 1)
                acc[j] += __shfl_xor_sync(0xffffffffu, acc[j], m);
        }
        if (lane == 0)
            op[(size_t)t * STR] = make_float4(acc[0], acc[1], acc[2], acc[3]);
    }
}

// ---------------- gate multiply + layernorm ----------------
// grid 8192, block 256; each thread owns 4 contiguous columns.
__global__ void __launch_bounds__(256)
gate_ln_kernel(const float* __restrict__ att, const float* __restrict__ gate,
               const float* __restrict__ nw, float* __restrict__ y) {
    const int row = blockIdx.x;
    const int tid = threadIdx.x;
    const int lane = tid & 31, wid = tid >> 5;
    __shared__ float red[8];

    float4 a = ((const float4*)(att + (size_t)row * EE))[tid];
    float4 g = ((const float4*)(gate + (size_t)row * EE))[tid];
    float4 yv;
    yv.x = a.x * g.x; yv.y = a.y * g.y; yv.z = a.z * g.z; yv.w = a.w * g.w;

    // pass 1: mean
    float ssum = yv.x + yv.y + yv.z + yv.w;
#pragma unroll
    for (int m = 16; m; m >>= 1) ssum += __shfl_xor_sync(0xffffffffu, ssum, m);
    if (lane == 0) red[wid] = ssum;
    __syncthreads();
    float tot = 0.0f;
#pragma unroll
    for (int w = 0; w < 8; w++) tot += red[w];
    const float mean = tot * (1.0f / (float)EE);
    __syncthreads();

    // pass 2: variance (two-pass, matches reference)
    float dx = yv.x - mean, dy = yv.y - mean, dz = yv.z - mean, dw = yv.w - mean;
    float ssq = dx * dx + dy * dy + dz * dz + dw * dw;
#pragma unroll
    for (int m = 16; m; m >>= 1) ssq += __shfl_xor_sync(0xffffffffu, ssq, m);
    if (lane == 0) red[wid] = ssq;
    __syncthreads();
    float totsq = 0.0f;
#pragma unroll
    for (int w = 0; w < 8; w++) totsq += red[w];
    const float rstd = rsqrtf(totsq * (1.0f / (float)EE) + 1e-5f);

    float4 w4 = ((const float4*)nw)[tid];
    float4 o;
    o.x = dx * rstd * w4.x;
    o.y = dy * rstd * w4.y;
    o.z = dz * rstd * w4.z;
    o.w = dw * rstd * w4.w;
    ((float4*)(y + (size_t)row * EE))[tid] = o;
}

// ---------------- launch ----------------
extern "C" void kernel_launch(void* const* d_in, const int* in_sizes, int n_in,
                              void* d_out, int out_size) {
    const float* x   = (const float*)d_in[0];
    const float* wq  = (const float*)d_in[1];
    const float* wk  = (const float*)d_in[2];
    const float* wv  = (const float*)d_in[3];
    const float* wo  = (const float*)d_in[4];
    const float* wg1 = (const float*)d_in[5];
    const float* wg2 = (const float*)d_in[6];
    const float* nw  = (const float*)d_in[7];
    float* out = (float*)d_out;

    // resolve scratch symbol addresses (capture-safe, no allocation)
    void *pq, *pk, *pv, *patt, *pg1, *pgate, *py;
    cudaGetSymbolAddress(&pq, g_q);
    cudaGetSymbolAddress(&pk, g_k);
    cudaGetSymbolAddress(&pv, g_v);
    cudaGetSymbolAddress(&patt, g_att);
    cudaGetSymbolAddress(&pg1, g_g1);
    cudaGetSymbolAddress(&pgate, g_gate);
    cudaGetSymbolAddress(&py, g_y);
    float* fq = (float*)pq;   float* fk = (float*)pk;   float* fv = (float*)pv;
    float* fatt = (float*)patt; float* fg1 = (float*)pg1;
    float* fgate = (float*)pgate; float* fy = (float*)py;

    const dim3 blk(256);
    const dim3 grid_big(EE / BNt, MM / BMt);   // (8, 64)
    const dim3 grid_g1(DD / BNt, MM / BMt);    // (1, 64)

    gemm_kernel<1><<<grid_big, blk>>>(x, wq, fq, MM, EE, EE);   // q = silu
    gemm_kernel<2><<<grid_big, blk>>>(x, wk, fk, MM, EE, EE);   // k = sigmoid
    gemm_kernel<0><<<grid_big, blk>>>(x, wv, fv, MM, EE, EE);   // v
    gemm_kernel<0><<<grid_g1,  blk>>>(x, wg1, fg1, MM, DD, EE); // g1

    scan_kernel<<<dim3(8, HH, BB), 128>>>(fq, fk, fv, fatt);

    gemm_kernel<2><<<grid_big, blk>>>(fg1, wg2, fgate, MM, EE, DD); // gate = sigmoid

    gate_ln_kernel<<<MM, blk>>>(fatt, fgate, nw, fy);

    gemm_kernel<0><<<grid_big, blk>>>(fy, wo, out, MM, EE, EE);     // final proj
}

// round 3
// speedup vs baseline: 1.2466x; 1.2466x over previous
#include <cuda_runtime.h>
#include <cuda_bf16.h>
#include <cstdint>

// Problem constants
#define BB 4
#define TT 2048
#define EE 1024
#define DD 128
#define HH 8
#define MM (BB * TT)   // 8192 rows

// ---------------- scratch (static device memory; no allocation) ----------------
__device__ float g_q[MM * EE];
__device__ float g_k[MM * EE];
__device__ float g_v[MM * EE];
__device__ float g_att[MM * EE];
__device__ float g_g1[MM * DD];
__device__ float g_gate[MM * EE];
__device__ float g_y[MM * EE];

// ---------------- bf16x3 tensor-core GEMM ----------------
// C[M,N] = act(A[M,K] @ B[K,N]), all fp32 in gmem.
// Split a = hi + lo (bf16 each); C = Ah*Bh + Ah*Bl + Al*Bh (fp32 accum).
// CTA tile 128x128x32, 256 threads (8 warps), warp tile 64x32.
#define GBM 128
#define GBN 128
#define GBK 32
#define APAD 40    // A smem row stride (bf16 elems) -> conflict-free ldmatrix
#define BPAD 136   // B smem row stride

__device__ __forceinline__ void ldsm4(uint32_t& r0, uint32_t& r1, uint32_t& r2,
                                      uint32_t& r3, uint32_t a) {
    asm volatile("ldmatrix.sync.aligned.m8n8.x4.shared.b16 {%0,%1,%2,%3}, [%4];"
                 : "=r"(r0), "=r"(r1), "=r"(r2), "=r"(r3) : "r"(a));
}
__device__ __forceinline__ void ldsm4t(uint32_t& r0, uint32_t& r1, uint32_t& r2,
                                       uint32_t& r3, uint32_t a) {
    asm volatile("ldmatrix.sync.aligned.m8n8.x4.trans.shared.b16 {%0,%1,%2,%3}, [%4];"
                 : "=r"(r0), "=r"(r1), "=r"(r2), "=r"(r3) : "r"(a));
}
__device__ __forceinline__ void mma16816(float* d, const uint32_t* a, const uint32_t* b) {
    asm volatile("mma.sync.aligned.m16n8k16.row.col.f32.bf16.bf16.f32 "
                 "{%0,%1,%2,%3}, {%4,%5,%6,%7}, {%8,%9}, {%0,%1,%2,%3};"
                 : "+f"(d[0]), "+f"(d[1]), "+f"(d[2]), "+f"(d[3])
                 : "r"(a[0]), "r"(a[1]), "r"(a[2]), "r"(a[3]),
                   "r"(b[0]), "r"(b[1]));
}

__device__ __forceinline__ void split1(__nv_bfloat16* hi, __nv_bfloat16* lo,
                                       int idx, float x) {
    __nv_bfloat16 h = __float2bfloat16(x);
    hi[idx] = h;
    lo[idx] = __float2bfloat16(x - __bfloat162float(h));
}
__device__ __forceinline__ void split4(__nv_bfloat16* hi, __nv_bfloat16* lo,
                                       int idx, float4 v) {
    split1(hi, lo, idx + 0, v.x);
    split1(hi, lo, idx + 1, v.y);
    split1(hi, lo, idx + 2, v.z);
    split1(hi, lo, idx + 3, v.w);
}

template <int ACT>
__device__ __forceinline__ float actf(float v) {
    if (ACT == 1) return v / (1.0f + expf(-v));       // silu
    if (ACT == 2) return 1.0f / (1.0f + expf(-v));    // sigmoid
    return v;
}

template <int ACT>
__global__ void __launch_bounds__(256)
gemm_tc(const float* __restrict__ A, const float* __restrict__ B,
        float* __restrict__ C, int M, int N, int K) {
    __shared__ __nv_bfloat16 Ah[GBM * APAD];
    __shared__ __nv_bfloat16 Al[GBM * APAD];
    __shared__ __nv_bfloat16 Bh[GBK * BPAD];
    __shared__ __nv_bfloat16 Bl[GBK * BPAD];

    const int tid  = threadIdx.x;
    const int warp = tid >> 5, lane = tid & 31;
    const int wm = warp >> 2, wn = warp & 3;     // warp tile origin (wm*64, wn*32)
    const int row0 = blockIdx.y * GBM;
    const int col0 = blockIdx.x * GBN;

    // gmem tile load mapping
    const int arow = tid >> 3;            // 0..31
    const int acol = (tid & 7) * 4;       // 0..28
    const int brow = tid >> 3;            // 0..31
    const int bc0  = (tid & 7) * 4;       // 0..28

    float acc[4][4][4];
#pragma unroll
    for (int i = 0; i < 4; i++)
#pragma unroll
        for (int j = 0; j < 4; j++)
#pragma unroll
            for (int c = 0; c < 4; c++) acc[i][j][c] = 0.0f;

    float4 pa[4], pb[4];

    // prologue: load tile 0
#pragma unroll
    for (int r = 0; r < 4; r++)
        pa[r] = *(const float4*)&A[(size_t)(row0 + arow + r * 32) * K + acol];
#pragma unroll
    for (int it = 0; it < 4; it++)
        pb[it] = *(const float4*)&B[(size_t)brow * N + col0 + bc0 + it * 32];
#pragma unroll
    for (int r = 0; r < 4; r++)
        split4(Ah, Al, (arow + r * 32) * APAD + acol, pa[r]);
#pragma unroll
    for (int it = 0; it < 4; it++)
        split4(Bh, Bl, brow * BPAD + bc0 + it * 32, pb[it]);
    __syncthreads();

    const uint32_t aHB = (uint32_t)__cvta_generic_to_shared(Ah);
    const uint32_t aLB = (uint32_t)__cvta_generic_to_shared(Al);
    const uint32_t bHB = (uint32_t)__cvta_generic_to_shared(Bh);
    const uint32_t bLB = (uint32_t)__cvta_generic_to_shared(Bl);

    // ldmatrix per-lane addressing
    const int laneRow = (lane & 7) + ((lane >> 3) & 1) * 8;  // 0..15
    const int laneCol = (lane >> 4) * 8;                     // 0 or 8

    const int KITERS = K / GBK;
    for (int itk = 0; itk < KITERS; ++itk) {
        const bool more = (itk + 1 < KITERS);
        if (more) {
            const int k0 = (itk + 1) * GBK;
#pragma unroll
            for (int r = 0; r < 4; r++)
                pa[r] = *(const float4*)&A[(size_t)(row0 + arow + r * 32) * K + k0 + acol];
#pragma unroll
            for (int it = 0; it < 4; it++)
                pb[it] = *(const float4*)&B[(size_t)(k0 + brow) * N + col0 + bc0 + it * 32];
        }

#pragma unroll
        for (int ks = 0; ks < 2; ks++) {
            // A fragments (4 m-tiles, hi and lo)
            uint32_t ah[4][4], al[4][4];
#pragma unroll
            for (int mi = 0; mi < 4; mi++) {
                uint32_t off = (uint32_t)(((wm * 64 + mi * 16 + laneRow) * APAD
                                           + ks * 16 + laneCol) * 2);
                ldsm4(ah[mi][0], ah[mi][1], ah[mi][2], ah[mi][3], aHB + off);
                ldsm4(al[mi][0], al[mi][1], al[mi][2], al[mi][3], aLB + off);
            }
            // B fragments: 2 x4 loads cover 4 n-tiles (hi and lo)
            uint32_t bh[2][4], bl[2][4];
#pragma unroll
            for (int p = 0; p < 2; p++) {
                uint32_t off = (uint32_t)(((ks * 16 + laneRow) * BPAD
                                           + wn * 32 + p * 16 + laneCol) * 2);
                ldsm4t(bh[p][0], bh[p][1], bh[p][2], bh[p][3], bHB + off);
                ldsm4t(bl[p][0], bl[p][1], bl[p][2], bl[p][3], bLB + off);
            }
#pragma unroll
            for (int mi = 0; mi < 4; mi++) {
#pragma unroll
                for (int ni = 0; ni < 4; ni++) {
                    const uint32_t* bhp = &bh[ni >> 1][(ni & 1) * 2];
                    const uint32_t* blp = &bl[ni >> 1][(ni & 1) * 2];
                    mma16816(acc[mi][ni], ah[mi], bhp);   // hi*hi
                    mma16816(acc[mi][ni], ah[mi], blp);   // hi*lo
                    mma16816(acc[mi][ni], al[mi], bhp);   // lo*hi
                }
            }
        }
        __syncthreads();
        if (more) {
#pragma unroll
            for (int r = 0; r < 4; r++)
                split4(Ah, Al, (arow + r * 32) * APAD + acol, pa[r]);
#pragma unroll
            for (int it = 0; it < 4; it++)
                split4(Bh, Bl, brow * BPAD + bc0 + it * 32, pb[it]);
            __syncthreads();
        }
    }

    // epilogue
#pragma unroll
    for (int mi = 0; mi < 4; mi++) {
#pragma unroll
        for (int ni = 0; ni < 4; ni++) {
            const int r = row0 + wm * 64 + mi * 16 + (lane >> 2);
            const int c = col0 + wn * 32 + ni * 8 + (lane & 3) * 2;
            float2 v0 = make_float2(actf<ACT>(acc[mi][ni][0]),
                                    actf<ACT>(acc[mi][ni][1]));
            float2 v1 = make_float2(actf<ACT>(acc[mi][ni][2]),
                                    actf<ACT>(acc[mi][ni][3]));
            *(float2*)&C[(size_t)r * N + c]       = v0;
            *(float2*)&C[(size_t)(r + 8) * N + c] = v1;
        }
    }
}

// ---------------- GLA scan (unchanged from R2; correct) ----------------
__global__ void __launch_bounds__(128)
scan_kernel(const float* __restrict__ q, const float* __restrict__ k,
            const float* __restrict__ v, float* __restrict__ att) {
    const int lane = threadIdx.x & 31;
    const int warp = threadIdx.x >> 5;
    const int dvb  = blockIdx.x;
    const int h    = blockIdx.y;
    const int b    = blockIdx.z;
    const int dv0  = dvb * 16 + warp * 4;

    const size_t base = ((size_t)b * TT * HH + h) * DD;
    const int STR = EE / 4;

    const float4* qp = (const float4*)(q + base) + lane;
    const float4* kp = (const float4*)(k + base) + lane;
    const float4* vp = (const float4*)(v + base) + (dv0 >> 2);
    float4*       op = (float4*)(att + base) + (dv0 >> 2);

    float s[4][4];
#pragma unroll
    for (int i = 0; i < 4; i++)
#pragma unroll
        for (int j = 0; j < 4; j++) s[i][j] = 0.0f;

    float4 qn = qp[0], kn = kp[0], vn = vp[0];

    for (int t = 0; t < TT; ++t) {
        float4 qc = qn, kc = kn, vv = vn;
        int tn = (t + 1 < TT) ? t + 1 : t;
        qn = qp[(size_t)tn * STR];
        kn = kp[(size_t)tn * STR];
        vn = vp[(size_t)tn * STR];

        const float c  = (t & 1) ? 1.0f : -1.0f;
        const float qs = c * 0.0625f;

        float f[4]   = {1.0f - kc.x, 1.0f - kc.y, 1.0f - kc.z, 1.0f - kc.w};
        float kk4[4] = {kc.x * c, kc.y * c, kc.z * c, kc.w * c};
        float qq[4]  = {qc.x * qs, qc.y * qs, qc.z * qs, qc.w * qs};
        float vj[4]  = {vv.x, vv.y, vv.z, vv.w};

        float acc[4] = {0.0f, 0.0f, 0.0f, 0.0f};
#pragma unroll
        for (int i = 0; i < 4; i++) {
#pragma unroll
            for (int j = 0; j < 4; j++) {
                s[i][j] = fmaf(f[i], s[i][j], kk4[i] * vj[j]);
                acc[j]  = fmaf(qq[i], s[i][j], acc[j]);
            }
        }
#pragma unroll
        for (int j = 0; j < 4; j++) {
#pragma unroll
            for (int m = 16; m; m >>= 1)
                acc[j] += __shfl_xor_sync(0xffffffffu, acc[j], m);
        }
        if (lane == 0)
            op[(size_t)t * STR] = make_float4(acc[0], acc[1], acc[2], acc[3]);
    }
}

// ---------------- gate multiply + layernorm (unchanged) ----------------
__global__ void __launch_bounds__(256)
gate_ln_kernel(const float* __restrict__ att, const float* __restrict__ gate,
               const float* __restrict__ nw, float* __restrict__ y) {
    const int row = blockIdx.x;
    const int tid = threadIdx.x;
    const int lane = tid & 31, wid = tid >> 5;
    __shared__ float red[8];

    float4 a = ((const float4*)(att + (size_t)row * EE))[tid];
    float4 g = ((const float4*)(gate + (size_t)row * EE))[tid];
    float4 yv;
    yv.x = a.x * g.x; yv.y = a.y * g.y; yv.z = a.z * g.z; yv.w = a.w * g.w;

    float ssum = yv.x + yv.y + yv.z + yv.w;
#pragma unroll
    for (int m = 16; m; m >>= 1) ssum += __shfl_xor_sync(0xffffffffu, ssum, m);
    if (lane == 0) red[wid] = ssum;
    __syncthreads();
    float tot = 0.0f;
#pragma unroll
    for (int w = 0; w < 8; w++) tot += red[w];
    const float mean = tot * (1.0f / (float)EE);
    __syncthreads();

    float dx = yv.x - mean, dy = yv.y - mean, dz = yv.z - mean, dw = yv.w - mean;
    float ssq = dx * dx + dy * dy + dz * dz + dw * dw;
#pragma unroll
    for (int m = 16; m; m >>= 1) ssq += __shfl_xor_sync(0xffffffffu, ssq, m);
    if (lane == 0) red[wid] = ssq;
    __syncthreads();
    float totsq = 0.0f;
#pragma unroll
    for (int w = 0; w < 8; w++) totsq += red[w];
    const float rstd = rsqrtf(totsq * (1.0f / (float)EE) + 1e-5f);

    float4 w4 = ((const float4*)nw)[tid];
    float4 o;
    o.x = dx * rstd * w4.x;
    o.y = dy * rstd * w4.y;
    o.z = dz * rstd * w4.z;
    o.w = dw * rstd * w4.w;
    ((float4*)(y + (size_t)row * EE))[tid] = o;
}

// ---------------- launch ----------------
extern "C" void kernel_launch(void* const* d_in, const int* in_sizes, int n_in,
                              void* d_out, int out_size) {
    const float* x   = (const float*)d_in[0];
    const float* wq  = (const float*)d_in[1];
    const float* wk  = (const float*)d_in[2];
    const float* wv  = (const float*)d_in[3];
    const float* wo  = (const float*)d_in[4];
    const float* wg1 = (const float*)d_in[5];
    const float* wg2 = (const float*)d_in[6];
    const float* nw  = (const float*)d_in[7];
    float* out = (float*)d_out;

    void *pq, *pk, *pv, *patt, *pg1, *pgate, *py;
    cudaGetSymbolAddress(&pq, g_q);
    cudaGetSymbolAddress(&pk, g_k);
    cudaGetSymbolAddress(&pv, g_v);
    cudaGetSymbolAddress(&patt, g_att);
    cudaGetSymbolAddress(&pg1, g_g1);
    cudaGetSymbolAddress(&pgate, g_gate);
    cudaGetSymbolAddress(&py, g_y);
    float* fq = (float*)pq;     float* fk = (float*)pk;   float* fv = (float*)pv;
    float* fatt = (float*)patt; float* fg1 = (float*)pg1;
    float* fgate = (float*)pgate; float* fy = (float*)py;

    const dim3 blk(256);
    const dim3 grid_big(EE / GBN, MM / GBM);   // (8, 64)
    const dim3 grid_g1(DD / GBN, MM / GBM);    // (1, 64)

    gemm_tc<1><<<grid_big, blk>>>(x, wq, fq, MM, EE, EE);     // q = silu
    gemm_tc<2><<<grid_big, blk>>>(x, wk, fk, MM, EE, EE);     // k = sigmoid
    gemm_tc<0><<<grid_big, blk>>>(x, wv, fv, MM, EE, EE);     // v
    gemm_tc<0><<<grid_g1,  blk>>>(x, wg1, fg1, MM, DD, EE);   // g1

    scan_kernel<<<dim3(8, HH, BB), 128>>>(fq, fk, fv, fatt);

    gemm_tc<2><<<grid_big, blk>>>(fg1, wg2, fgate, MM, EE, DD); // gate = sigmoid

    gate_ln_kernel<<<MM, blk>>>(fatt, fgate, nw, fy);

    gemm_tc<0><<<grid_big, blk>>>(fy, wo, out, MM, EE, EE);     // final proj
}

// round 5
// speedup vs baseline: 1.7401x; 1.3959x over previous
#include <cuda_runtime.h>
#include <cuda_bf16.h>
#include <cstdint>

// Problem constants
#define BB 4
#define TT 2048
#define EE 1024
#define DD 128
#define HH 8
#define MM (BB * TT)   // 8192 rows

// ---------------- scratch (static device memory; no allocation) ----------------
__device__ float g_q[MM * EE];
__device__ float g_k[MM * EE];
__device__ float g_v[MM * EE];
__device__ float g_att[MM * EE];
__device__ float g_g1[MM * DD];
__device__ float g_gate[MM * EE];
__device__ float g_y[MM * EE];

// ---------------- bf16x3 tensor-core GEMM ----------------
#define GBM 128
#define GBN 128
#define GBK 32
#define APAD 40
#define BPAD 136

__device__ __forceinline__ void ldsm4(uint32_t& r0, uint32_t& r1, uint32_t& r2,
                                      uint32_t& r3, uint32_t a) {
    asm volatile("ldmatrix.sync.aligned.m8n8.x4.shared.b16 {%0,%1,%2,%3}, [%4];"
                 : "=r"(r0), "=r"(r1), "=r"(r2), "=r"(r3) : "r"(a));
}
__device__ __forceinline__ void ldsm4t(uint32_t& r0, uint32_t& r1, uint32_t& r2,
                                       uint32_t& r3, uint32_t a) {
    asm volatile("ldmatrix.sync.aligned.m8n8.x4.trans.shared.b16 {%0,%1,%2,%3}, [%4];"
                 : "=r"(r0), "=r"(r1), "=r"(r2), "=r"(r3) : "r"(a));
}
__device__ __forceinline__ void mma16816(float* d, const uint32_t* a, const uint32_t* b) {
    asm volatile("mma.sync.aligned.m16n8k16.row.col.f32.bf16.bf16.f32 "
                 "{%0,%1,%2,%3}, {%4,%5,%6,%7}, {%8,%9}, {%0,%1,%2,%3};"
                 : "+f"(d[0]), "+f"(d[1]), "+f"(d[2]), "+f"(d[3])
                 : "r"(a[0]), "r"(a[1]), "r"(a[2]), "r"(a[3]),
                   "r"(b[0]), "r"(b[1]));
}

__device__ __forceinline__ void split1(__nv_bfloat16* hi, __nv_bfloat16* lo,
                                       int idx, float x) {
    __nv_bfloat16 h = __float2bfloat16(x);
    hi[idx] = h;
    lo[idx] = __float2bfloat16(x - __bfloat162float(h));
}
__device__ __forceinline__ void split4(__nv_bfloat16* hi, __nv_bfloat16* lo,
                                       int idx, float4 v) {
    split1(hi, lo, idx + 0, v.x);
    split1(hi, lo, idx + 1, v.y);
    split1(hi, lo, idx + 2, v.z);
    split1(hi, lo, idx + 3, v.w);
}

template <int ACT>
__device__ __forceinline__ float actf(float v) {
    if (ACT == 1) return v / (1.0f + expf(-v));
    if (ACT == 2) return 1.0f / (1.0f + expf(-v));
    return v;
}

template <int ACT>
__global__ void __launch_bounds__(256)
gemm_tc(const float* __restrict__ A, const float* __restrict__ B,
        float* __restrict__ C, int M, int N, int K) {
    __shared__ __nv_bfloat16 Ah[GBM * APAD];
    __shared__ __nv_bfloat16 Al[GBM * APAD];
    __shared__ __nv_bfloat16 Bh[GBK * BPAD];
    __shared__ __nv_bfloat16 Bl[GBK * BPAD];

    const int tid  = threadIdx.x;
    const int warp = tid >> 5, lane = tid & 31;
    const int wm = warp >> 2, wn = warp & 3;
    const int row0 = blockIdx.y * GBM;
    const int col0 = blockIdx.x * GBN;

    const int arow = tid >> 3;
    const int acol = (tid & 7) * 4;
    const int brow = tid >> 3;
    const int bc0  = (tid & 7) * 4;

    float acc[4][4][4];
#pragma unroll
    for (int i = 0; i < 4; i++)
#pragma unroll
        for (int j = 0; j < 4; j++)
#pragma unroll
            for (int c = 0; c < 4; c++) acc[i][j][c] = 0.0f;

    float4 pa[4], pb[4];

#pragma unroll
    for (int r = 0; r < 4; r++)
        pa[r] = *(const float4*)&A[(size_t)(row0 + arow + r * 32) * K + acol];
#pragma unroll
    for (int it = 0; it < 4; it++)
        pb[it] = *(const float4*)&B[(size_t)brow * N + col0 + bc0 + it * 32];
#pragma unroll
    for (int r = 0; r < 4; r++)
        split4(Ah, Al, (arow + r * 32) * APAD + acol, pa[r]);
#pragma unroll
    for (int it = 0; it < 4; it++)
        split4(Bh, Bl, brow * BPAD + bc0 + it * 32, pb[it]);
    __syncthreads();

    const uint32_t aHB = (uint32_t)__cvta_generic_to_shared(Ah);
    const uint32_t aLB = (uint32_t)__cvta_generic_to_shared(Al);
    const uint32_t bHB = (uint32_t)__cvta_generic_to_shared(Bh);
    const uint32_t bLB = (uint32_t)__cvta_generic_to_shared(Bl);

    const int laneRow = (lane & 7) + ((lane >> 3) & 1) * 8;
    const int laneCol = (lane >> 4) * 8;

    const int KITERS = K / GBK;
    for (int itk = 0; itk < KITERS; ++itk) {
        const bool more = (itk + 1 < KITERS);
        if (more) {
            const int k0 = (itk + 1) * GBK;
#pragma unroll
            for (int r = 0; r < 4; r++)
                pa[r] = *(const float4*)&A[(size_t)(row0 + arow + r * 32) * K + k0 + acol];
#pragma unroll
            for (int it = 0; it < 4; it++)
                pb[it] = *(const float4*)&B[(size_t)(k0 + brow) * N + col0 + bc0 + it * 32];
        }

#pragma unroll
        for (int ks = 0; ks < 2; ks++) {
            uint32_t ah[4][4], al[4][4];
#pragma unroll
            for (int mi = 0; mi < 4; mi++) {
                uint32_t off = (uint32_t)(((wm * 64 + mi * 16 + laneRow) * APAD
                                           + ks * 16 + laneCol) * 2);
                ldsm4(ah[mi][0], ah[mi][1], ah[mi][2], ah[mi][3], aHB + off);
                ldsm4(al[mi][0], al[mi][1], al[mi][2], al[mi][3], aLB + off);
            }
            uint32_t bh[2][4], bl[2][4];
#pragma unroll
            for (int p = 0; p < 2; p++) {
                uint32_t off = (uint32_t)(((ks * 16 + laneRow) * BPAD
                                           + wn * 32 + p * 16 + laneCol) * 2);
                ldsm4t(bh[p][0], bh[p][1], bh[p][2], bh[p][3], bHB + off);
                ldsm4t(bl[p][0], bl[p][1], bl[p][2], bl[p][3], bLB + off);
            }
#pragma unroll
            for (int mi = 0; mi < 4; mi++) {
#pragma unroll
                for (int ni = 0; ni < 4; ni++) {
                    const uint32_t* bhp = &bh[ni >> 1][(ni & 1) * 2];
                    const uint32_t* blp = &bl[ni >> 1][(ni & 1) * 2];
                    mma16816(acc[mi][ni], ah[mi], bhp);
                    mma16816(acc[mi][ni], ah[mi], blp);
                    mma16816(acc[mi][ni], al[mi], bhp);
                }
            }
        }
        __syncthreads();
        if (more) {
#pragma unroll
            for (int r = 0; r < 4; r++)
                split4(Ah, Al, (arow + r * 32) * APAD + acol, pa[r]);
#pragma unroll
            for (int it = 0; it < 4; it++)
                split4(Bh, Bl, brow * BPAD + bc0 + it * 32, pb[it]);
            __syncthreads();
        }
    }

#pragma unroll
    for (int mi = 0; mi < 4; mi++) {
#pragma unroll
        for (int ni = 0; ni < 4; ni++) {
            const int r = row0 + wm * 64 + mi * 16 + (lane >> 2);
            const int c = col0 + wn * 32 + ni * 8 + (lane & 3) * 2;
            float2 v0 = make_float2(actf<ACT>(acc[mi][ni][0]),
                                    actf<ACT>(acc[mi][ni][1]));
            float2 v1 = make_float2(actf<ACT>(acc[mi][ni][2]),
                                    actf<ACT>(acc[mi][ni][3]));
            *(float2*)&C[(size_t)r * N + c]       = v0;
            *(float2*)&C[(size_t)(r + 8) * N + c] = v1;
        }
    }
}

// ---------------- GLA scan v2: 8 warps/block, 2 dv/warp, 4-step unroll ----------------
__global__ void __launch_bounds__(256, 2)
scan_kernel(const float* __restrict__ q, const float* __restrict__ k,
            const float* __restrict__ v, float* __restrict__ att) {
    const int lane = threadIdx.x & 31;
    const int warp = threadIdx.x >> 5;   // 0..7
    const int dvb  = blockIdx.x;         // 0..7
    const int h    = blockIdx.y;
    const int b    = blockIdx.z;
    const int dv0  = dvb * 16 + warp * 2;

    const size_t base = (size_t)b * TT * EE + (size_t)h * DD;
    const int S4 = EE / 4;   // float4 stride per t
    const int S2 = EE / 2;   // float2 stride per t

    const float4* qp = (const float4*)(q + base) + lane;
    const float4* kp = (const float4*)(k + base) + lane;
    const float2* vp = (const float2*)(v + base) + (dv0 >> 1);
    float2*       op = (float2*)(att + base) + (dv0 >> 1);

    float s0x = 0.f, s0y = 0.f, s1x = 0.f, s1y = 0.f;
    float s2x = 0.f, s2y = 0.f, s3x = 0.f, s3y = 0.f;

    float4 qc[4], kc[4];
    float2 vc[4];
    float4 qn[4], kn[4];
    float2 vn[4];

#pragma unroll
    for (int u = 0; u < 4; u++) {
        qc[u] = qp[(size_t)u * S4];
        kc[u] = kp[(size_t)u * S4];
        vc[u] = vp[(size_t)u * S2];
    }

    for (int t0 = 0; t0 < TT; t0 += 4) {
        const int tnx = (t0 + 4 < TT) ? t0 + 4 : t0;
#pragma unroll
        for (int u = 0; u < 4; u++) {
            qn[u] = qp[(size_t)(tnx + u) * S4];
            kn[u] = kp[(size_t)(tnx + u) * S4];
            vn[u] = vp[(size_t)(tnx + u) * S2];
        }

#pragma unroll
        for (int u = 0; u < 4; u++) {
            const float c  = ((t0 + u) & 1) ? 1.0f : -1.0f;  // (-1)^(t+1)
            const float qs = c * 0.0625f;                    // (2d)^(-1/2)

            const float f0 = 1.0f - kc[u].x, f1 = 1.0f - kc[u].y;
            const float f2 = 1.0f - kc[u].z, f3 = 1.0f - kc[u].w;
            const float k0 = kc[u].x * c, k1 = kc[u].y * c;
            const float k2 = kc[u].z * c, k3 = kc[u].w * c;
            const float q0 = qc[u].x * qs, q1 = qc[u].y * qs;
            const float q2 = qc[u].z * qs, q3 = qc[u].w * qs;
            const float vx = vc[u].x, vy = vc[u].y;

            s0x = fmaf(f0, s0x, k0 * vx);  s0y = fmaf(f0, s0y, k0 * vy);
            s1x = fmaf(f1, s1x, k1 * vx);  s1y = fmaf(f1, s1y, k1 * vy);
            s2x = fmaf(f2, s2x, k2 * vx);  s2y = fmaf(f2, s2y, k2 * vy);
            s3x = fmaf(f3, s3x, k3 * vx);  s3y = fmaf(f3, s3y, k3 * vy);

            float ax = q0 * s0x; ax = fmaf(q1, s1x, ax);
            ax = fmaf(q2, s2x, ax); ax = fmaf(q3, s3x, ax);
            float ay = q0 * s0y; ay = fmaf(q1, s1y, ay);
            ay = fmaf(q2, s2y, ay); ay = fmaf(q3, s3y, ay);

#pragma unroll
            for (int m = 16; m; m >>= 1) {
                ax += __shfl_xor_sync(0xffffffffu, ax, m);
                ay += __shfl_xor_sync(0xffffffffu, ay, m);
            }
            if (lane == 0)
                op[(size_t)(t0 + u) * S2] = make_float2(ax, ay);
        }

#pragma unroll
        for (int u = 0; u < 4; u++) {
            qc[u] = qn[u];
            kc[u] = kn[u];
            vc[u] = vn[u];
        }
    }
}

// ---------------- gate multiply + layernorm ----------------
__global__ void __launch_bounds__(256)
gate_ln_kernel(const float* __restrict__ att, const float* __restrict__ gate,
               const float* __restrict__ nw, float* __restrict__ y) {
    const int row = blockIdx.x;
    const int tid = threadIdx.x;
    const int lane = tid & 31, wid = tid >> 5;
    __shared__ float red[8];

    float4 a = ((const float4*)(att + (size_t)row * EE))[tid];
    float4 g = ((const float4*)(gate + (size_t)row * EE))[tid];
    float4 yv;
    yv.x = a.x * g.x; yv.y = a.y * g.y; yv.z = a.z * g.z; yv.w = a.w * g.w;

    float ssum = yv.x + yv.y + yv.z + yv.w;
#pragma unroll
    for (int m = 16; m; m >>= 1) ssum += __shfl_xor_sync(0xffffffffu, ssum, m);
    if (lane == 0) red[wid] = ssum;
    __syncthreads();
    float tot = 0.0f;
#pragma unroll
    for (int w = 0; w < 8; w++) tot += red[w];
    const float mean = tot * (1.0f / (float)EE);
    __syncthreads();

    float dx = yv.x - mean, dy = yv.y - mean, dz = yv.z - mean, dw = yv.w - mean;
    float ssq = dx * dx + dy * dy + dz * dz + dw * dw;
#pragma unroll
    for (int m = 16; m; m >>= 1) ssq += __shfl_xor_sync(0xffffffffu, ssq, m);
    if (lane == 0) red[wid] = ssq;
    __syncthreads();
    float totsq = 0.0f;
#pragma unroll
    for (int w = 0; w < 8; w++) totsq += red[w];
    const float rstd = rsqrtf(totsq * (1.0f / (float)EE) + 1e-5f);

    float4 w4 = ((const float4*)nw)[tid];
    float4 o;
    o.x = dx * rstd * w4.x;
    o.y = dy * rstd * w4.y;
    o.z = dz * rstd * w4.z;
    o.w = dw * rstd * w4.w;
    ((float4*)(y + (size_t)row * EE))[tid] = o;
}

// ---------------- launch ----------------
extern "C" void kernel_launch(void* const* d_in, const int* in_sizes, int n_in,
                              void* d_out, int out_size) {
    const float* x   = (const float*)d_in[0];
    const float* wq  = (const float*)d_in[1];
    const float* wk  = (const float*)d_in[2];
    const float* wv  = (const float*)d_in[3];
    const float* wo  = (const float*)d_in[4];
    const float* wg1 = (const float*)d_in[5];
    const float* wg2 = (const float*)d_in[6];
    const float* nw  = (const float*)d_in[7];
    float* out = (float*)d_out;

    void *pq, *pk, *pv, *patt, *pg1, *pgate, *py;
    cudaGetSymbolAddress(&pq, g_q);
    cudaGetSymbolAddress(&pk, g_k);
    cudaGetSymbolAddress(&pv, g_v);
    cudaGetSymbolAddress(&patt, g_att);
    cudaGetSymbolAddress(&pg1, g_g1);
    cudaGetSymbolAddress(&pgate, g_gate);
    cudaGetSymbolAddress(&py, g_y);
    float* fq = (float*)pq;     float* fk = (float*)pk;   float* fv = (float*)pv;
    float* fatt = (float*)patt; float* fg1 = (float*)pg1;
    float* fgate = (float*)pgate; float* fy = (float*)py;

    const dim3 blk(256);
    const dim3 grid_big(EE / GBN, MM / GBM);   // (8, 64)
    const dim3 grid_g1(DD / GBN, MM / GBM);    // (1, 64)

    gemm_tc<1><<<grid_big, blk>>>(x, wq, fq, MM, EE, EE);     // q = silu
    gemm_tc<2><<<grid_big, blk>>>(x, wk, fk, MM, EE, EE);     // k = sigmoid
    gemm_tc<0><<<grid_big, blk>>>(x, wv, fv, MM, EE, EE);     // v
    gemm_tc<0><<<grid_g1,  blk>>>(x, wg1, fg1, MM, DD, EE);   // g1

    scan_kernel<<<dim3(8, HH, BB), 256>>>(fq, fk, fv, fatt);

    gemm_tc<2><<<grid_big, blk>>>(fg1, wg2, fgate, MM, EE, DD); // gate = sigmoid

    gate_ln_kernel<<<MM, blk>>>(fatt, fgate, nw, fy);

    gemm_tc<0><<<grid_big, blk>>>(fy, wo, out, MM, EE, EE);     // final proj
}

// round 7
// speedup vs baseline: 1.9560x; 1.1241x over previous
#include <cuda_runtime.h>
#include <cuda_bf16.h>
#include <cstdint>

// Problem constants
#define BB 4
#define TT 2048
#define EE 1024
#define DD 128
#define HH 8
#define MM (BB * TT)   // 8192 rows

// ---------------- scratch (static device memory; no allocation) ----------------
__device__ float g_q[MM * EE];
__device__ float g_k[MM * EE];
__device__ float g_v[MM * EE];
__device__ float g_att[MM * EE];
__device__ float g_g1[MM * DD];
__device__ float g_gate[MM * EE];
__device__ float g_y[MM * EE];

// ---------------- bf16x3 tensor-core GEMM (unchanged from R3/R5) ----------------
#define GBM 128
#define GBN 128
#define GBK 32
#define APAD 40
#define BPAD 136

__device__ __forceinline__ void ldsm4(uint32_t& r0, uint32_t& r1, uint32_t& r2,
                                      uint32_t& r3, uint32_t a) {
    asm volatile("ldmatrix.sync.aligned.m8n8.x4.shared.b16 {%0,%1,%2,%3}, [%4];"
                 : "=r"(r0), "=r"(r1), "=r"(r2), "=r"(r3) : "r"(a));
}
__device__ __forceinline__ void ldsm4t(uint32_t& r0, uint32_t& r1, uint32_t& r2,
                                       uint32_t& r3, uint32_t a) {
    asm volatile("ldmatrix.sync.aligned.m8n8.x4.trans.shared.b16 {%0,%1,%2,%3}, [%4];"
                 : "=r"(r0), "=r"(r1), "=r"(r2), "=r"(r3) : "r"(a));
}
__device__ __forceinline__ void mma16816(float* d, const uint32_t* a, const uint32_t* b) {
    asm volatile("mma.sync.aligned.m16n8k16.row.col.f32.bf16.bf16.f32 "
                 "{%0,%1,%2,%3}, {%4,%5,%6,%7}, {%8,%9}, {%0,%1,%2,%3};"
                 : "+f"(d[0]), "+f"(d[1]), "+f"(d[2]), "+f"(d[3])
                 : "r"(a[0]), "r"(a[1]), "r"(a[2]), "r"(a[3]),
                   "r"(b[0]), "r"(b[1]));
}

__device__ __forceinline__ void split1(__nv_bfloat16* hi, __nv_bfloat16* lo,
                                       int idx, float x) {
    __nv_bfloat16 h = __float2bfloat16(x);
    hi[idx] = h;
    lo[idx] = __float2bfloat16(x - __bfloat162float(h));
}
__device__ __forceinline__ void split4(__nv_bfloat16* hi, __nv_bfloat16* lo,
                                       int idx, float4 v) {
    split1(hi, lo, idx + 0, v.x);
    split1(hi, lo, idx + 1, v.y);
    split1(hi, lo, idx + 2, v.z);
    split1(hi, lo, idx + 3, v.w);
}

template <int ACT>
__device__ __forceinline__ float actf(float v) {
    if (ACT == 1) return v / (1.0f + expf(-v));
    if (ACT == 2) return 1.0f / (1.0f + expf(-v));
    return v;
}

template <int ACT>
__global__ void __launch_bounds__(256)
gemm_tc(const float* __restrict__ A, const float* __restrict__ B,
        float* __restrict__ C, int M, int N, int K) {
    __shared__ __nv_bfloat16 Ah[GBM * APAD];
    __shared__ __nv_bfloat16 Al[GBM * APAD];
    __shared__ __nv_bfloat16 Bh[GBK * BPAD];
    __shared__ __nv_bfloat16 Bl[GBK * BPAD];

    const int tid  = threadIdx.x;
    const int warp = tid >> 5, lane = tid & 31;
    const int wm = warp >> 2, wn = warp & 3;
    const int row0 = blockIdx.y * GBM;
    const int col0 = blockIdx.x * GBN;

    const int arow = tid >> 3;
    const int acol = (tid & 7) * 4;
    const int brow = tid >> 3;
    const int bc0  = (tid & 7) * 4;

    float acc[4][4][4];
#pragma unroll
    for (int i = 0; i < 4; i++)
#pragma unroll
        for (int j = 0; j < 4; j++)
#pragma unroll
            for (int c = 0; c < 4; c++) acc[i][j][c] = 0.0f;

    float4 pa[4], pb[4];

#pragma unroll
    for (int r = 0; r < 4; r++)
        pa[r] = *(const float4*)&A[(size_t)(row0 + arow + r * 32) * K + acol];
#pragma unroll
    for (int it = 0; it < 4; it++)
        pb[it] = *(const float4*)&B[(size_t)brow * N + col0 + bc0 + it * 32];
#pragma unroll
    for (int r = 0; r < 4; r++)
        split4(Ah, Al, (arow + r * 32) * APAD + acol, pa[r]);
#pragma unroll
    for (int it = 0; it < 4; it++)
        split4(Bh, Bl, brow * BPAD + bc0 + it * 32, pb[it]);
    __syncthreads();

    const uint32_t aHB = (uint32_t)__cvta_generic_to_shared(Ah);
    const uint32_t aLB = (uint32_t)__cvta_generic_to_shared(Al);
    const uint32_t bHB = (uint32_t)__cvta_generic_to_shared(Bh);
    const uint32_t bLB = (uint32_t)__cvta_generic_to_shared(Bl);

    const int laneRow = (lane & 7) + ((lane >> 3) & 1) * 8;
    const int laneCol = (lane >> 4) * 8;

    const int KITERS = K / GBK;
    for (int itk = 0; itk < KITERS; ++itk) {
        const bool more = (itk + 1 < KITERS);
        if (more) {
            const int k0 = (itk + 1) * GBK;
#pragma unroll
            for (int r = 0; r < 4; r++)
                pa[r] = *(const float4*)&A[(size_t)(row0 + arow + r * 32) * K + k0 + acol];
#pragma unroll
            for (int it = 0; it < 4; it++)
                pb[it] = *(const float4*)&B[(size_t)(k0 + brow) * N + col0 + bc0 + it * 32];
        }

#pragma unroll
        for (int ks = 0; ks < 2; ks++) {
            uint32_t ah[4][4], al[4][4];
#pragma unroll
            for (int mi = 0; mi < 4; mi++) {
                uint32_t off = (uint32_t)(((wm * 64 + mi * 16 + laneRow) * APAD
                                           + ks * 16 + laneCol) * 2);
                ldsm4(ah[mi][0], ah[mi][1], ah[mi][2], ah[mi][3], aHB + off);
                ldsm4(al[mi][0], al[mi][1], al[mi][2], al[mi][3], aLB + off);
            }
            uint32_t bh[2][4], bl[2][4];
#pragma unroll
            for (int p = 0; p < 2; p++) {
                uint32_t off = (uint32_t)(((ks * 16 + laneRow) * BPAD
                                           + wn * 32 + p * 16 + laneCol) * 2);
                ldsm4t(bh[p][0], bh[p][1], bh[p][2], bh[p][3], bHB + off);
                ldsm4t(bl[p][0], bl[p][1], bl[p][2], bl[p][3], bLB + off);
            }
#pragma unroll
            for (int mi = 0; mi < 4; mi++) {
#pragma unroll
                for (int ni = 0; ni < 4; ni++) {
                    const uint32_t* bhp = &bh[ni >> 1][(ni & 1) * 2];
                    const uint32_t* blp = &bl[ni >> 1][(ni & 1) * 2];
                    mma16816(acc[mi][ni], ah[mi], bhp);
                    mma16816(acc[mi][ni], ah[mi], blp);
                    mma16816(acc[mi][ni], al[mi], bhp);
                }
            }
        }
        __syncthreads();
        if (more) {
#pragma unroll
            for (int r = 0; r < 4; r++)
                split4(Ah, Al, (arow + r * 32) * APAD + acol, pa[r]);
#pragma unroll
            for (int it = 0; it < 4; it++)
                split4(Bh, Bl, brow * BPAD + bc0 + it * 32, pb[it]);
            __syncthreads();
        }
    }

#pragma unroll
    for (int mi = 0; mi < 4; mi++) {
#pragma unroll
        for (int ni = 0; ni < 4; ni++) {
            const int r = row0 + wm * 64 + mi * 16 + (lane >> 2);
            const int c = col0 + wn * 32 + ni * 8 + (lane & 3) * 2;
            float2 v0 = make_float2(actf<ACT>(acc[mi][ni][0]),
                                    actf<ACT>(acc[mi][ni][1]));
            float2 v1 = make_float2(actf<ACT>(acc[mi][ni][2]),
                                    actf<ACT>(acc[mi][ni][3]));
            *(float2*)&C[(size_t)r * N + c]       = v0;
            *(float2*)&C[(size_t)(r + 8) * N + c] = v1;
        }
    }
}

// ---------------- GLA scan v3: smem staging + cp.async + batched reductions ----
// grid: (8 dv-blocks, H, B) = 256 blocks, 256 threads (8 warps).
// Warp owns 2 dv columns; lane owns dk rows {4*lane..4*lane+3}.
// Per stage: 8 timesteps of q/k (full 128-dk rows, shared by all warps) and the
// block's 16 v columns are staged into smem via cp.async (double-buffered).
#define SSTEP 8
#define NITER (TT / SSTEP)

__device__ __forceinline__ void cp16(uint32_t s, const void* g) {
    asm volatile("cp.async.ca.shared.global [%0], [%1], 16;" :: "r"(s), "l"(g));
}

__global__ void __launch_bounds__(256, 2)
scan_kernel(const float* __restrict__ q, const float* __restrict__ k,
            const float* __restrict__ v, float* __restrict__ att) {
    __shared__ __align__(16) float sQ[2][SSTEP][128];
    __shared__ __align__(16) float sK[2][SSTEP][128];
    __shared__ __align__(16) float sV[2][SSTEP][16];

    const int tid  = threadIdx.x;
    const int lane = tid & 31;
    const int warp = tid >> 5;      // 0..7
    const int dvb  = blockIdx.x;    // 0..7
    const int h    = blockIdx.y;
    const int b    = blockIdx.z;
    const int dv0  = dvb * 16 + warp * 2;

    const size_t rowbase = (size_t)b * TT * EE + (size_t)h * DD;
    const float* qb = q + rowbase;
    const float* kb = k + rowbase;
    const float* vb = v + rowbase + dvb * 16;
    float*       ob = att + rowbase + dv0;

    // staging mapping: all 256 threads load one float4 of q and one of k;
    // threads 0..31 additionally load one float4 of v.
    const int lu = tid >> 5;           // step 0..7
    const int li = (tid & 31) * 4;     // float offset 0..124
    const int vu = tid >> 2;           // step 0..7 (tid<32)
    const int vj = (tid & 3) * 4;      // 0,4,8,12

    auto issue_stage = [&](int t0, int buf) {
        cp16((uint32_t)__cvta_generic_to_shared(&sQ[buf][lu][li]),
             qb + (size_t)(t0 + lu) * EE + li);
        cp16((uint32_t)__cvta_generic_to_shared(&sK[buf][lu][li]),
             kb + (size_t)(t0 + lu) * EE + li);
        if (tid < 32)
            cp16((uint32_t)__cvta_generic_to_shared(&sV[buf][vu][vj]),
                 vb + (size_t)(t0 + vu) * EE + vj);
        asm volatile("cp.async.commit_group;" ::: "memory");
    };

    issue_stage(0, 0);
    issue_stage(SSTEP, 1);

    float s0x = 0.f, s0y = 0.f, s1x = 0.f, s1y = 0.f;
    float s2x = 0.f, s2y = 0.f, s3x = 0.f, s3y = 0.f;

    for (int iter = 0; iter < NITER; ++iter) {
        const int buf = iter & 1;
        const int t0  = iter * SSTEP;

        if (iter + 2 < NITER)
            asm volatile("cp.async.wait_group 1;" ::: "memory");
        else
            asm volatile("cp.async.wait_group 0;" ::: "memory");
        __syncthreads();

        float axs[SSTEP], ays[SSTEP];

#pragma unroll
        for (int u = 0; u < SSTEP; u++) {
            const float4 qc = *(const float4*)&sQ[buf][u][lane * 4];
            const float4 kc = *(const float4*)&sK[buf][u][lane * 4];
            const float2 vv = *(const float2*)&sV[buf][u][warp * 2];

            const float c  = ((t0 + u) & 1) ? 1.0f : -1.0f;  // (-1)^(t+1)
            const float qs = c * 0.0625f;                    // (2d)^(-1/2)

            const float f0 = 1.0f - kc.x, f1 = 1.0f - kc.y;
            const float f2 = 1.0f - kc.z, f3 = 1.0f - kc.w;
            const float k0 = kc.x * c, k1 = kc.y * c;
            const float k2 = kc.z * c, k3 = kc.w * c;
            const float q0 = qc.x * qs, q1 = qc.y * qs;
            const float q2 = qc.z * qs, q3 = qc.w * qs;
            const float vx = vv.x, vy = vv.y;

            s0x = fmaf(f0, s0x, k0 * vx);  s0y = fmaf(f0, s0y, k0 * vy);
            s1x = fmaf(f1, s1x, k1 * vx);  s1y = fmaf(f1, s1y, k1 * vy);
            s2x = fmaf(f2, s2x, k2 * vx);  s2y = fmaf(f2, s2y, k2 * vy);
            s3x = fmaf(f3, s3x, k3 * vx);  s3y = fmaf(f3, s3y, k3 * vy);

            float ax = q0 * s0x; ax = fmaf(q1, s1x, ax);
            ax = fmaf(q2, s2x, ax); ax = fmaf(q3, s3x, ax);
            float ay = q0 * s0y; ay = fmaf(q1, s1y, ay);
            ay = fmaf(q2, s2y, ay); ay = fmaf(q3, s3y, ay);
            axs[u] = ax;
            ays[u] = ay;
        }

        // batched reductions: 16 independent shfl trees, level-major
#pragma unroll
        for (int m = 16; m; m >>= 1) {
#pragma unroll
            for (int u = 0; u < SSTEP; u++) {
                axs[u] += __shfl_xor_sync(0xffffffffu, axs[u], m);
                ays[u] += __shfl_xor_sync(0xffffffffu, ays[u], m);
            }
        }

        if (lane == 0) {
#pragma unroll
            for (int u = 0; u < SSTEP; u++)
                *(float2*)(ob + (size_t)(t0 + u) * EE) = make_float2(axs[u], ays[u]);
        }

        __syncthreads();
        if (iter + 2 < NITER)
            issue_stage((iter + 2) * SSTEP, buf);
    }
}

// ---------------- gate multiply + layernorm (unchanged) ----------------
__global__ void __launch_bounds__(256)
gate_ln_kernel(const float* __restrict__ att, const float* __restrict__ gate,
               const float* __restrict__ nw, float* __restrict__ y) {
    const int row = blockIdx.x;
    const int tid = threadIdx.x;
    const int lane = tid & 31, wid = tid >> 5;
    __shared__ float red[8];

    float4 a = ((const float4*)(att + (size_t)row * EE))[tid];
    float4 g = ((const float4*)(gate + (size_t)row * EE))[tid];
    float4 yv;
    yv.x = a.x * g.x; yv.y = a.y * g.y; yv.z = a.z * g.z; yv.w = a.w * g.w;

    float ssum = yv.x + yv.y + yv.z + yv.w;
#pragma unroll
    for (int m = 16; m; m >>= 1) ssum += __shfl_xor_sync(0xffffffffu, ssum, m);
    if (lane == 0) red[wid] = ssum;
    __syncthreads();
    float tot = 0.0f;
#pragma unroll
    for (int w = 0; w < 8; w++) tot += red[w];
    const float mean = tot * (1.0f / (float)EE);
    __syncthreads();

    float dx = yv.x - mean, dy = yv.y - mean, dz = yv.z - mean, dw = yv.w - mean;
    float ssq = dx * dx + dy * dy + dz * dz + dw * dw;
#pragma unroll
    for (int m = 16; m; m >>= 1) ssq += __shfl_xor_sync(0xffffffffu, ssq, m);
    if (lane == 0) red[wid] = ssq;
    __syncthreads();
    float totsq = 0.0f;
#pragma unroll
    for (int w = 0; w < 8; w++) totsq += red[w];
    const float rstd = rsqrtf(totsq * (1.0f / (float)EE) + 1e-5f);

    float4 w4 = ((const float4*)nw)[tid];
    float4 o;
    o.x = dx * rstd * w4.x;
    o.y = dy * rstd * w4.y;
    o.z = dz * rstd * w4.z;
    o.w = dw * rstd * w4.w;
    ((float4*)(y + (size_t)row * EE))[tid] = o;
}

// ---------------- launch ----------------
extern "C" void kernel_launch(void* const* d_in, const int* in_sizes, int n_in,
                              void* d_out, int out_size) {
    const float* x   = (const float*)d_in[0];
    const float* wq  = (const float*)d_in[1];
    const float* wk  = (const float*)d_in[2];
    const float* wv  = (const float*)d_in[3];
    const float* wo  = (const float*)d_in[4];
    const float* wg1 = (const float*)d_in[5];
    const float* wg2 = (const float*)d_in[6];
    const float* nw  = (const float*)d_in[7];
    float* out = (float*)d_out;

    void *pq, *pk, *pv, *patt, *pg1, *pgate, *py;
    cudaGetSymbolAddress(&pq, g_q);
    cudaGetSymbolAddress(&pk, g_k);
    cudaGetSymbolAddress(&pv, g_v);
    cudaGetSymbolAddress(&patt, g_att);
    cudaGetSymbolAddress(&pg1, g_g1);
    cudaGetSymbolAddress(&pgate, g_gate);
    cudaGetSymbolAddress(&py, g_y);
    float* fq = (float*)pq;     float* fk = (float*)pk;   float* fv = (float*)pv;
    float* fatt = (float*)patt; float* fg1 = (float*)pg1;
    float* fgate = (float*)pgate; float* fy = (float*)py;

    const dim3 blk(256);
    const dim3 grid_big(EE / GBN, MM / GBM);   // (8, 64)
    const dim3 grid_g1(DD / GBN, MM / GBM);    // (1, 64)

    gemm_tc<1><<<grid_big, blk>>>(x, wq, fq, MM, EE, EE);     // q = silu
    gemm_tc<2><<<grid_big, blk>>>(x, wk, fk, MM, EE, EE);     // k = sigmoid
    gemm_tc<0><<<grid_big, blk>>>(x, wv, fv, MM, EE, EE);     // v
    gemm_tc<0><<<grid_g1,  blk>>>(x, wg1, fg1, MM, DD, EE);   // g1

    scan_kernel<<<dim3(8, HH, BB), 256>>>(fq, fk, fv, fatt);

    gemm_tc<2><<<grid_big, blk>>>(fg1, wg2, fgate, MM, EE, DD); // gate = sigmoid

    gate_ln_kernel<<<MM, blk>>>(fatt, fgate, nw, fy);

    gemm_tc<0><<<grid_big, blk>>>(fy, wo, out, MM, EE, EE);     // final proj
}

// round 9
// speedup vs baseline: 2.0062x; 1.0256x over previous
#include <cuda_runtime.h>
#include <cuda_bf16.h>
#include <cstdint>

// Problem constants
#define BB 4
#define TT 2048
#define EE 1024
#define DD 128
#define HH 8
#define MM (BB * TT)   // 8192 rows

// ---------------- scratch (static device memory; no allocation) ----------------
__device__ float g_q[MM * EE];
__device__ float g_k[MM * EE];
__device__ float g_v[MM * EE];
__device__ float g_att[MM * EE];
__device__ float g_g1[MM * DD];
__device__ float g_gate[MM * EE];
__device__ float g_y[MM * EE];

// ---------------- bf16x3 tensor-core GEMM ----------------
#define GBM 128
#define GBN 128
#define GBK 32
#define APAD 40
#define BPAD 136

__device__ __forceinline__ void ldsm4(uint32_t& r0, uint32_t& r1, uint32_t& r2,
                                      uint32_t& r3, uint32_t a) {
    asm volatile("ldmatrix.sync.aligned.m8n8.x4.shared.b16 {%0,%1,%2,%3}, [%4];"
                 : "=r"(r0), "=r"(r1), "=r"(r2), "=r"(r3) : "r"(a));
}
__device__ __forceinline__ void ldsm4t(uint32_t& r0, uint32_t& r1, uint32_t& r2,
                                       uint32_t& r3, uint32_t a) {
    asm volatile("ldmatrix.sync.aligned.m8n8.x4.trans.shared.b16 {%0,%1,%2,%3}, [%4];"
                 : "=r"(r0), "=r"(r1), "=r"(r2), "=r"(r3) : "r"(a));
}
__device__ __forceinline__ void mma16816(float* d, const uint32_t* a, const uint32_t* b) {
    asm volatile("mma.sync.aligned.m16n8k16.row.col.f32.bf16.bf16.f32 "
                 "{%0,%1,%2,%3}, {%4,%5,%6,%7}, {%8,%9}, {%0,%1,%2,%3};"
                 : "+f"(d[0]), "+f"(d[1]), "+f"(d[2]), "+f"(d[3])
                 : "r"(a[0]), "r"(a[1]), "r"(a[2]), "r"(a[3]),
                   "r"(b[0]), "r"(b[1]));
}

__device__ __forceinline__ void split1(__nv_bfloat16* hi, __nv_bfloat16* lo,
                                       int idx, float x) {
    __nv_bfloat16 h = __float2bfloat16(x);
    hi[idx] = h;
    lo[idx] = __float2bfloat16(x - __bfloat162float(h));
}
__device__ __forceinline__ void split4(__nv_bfloat16* hi, __nv_bfloat16* lo,
                                       int idx, float4 v) {
    split1(hi, lo, idx + 0, v.x);
    split1(hi, lo, idx + 1, v.y);
    split1(hi, lo, idx + 2, v.z);
    split1(hi, lo, idx + 3, v.w);
}

__device__ __forceinline__ float actsel(float v, int act) {
    if (act == 1) return v / (1.0f + expf(-v));       // silu
    if (act == 2) return 1.0f / (1.0f + expf(-v));    // sigmoid
    return v;
}

// Core bf16x3 GEMM body; A[M,K]@B[K,N] -> C with runtime activation.
__device__ __forceinline__ void gemm_body(const float* __restrict__ A,
                                          const float* __restrict__ B,
                                          float* __restrict__ C,
                                          int N, int K, int row0, int col0, int act) {
    __shared__ __nv_bfloat16 Ah[GBM * APAD];
    __shared__ __nv_bfloat16 Al[GBM * APAD];
    __shared__ __nv_bfloat16 Bh[GBK * BPAD];
    __shared__ __nv_bfloat16 Bl[GBK * BPAD];

    const int tid  = threadIdx.x;
    const int warp = tid >> 5, lane = tid & 31;
    const int wm = warp >> 2, wn = warp & 3;

    const int arow = tid >> 3;
    const int acol = (tid & 7) * 4;
    const int brow = tid >> 3;
    const int bc0  = (tid & 7) * 4;

    float acc[4][4][4];
#pragma unroll
    for (int i = 0; i < 4; i++)
#pragma unroll
        for (int j = 0; j < 4; j++)
#pragma unroll
            for (int c = 0; c < 4; c++) acc[i][j][c] = 0.0f;

    float4 pa[4], pb[4];

#pragma unroll
    for (int r = 0; r < 4; r++)
        pa[r] = *(const float4*)&A[(size_t)(row0 + arow + r * 32) * K + acol];
#pragma unroll
    for (int it = 0; it < 4; it++)
        pb[it] = *(const float4*)&B[(size_t)brow * N + col0 + bc0 + it * 32];
#pragma unroll
    for (int r = 0; r < 4; r++)
        split4(Ah, Al, (arow + r * 32) * APAD + acol, pa[r]);
#pragma unroll
    for (int it = 0; it < 4; it++)
        split4(Bh, Bl, brow * BPAD + bc0 + it * 32, pb[it]);
    __syncthreads();

    const uint32_t aHB = (uint32_t)__cvta_generic_to_shared(Ah);
    const uint32_t aLB = (uint32_t)__cvta_generic_to_shared(Al);
    const uint32_t bHB = (uint32_t)__cvta_generic_to_shared(Bh);
    const uint32_t bLB = (uint32_t)__cvta_generic_to_shared(Bl);

    const int laneRow = (lane & 7) + ((lane >> 3) & 1) * 8;
    const int laneCol = (lane >> 4) * 8;

    const int KITERS = K / GBK;
    for (int itk = 0; itk < KITERS; ++itk) {
        const bool more = (itk + 1 < KITERS);
        if (more) {
            const int k0 = (itk + 1) * GBK;
#pragma unroll
            for (int r = 0; r < 4; r++)
                pa[r] = *(const float4*)&A[(size_t)(row0 + arow + r * 32) * K + k0 + acol];
#pragma unroll
            for (int it = 0; it < 4; it++)
                pb[it] = *(const float4*)&B[(size_t)(k0 + brow) * N + col0 + bc0 + it * 32];
        }

#pragma unroll
        for (int ks = 0; ks < 2; ks++) {
            uint32_t ah[4][4], al[4][4];
#pragma unroll
            for (int mi = 0; mi < 4; mi++) {
                uint32_t off = (uint32_t)(((wm * 64 + mi * 16 + laneRow) * APAD
                                           + ks * 16 + laneCol) * 2);
                ldsm4(ah[mi][0], ah[mi][1], ah[mi][2], ah[mi][3], aHB + off);
                ldsm4(al[mi][0], al[mi][1], al[mi][2], al[mi][3], aLB + off);
            }
            uint32_t bh[2][4], bl[2][4];
#pragma unroll
            for (int p = 0; p < 2; p++) {
                uint32_t off = (uint32_t)(((ks * 16 + laneRow) * BPAD
                                           + wn * 32 + p * 16 + laneCol) * 2);
                ldsm4t(bh[p][0], bh[p][1], bh[p][2], bh[p][3], bHB + off);
                ldsm4t(bl[p][0], bl[p][1], bl[p][2], bl[p][3], bLB + off);
            }
#pragma unroll
            for (int mi = 0; mi < 4; mi++) {
#pragma unroll
                for (int ni = 0; ni < 4; ni++) {
                    const uint32_t* bhp = &bh[ni >> 1][(ni & 1) * 2];
                    const uint32_t* blp = &bl[ni >> 1][(ni & 1) * 2];
                    mma16816(acc[mi][ni], ah[mi], bhp);
                    mma16816(acc[mi][ni], ah[mi], blp);
                    mma16816(acc[mi][ni], al[mi], bhp);
                }
            }
        }
        __syncthreads();
        if (more) {
#pragma unroll
            for (int r = 0; r < 4; r++)
                split4(Ah, Al, (arow + r * 32) * APAD + acol, pa[r]);
#pragma unroll
            for (int it = 0; it < 4; it++)
                split4(Bh, Bl, brow * BPAD + bc0 + it * 32, pb[it]);
            __syncthreads();
        }
    }

#pragma unroll
    for (int mi = 0; mi < 4; mi++) {
#pragma unroll
        for (int ni = 0; ni < 4; ni++) {
            const int r = row0 + wm * 64 + mi * 16 + (lane >> 2);
            const int c = col0 + wn * 32 + ni * 8 + (lane & 3) * 2;
            float2 v0 = make_float2(actsel(acc[mi][ni][0], act),
                                    actsel(acc[mi][ni][1], act));
            float2 v1 = make_float2(actsel(acc[mi][ni][2], act),
                                    actsel(acc[mi][ni][3], act));
            *(float2*)&C[(size_t)r * N + c]       = v0;
            *(float2*)&C[(size_t)(r + 8) * N + c] = v1;
        }
    }
}

// Standalone GEMM with compile-time act
template <int ACT>
__global__ void __launch_bounds__(256)
gemm_tc(const float* __restrict__ A, const float* __restrict__ B,
        float* __restrict__ C, int M, int N, int K) {
    gemm_body(A, B, C, N, K, blockIdx.y * GBM, blockIdx.x * GBN, ACT);
}

// Fused QKV: grid (24, 64); blockIdx.x>>3 selects weight/output/activation.
__global__ void __launch_bounds__(256)
gemm_qkv(const float* __restrict__ x,
         const float* __restrict__ wq, const float* __restrict__ wk,
         const float* __restrict__ wv,
         float* __restrict__ q, float* __restrict__ k, float* __restrict__ v) {
    const int wsel = blockIdx.x >> 3;
    const float* B = (wsel == 0) ? wq : (wsel == 1) ? wk : wv;
    float*       C = (wsel == 0) ? q  : (wsel == 1) ? k  : v;
    const int act  = (wsel == 0) ? 1  : (wsel == 1) ? 2  : 0;
    gemm_body(x, B, C, EE, EE, blockIdx.y * GBM, (blockIdx.x & 7) * GBN, act);
}

// ---------------- GLA scan v4: 16-step stages, triple-buffer, dynamic smem ----
#define SSTEP 16
#define NBUF 3
#define NITER (TT / SSTEP)   // 128

// dynamic smem layout (floats):
//   sQ: NBUF*SSTEP*128 = 6144
//   sK: NBUF*SSTEP*128 = 6144
//   sV: NBUF*SSTEP*16  = 768
// total 13056 floats = 52224 bytes
#define SCAN_SMEM_BYTES ((NBUF * SSTEP * 128 * 2 + NBUF * SSTEP * 16) * 4)

__device__ __forceinline__ void cp16(uint32_t s, const void* g) {
    asm volatile("cp.async.ca.shared.global [%0], [%1], 16;" :: "r"(s), "l"(g));
}

__global__ void __launch_bounds__(256, 2)
scan_kernel(const float* __restrict__ q, const float* __restrict__ k,
            const float* __restrict__ v, float* __restrict__ att) {
    extern __shared__ __align__(16) float smem[];
    float* sQ = smem;                               // [NBUF][SSTEP][128]
    float* sK = sQ + NBUF * SSTEP * 128;            // [NBUF][SSTEP][128]
    float* sV = sK + NBUF * SSTEP * 128;            // [NBUF][SSTEP][16]

    const int tid  = threadIdx.x;
    const int lane = tid & 31;
    const int warp = tid >> 5;      // 0..7
    const int dvb  = blockIdx.x;    // 0..7
    const int h    = blockIdx.y;
    const int b    = blockIdx.z;

    const size_t rowbase = (size_t)b * TT * EE + (size_t)h * DD;
    const float* qb = q + rowbase;
    const float* kb = k + rowbase;
    const float* vb = v + rowbase + dvb * 16;
    float*       ob = att + rowbase + dvb * 16 + warp * 2;

    // staging: q/k: 512 float4 per stage -> each thread 2; v: 64 float4 -> tid<64.
    const int r0row = tid >> 5,          r0col = (tid & 31) * 4;
    const int r1row = (tid + 256) >> 5,  r1col = r0col;
    const int vrow  = tid >> 2,          vcol  = (tid & 3) * 4;

    auto issue_stage = [&](int t0, int buf) {
        float* bQ = sQ + buf * SSTEP * 128;
        float* bK = sK + buf * SSTEP * 128;
        float* bV = sV + buf * SSTEP * 16;
        cp16((uint32_t)__cvta_generic_to_shared(&bQ[r0row * 128 + r0col]),
             qb + (size_t)(t0 + r0row) * EE + r0col);
        cp16((uint32_t)__cvta_generic_to_shared(&bQ[r1row * 128 + r1col]),
             qb + (size_t)(t0 + r1row) * EE + r1col);
        cp16((uint32_t)__cvta_generic_to_shared(&bK[r0row * 128 + r0col]),
             kb + (size_t)(t0 + r0row) * EE + r0col);
        cp16((uint32_t)__cvta_generic_to_shared(&bK[r1row * 128 + r1col]),
             kb + (size_t)(t0 + r1row) * EE + r1col);
        if (tid < 64)
            cp16((uint32_t)__cvta_generic_to_shared(&bV[vrow * 16 + vcol]),
                 vb + (size_t)(t0 + vrow) * EE + vcol);
        asm volatile("cp.async.commit_group;" ::: "memory");
    };

    issue_stage(0, 0);
    issue_stage(SSTEP, 1);

    float s0x = 0.f, s0y = 0.f, s1x = 0.f, s1y = 0.f;
    float s2x = 0.f, s2y = 0.f, s3x = 0.f, s3y = 0.f;

    for (int iter = 0; iter < NITER; ++iter) {
        const int buf = iter % NBUF;
        const int t0  = iter * SSTEP;
        const float* bQ = sQ + buf * SSTEP * 128;
        const float* bK = sK + buf * SSTEP * 128;
        const float* bV = sV + buf * SSTEP * 16;

        if (iter < NITER - 1)
            asm volatile("cp.async.wait_group 1;" ::: "memory");
        else
            asm volatile("cp.async.wait_group 0;" ::: "memory");
        __syncthreads();   // stage `iter` visible; all warps done with buf iter-1

        if (iter + 2 < NITER)
            issue_stage((iter + 2) * SSTEP, (iter + 2) % NBUF);

        float axs[SSTEP], ays[SSTEP];

#pragma unroll
        for (int u = 0; u < SSTEP; u++) {
            const float4 qc = *(const float4*)&bQ[u * 128 + lane * 4];
            const float4 kc = *(const float4*)&bK[u * 128 + lane * 4];
            const float2 vv = *(const float2*)&bV[u * 16 + warp * 2];

            const float c  = (u & 1) ? 1.0f : -1.0f;   // (-1)^(t+1), t0 even
            const float qs = c * 0.0625f;              // (2d)^(-1/2)

            const float f0 = 1.0f - kc.x, f1 = 1.0f - kc.y;
            const float f2 = 1.0f - kc.z, f3 = 1.0f - kc.w;
            const float k0 = kc.x * c, k1 = kc.y * c;
            const float k2 = kc.z * c, k3 = kc.w * c;
            const float q0 = qc.x * qs, q1 = qc.y * qs;
            const float q2 = qc.z * qs, q3 = qc.w * qs;
            const float vx = vv.x, vy = vv.y;

            s0x = fmaf(f0, s0x, k0 * vx);  s0y = fmaf(f0, s0y, k0 * vy);
            s1x = fmaf(f1, s1x, k1 * vx);  s1y = fmaf(f1, s1y, k1 * vy);
            s2x = fmaf(f2, s2x, k2 * vx);  s2y = fmaf(f2, s2y, k2 * vy);
            s3x = fmaf(f3, s3x, k3 * vx);  s3y = fmaf(f3, s3y, k3 * vy);

            float ax = q0 * s0x; ax = fmaf(q1, s1x, ax);
            ax = fmaf(q2, s2x, ax); ax = fmaf(q3, s3x, ax);
            float ay = q0 * s0y; ay = fmaf(q1, s1y, ay);
            ay = fmaf(q2, s2y, ay); ay = fmaf(q3, s3y, ay);
            axs[u] = ax;
            ays[u] = ay;
        }

        // batched reductions: 32 independent shfl trees, level-major
#pragma unroll
        for (int m = 16; m; m >>= 1) {
#pragma unroll
            for (int u = 0; u < SSTEP; u++) {
                axs[u] += __shfl_xor_sync(0xffffffffu, axs[u], m);
                ays[u] += __shfl_xor_sync(0xffffffffu, ays[u], m);
            }
        }

        if (lane == 0) {
#pragma unroll
            for (int u = 0; u < SSTEP; u++)
                *(float2*)(ob + (size_t)(t0 + u) * EE) = make_float2(axs[u], ays[u]);
        }
    }
}

// ---------------- gate multiply + layernorm (unchanged) ----------------
__global__ void __launch_bounds__(256)
gate_ln_kernel(const float* __restrict__ att, const float* __restrict__ gate,
               const float* __restrict__ nw, float* __restrict__ y) {
    const int row = blockIdx.x;
    const int tid = threadIdx.x;
    const int lane = tid & 31, wid = tid >> 5;
    __shared__ float red[8];

    float4 a = ((const float4*)(att + (size_t)row * EE))[tid];
    float4 g = ((const float4*)(gate + (size_t)row * EE))[tid];
    float4 yv;
    yv.x = a.x * g.x; yv.y = a.y * g.y; yv.z = a.z * g.z; yv.w = a.w * g.w;

    float ssum = yv.x + yv.y + yv.z + yv.w;
#pragma unroll
    for (int m = 16; m; m >>= 1) ssum += __shfl_xor_sync(0xffffffffu, ssum, m);
    if (lane == 0) red[wid] = ssum;
    __syncthreads();
    float tot = 0.0f;
#pragma unroll
    for (int w = 0; w < 8; w++) tot += red[w];
    const float mean = tot * (1.0f / (float)EE);
    __syncthreads();

    float dx = yv.x - mean, dy = yv.y - mean, dz = yv.z - mean, dw = yv.w - mean;
    float ssq = dx * dx + dy * dy + dz * dz + dw * dw;
#pragma unroll
    for (int m = 16; m; m >>= 1) ssq += __shfl_xor_sync(0xffffffffu, ssq, m);
    if (lane == 0) red[wid] = ssq;
    __syncthreads();
    float totsq = 0.0f;
#pragma unroll
    for (int w = 0; w < 8; w++) totsq += red[w];
    const float rstd = rsqrtf(totsq * (1.0f / (float)EE) + 1e-5f);

    float4 w4 = ((const float4*)nw)[tid];
    float4 o;
    o.x = dx * rstd * w4.x;
    o.y = dy * rstd * w4.y;
    o.z = dz * rstd * w4.z;
    o.w = dw * rstd * w4.w;
    ((float4*)(y + (size_t)row * EE))[tid] = o;
}

// ---------------- launch ----------------
extern "C" void kernel_launch(void* const* d_in, const int* in_sizes, int n_in,
                              void* d_out, int out_size) {
    const float* x   = (const float*)d_in[0];
    const float* wq  = (const float*)d_in[1];
    const float* wk  = (const float*)d_in[2];
    const float* wv  = (const float*)d_in[3];
    const float* wo  = (const float*)d_in[4];
    const float* wg1 = (const float*)d_in[5];
    const float* wg2 = (const float*)d_in[6];
    const float* nw  = (const float*)d_in[7];
    float* out = (float*)d_out;

    void *pq, *pk, *pv, *patt, *pg1, *pgate, *py;
    cudaGetSymbolAddress(&pq, g_q);
    cudaGetSymbolAddress(&pk, g_k);
    cudaGetSymbolAddress(&pv, g_v);
    cudaGetSymbolAddress(&patt, g_att);
    cudaGetSymbolAddress(&pg1, g_g1);
    cudaGetSymbolAddress(&pgate, g_gate);
    cudaGetSymbolAddress(&py, g_y);
    float* fq = (float*)pq;     float* fk = (float*)pk;   float* fv = (float*)pv;
    float* fatt = (float*)patt; float* fg1 = (float*)pg1;
    float* fgate = (float*)pgate; float* fy = (float*)py;

    // opt in to >48KB dynamic smem for the scan (idempotent, capture-safe)
    cudaFuncSetAttribute(scan_kernel,
                         cudaFuncAttributeMaxDynamicSharedMemorySize,
                         SCAN_SMEM_BYTES);

    const dim3 blk(256);

    // 1. fused q/k/v projections (1536 CTAs)
    gemm_qkv<<<dim3(24, MM / GBM), blk>>>(x, wq, wk, wv, fq, fk, fv);

    // 2. gate first projection
    gemm_tc<0><<<dim3(DD / GBN, MM / GBM), blk>>>(x, wg1, fg1, MM, DD, EE);

    // 3. GLA scan (dynamic smem)
    scan_kernel<<<dim3(8, HH, BB), 256, SCAN_SMEM_BYTES>>>(fq, fk, fv, fatt);

    // 4. gate second projection + sigmoid
    gemm_tc<2><<<dim3(EE / GBN, MM / GBM), blk>>>(fg1, wg2, fgate, MM, EE, DD);

    // 5. gate * att + layernorm
    gate_ln_kernel<<<MM, blk>>>(fatt, fgate, nw, fy);

    // 6. output projection (profiled slot: -s 5 -c 1)
    gemm_tc<0><<<dim3(EE / GBN, MM / GBM), blk>>>(fy, wo, out, MM, EE, EE);
}

// round 10
// speedup vs baseline: 3.0335x; 1.5121x over previous
#include <cuda_runtime.h>
#include <cuda_bf16.h>
#include <cstdint>

// Problem constants
#define BB 4
#define TT 2048
#define EE 1024
#define DD 128
#define HH 8
#define MM (BB * TT)   // 8192 rows

typedef __nv_bfloat16 bf16;

// ---------------- scratch (static device memory; no allocation) ----------------
__device__ float g_q[MM * EE];
__device__ float g_k[MM * EE];
__device__ float g_v[MM * EE];
__device__ float g_att[MM * EE];
__device__ float g_gate[MM * EE];

__device__ __align__(16) bf16 g_xh[MM * EE];
__device__ __align__(16) bf16 g_xl[MM * EE];
__device__ __align__(16) bf16 g_yh[MM * EE];
__device__ __align__(16) bf16 g_yl[MM * EE];
__device__ __align__(16) bf16 g_g1b[MM * DD];

__device__ __align__(16) bf16 g_wqh[EE * EE];
__device__ __align__(16) bf16 g_wql[EE * EE];
__device__ __align__(16) bf16 g_wkh[EE * EE];
__device__ __align__(16) bf16 g_wkl[EE * EE];
__device__ __align__(16) bf16 g_wvh[EE * EE];
__device__ __align__(16) bf16 g_wvl[EE * EE];
__device__ __align__(16) bf16 g_woh[EE * EE];
__device__ __align__(16) bf16 g_wol[EE * EE];
__device__ __align__(16) bf16 g_wg1b[EE * DD];
__device__ __align__(16) bf16 g_wg2b[DD * EE];

// ---------------- common asm helpers ----------------
__device__ __forceinline__ void cp16(uint32_t s, const void* g) {
    asm volatile("cp.async.ca.shared.global [%0], [%1], 16;" :: "r"(s), "l"(g));
}
__device__ __forceinline__ void ldsm4(uint32_t& r0, uint32_t& r1, uint32_t& r2,
                                      uint32_t& r3, uint32_t a) {
    asm volatile("ldmatrix.sync.aligned.m8n8.x4.shared.b16 {%0,%1,%2,%3}, [%4];"
                 : "=r"(r0), "=r"(r1), "=r"(r2), "=r"(r3) : "r"(a));
}
__device__ __forceinline__ void ldsm4t(uint32_t& r0, uint32_t& r1, uint32_t& r2,
                                       uint32_t& r3, uint32_t a) {
    asm volatile("ldmatrix.sync.aligned.m8n8.x4.trans.shared.b16 {%0,%1,%2,%3}, [%4];"
                 : "=r"(r0), "=r"(r1), "=r"(r2), "=r"(r3) : "r"(a));
}
__device__ __forceinline__ void mma16816(float* d, const uint32_t* a, const uint32_t* b) {
    asm volatile("mma.sync.aligned.m16n8k16.row.col.f32.bf16.bf16.f32 "
                 "{%0,%1,%2,%3}, {%4,%5,%6,%7}, {%8,%9}, {%0,%1,%2,%3};"
                 : "+f"(d[0]), "+f"(d[1]), "+f"(d[2]), "+f"(d[3])
                 : "r"(a[0]), "r"(a[1]), "r"(a[2]), "r"(a[3]),
                   "r"(b[0]), "r"(b[1]));
}

__device__ __forceinline__ float actsel(float v, int act) {
    if (act == 1) return v / (1.0f + expf(-v));       // silu
    if (act == 2) return 1.0f / (1.0f + expf(-v));    // sigmoid
    return v;
}

// ---------------- pipelined bf16 GEMM ----------------
// C[M,N] = act(A @ B); A,B pre-split bf16 (hi[, lo]).
// CTA 128x128, GBK 32, 256 thr, warp tile 64x32, 3-stage cp.async pipeline.
#define GBM 128
#define GBN 128
#define GBK 32
#define APAD 40
#define BPAD 136
#define AELEM (GBM * APAD)        // 5120 bf16
#define BELEM (GBK * BPAD)        // 4352 bf16
#define STG_ELEMS1 (2 * (AELEM + BELEM))   // split: 18944
#define STG_ELEMS0 (AELEM + BELEM)         // plain:  9472
#define SMEM_SPLIT1 (3 * STG_ELEMS1 * 2)   // 113664 B
#define SMEM_SPLIT0 (3 * STG_ELEMS0 * 2)   // 56832 B

extern __shared__ __align__(16) char dynsm[];

template <int SPLIT, int OBF>
__device__ __forceinline__ void gemm_pipe_body(
    const bf16* __restrict__ Ahg, const bf16* __restrict__ Alg,
    const bf16* __restrict__ Bhg, const bf16* __restrict__ Blg,
    float* __restrict__ C, bf16* __restrict__ Cb,
    int N, int K, int row0, int col0, int act)
{
    bf16* sm = (bf16*)dynsm;
    const int STG = SPLIT ? STG_ELEMS1 : STG_ELEMS0;

    const int tid = threadIdx.x;
    const int warp = tid >> 5, lane = tid & 31;
    const int wm = warp >> 2, wn = warp & 3;

    auto issue = [&](int itk, int buf) {
        const int k0 = itk * GBK;
        bf16* s   = sm + buf * STG;
        bf16* sAh = s;
        bf16* sAl = s + AELEM;                       // valid iff SPLIT
        bf16* sBh = s + (SPLIT ? 2 : 1) * AELEM;
        bf16* sBl = sBh + BELEM;                     // valid iff SPLIT
#pragma unroll
        for (int j = 0; j < 2; j++) {
            const int c = tid + j * 256;             // A chunk 0..511
            const int row = c >> 2, cc = (c & 3) * 8;
            const size_t g = (size_t)(row0 + row) * K + k0 + cc;
            cp16((uint32_t)__cvta_generic_to_shared(&sAh[row * APAD + cc]), Ahg + g);
            if (SPLIT)
                cp16((uint32_t)__cvta_generic_to_shared(&sAl[row * APAD + cc]), Alg + g);
        }
#pragma unroll
        for (int j = 0; j < 2; j++) {
            const int c = tid + j * 256;             // B chunk 0..511
            const int br = c >> 4, bc = (c & 15) * 8;
            const size_t g = (size_t)(k0 + br) * N + col0 + bc;
            cp16((uint32_t)__cvta_generic_to_shared(&sBh[br * BPAD + bc]), Bhg + g);
            if (SPLIT)
                cp16((uint32_t)__cvta_generic_to_shared(&sBl[br * BPAD + bc]), Blg + g);
        }
        asm volatile("cp.async.commit_group;" ::: "memory");
    };

    const int KIT = K / GBK;
    issue(0, 0);
    if (KIT > 1) issue(1, 1);

    float acc[4][4][4];
#pragma unroll
    for (int i = 0; i < 4; i++)
#pragma unroll
        for (int j = 0; j < 4; j++)
#pragma unroll
            for (int c = 0; c < 4; c++) acc[i][j][c] = 0.0f;

    const int laneRow = (lane & 7) + ((lane >> 3) & 1) * 8;
    const int laneCol = (lane >> 4) * 8;
    const uint32_t smBase = (uint32_t)__cvta_generic_to_shared(sm);

    for (int itk = 0; itk < KIT; ++itk) {
        const int buf = itk % 3;
        if (itk + 1 < KIT)
            asm volatile("cp.async.wait_group 1;" ::: "memory");
        else
            asm volatile("cp.async.wait_group 0;" ::: "memory");
        __syncthreads();
        if (itk + 2 < KIT) issue(itk + 2, (itk + 2) % 3);

        const uint32_t aH = smBase + buf * STG * 2;
        const uint32_t aL = aH + AELEM * 2;
        const uint32_t bH = aH + (SPLIT ? 2 : 1) * AELEM * 2;
        const uint32_t bL = bH + BELEM * 2;

#pragma unroll
        for (int ks = 0; ks < 2; ks++) {
            uint32_t ah[4][4], al[4][4];
#pragma unroll
            for (int mi = 0; mi < 4; mi++) {
                uint32_t off = (uint32_t)(((wm * 64 + mi * 16 + laneRow) * APAD
                                           + ks * 16 + laneCol) * 2);
                ldsm4(ah[mi][0], ah[mi][1], ah[mi][2], ah[mi][3], aH + off);
                if (SPLIT)
                    ldsm4(al[mi][0], al[mi][1], al[mi][2], al[mi][3], aL + off);
            }
            uint32_t bh[2][4], bl[2][4];
#pragma unroll
            for (int p = 0; p < 2; p++) {
                uint32_t off = (uint32_t)(((ks * 16 + laneRow) * BPAD
                                           + wn * 32 + p * 16 + laneCol) * 2);
                ldsm4t(bh[p][0], bh[p][1], bh[p][2], bh[p][3], bH + off);
                if (SPLIT)
                    ldsm4t(bl[p][0], bl[p][1], bl[p][2], bl[p][3], bL + off);
            }
#pragma unroll
            for (int mi = 0; mi < 4; mi++) {
#pragma unroll
                for (int ni = 0; ni < 4; ni++) {
                    const uint32_t* bhp = &bh[ni >> 1][(ni & 1) * 2];
                    mma16816(acc[mi][ni], ah[mi], bhp);
                    if (SPLIT) {
                        const uint32_t* blp = &bl[ni >> 1][(ni & 1) * 2];
                        mma16816(acc[mi][ni], ah[mi], blp);
                        mma16816(acc[mi][ni], al[mi], bhp);
                    }
                }
            }
        }
    }

    // epilogue
#pragma unroll
    for (int mi = 0; mi < 4; mi++) {
#pragma unroll
        for (int ni = 0; ni < 4; ni++) {
            const int r = row0 + wm * 64 + mi * 16 + (lane >> 2);
            const int c = col0 + wn * 32 + ni * 8 + (lane & 3) * 2;
            float2 v0 = make_float2(actsel(acc[mi][ni][0], act),
                                    actsel(acc[mi][ni][1], act));
            float2 v1 = make_float2(actsel(acc[mi][ni][2], act),
                                    actsel(acc[mi][ni][3], act));
            if (OBF) {
                *(__nv_bfloat162*)&Cb[(size_t)r * N + c] =
                    __floats2bfloat162_rn(v0.x, v0.y);
                *(__nv_bfloat162*)&Cb[(size_t)(r + 8) * N + c] =
                    __floats2bfloat162_rn(v1.x, v1.y);
            } else {
                *(float2*)&C[(size_t)r * N + c]       = v0;
                *(float2*)&C[(size_t)(r + 8) * N + c] = v1;
            }
        }
    }
}

template <int SPLIT, int OBF, int ACT>
__global__ void __launch_bounds__(256)
gemm_std(const bf16* __restrict__ Ah, const bf16* __restrict__ Al,
         const bf16* __restrict__ Bh, const bf16* __restrict__ Bl,
         float* __restrict__ C, bf16* __restrict__ Cb, int N, int K) {
    gemm_pipe_body<SPLIT, OBF>(Ah, Al, Bh, Bl, C, Cb, N, K,
                               blockIdx.y * GBM, blockIdx.x * GBN, ACT);
}

// Fused QKV + wg1: grid (25, 64).
__global__ void __launch_bounds__(256)
gemm_qkvg(float* __restrict__ q, float* __restrict__ k, float* __restrict__ v) {
    const int bx = blockIdx.x;
    const int row0 = blockIdx.y * GBM;
    if (bx < 24) {
        const int wsel = bx >> 3;
        const bf16* Bh = (wsel == 0) ? g_wqh : (wsel == 1) ? g_wkh : g_wvh;
        const bf16* Bl = (wsel == 0) ? g_wql : (wsel == 1) ? g_wkl : g_wvl;
        float*      C  = (wsel == 0) ? q : (wsel == 1) ? k : v;
        const int act  = (wsel == 0) ? 1 : (wsel == 1) ? 2 : 0;
        gemm_pipe_body<1, 0>(g_xh, g_xl, Bh, Bl, C, nullptr,
                             EE, EE, row0, (bx & 7) * GBN, act);
    } else {
        // g1 = x @ wg1 in plain bf16 (gate path; precision budget analyzed)
        gemm_pipe_body<0, 1>(g_xh, nullptr, g_wg1b, nullptr, nullptr, g_g1b,
                             DD, EE, row0, 0, 0);
    }
}

// ---------------- split kernels ----------------
__device__ __forceinline__ void split1g(bf16* hi, bf16* lo, int i, float x) {
    bf16 h = __float2bfloat16(x);
    hi[i] = h;
    lo[i] = __float2bfloat16(x - __bfloat162float(h));
}

__global__ void __launch_bounds__(256)
split_weights(const float* __restrict__ wq, const float* __restrict__ wk,
              const float* __restrict__ wv, const float* __restrict__ wo,
              const float* __restrict__ wg1, const float* __restrict__ wg2) {
    const int i = blockIdx.x * 256 + threadIdx.x;   // grid covers EE*EE
    split1g(g_wqh, g_wql, i, wq[i]);
    split1g(g_wkh, g_wkl, i, wk[i]);
    split1g(g_wvh, g_wvl, i, wv[i]);
    split1g(g_woh, g_wol, i, wo[i]);
    if (i < EE * DD) {
        g_wg1b[i] = __float2bfloat16(wg1[i]);
        g_wg2b[i] = __float2bfloat16(wg2[i]);
    }
}

__global__ void __launch_bounds__(256)
split_x_kernel(const float* __restrict__ x) {
    const int i = (blockIdx.x * 256 + threadIdx.x) * 4;
    float4 v = *(const float4*)&x[i];
    bf16 h0 = __float2bfloat16(v.x), h1 = __float2bfloat16(v.y);
    bf16 h2 = __float2bfloat16(v.z), h3 = __float2bfloat16(v.w);
    *(__nv_bfloat162*)&g_xh[i]     = __nv_bfloat162(h0, h1);
    *(__nv_bfloat162*)&g_xh[i + 2] = __nv_bfloat162(h2, h3);
    *(__nv_bfloat162*)&g_xl[i] = __floats2bfloat162_rn(
        v.x - __bfloat162float(h0), v.y - __bfloat162float(h1));
    *(__nv_bfloat162*)&g_xl[i + 2] = __floats2bfloat162_rn(
        v.z - __bfloat162float(h2), v.w - __bfloat162float(h3));
}

// ---------------- GLA scan v4 (unchanged from R9) ----------------
#define SSTEP 16
#define NBUF 3
#define NITER (TT / SSTEP)   // 128
#define SCAN_SMEM_BYTES ((NBUF * SSTEP * 128 * 2 + NBUF * SSTEP * 16) * 4)

__global__ void __launch_bounds__(256, 2)
scan_kernel(const float* __restrict__ q, const float* __restrict__ k,
            const float* __restrict__ v, float* __restrict__ att) {
    float* smem = (float*)dynsm;
    float* sQ = smem;
    float* sK = sQ + NBUF * SSTEP * 128;
    float* sV = sK + NBUF * SSTEP * 128;

    const int tid  = threadIdx.x;
    const int lane = tid & 31;
    const int warp = tid >> 5;
    const int dvb  = blockIdx.x;
    const int h    = blockIdx.y;
    const int b    = blockIdx.z;

    const size_t rowbase = (size_t)b * TT * EE + (size_t)h * DD;
    const float* qb = q + rowbase;
    const float* kb = k + rowbase;
    const float* vb = v + rowbase + dvb * 16;
    float*       ob = att + rowbase + dvb * 16 + warp * 2;

    const int r0row = tid >> 5,          r0col = (tid & 31) * 4;
    const int r1row = (tid + 256) >> 5,  r1col = r0col;
    const int vrow  = tid >> 2,          vcol  = (tid & 3) * 4;

    auto issue_stage = [&](int t0, int buf) {
        float* bQ = sQ + buf * SSTEP * 128;
        float* bK = sK + buf * SSTEP * 128;
        float* bV = sV + buf * SSTEP * 16;
        cp16((uint32_t)__cvta_generic_to_shared(&bQ[r0row * 128 + r0col]),
             qb + (size_t)(t0 + r0row) * EE + r0col);
        cp16((uint32_t)__cvta_generic_to_shared(&bQ[r1row * 128 + r1col]),
             qb + (size_t)(t0 + r1row) * EE + r1col);
        cp16((uint32_t)__cvta_generic_to_shared(&bK[r0row * 128 + r0col]),
             kb + (size_t)(t0 + r0row) * EE + r0col);
        cp16((uint32_t)__cvta_generic_to_shared(&bK[r1row * 128 + r1col]),
             kb + (size_t)(t0 + r1row) * EE + r1col);
        if (tid < 64)
            cp16((uint32_t)__cvta_generic_to_shared(&bV[vrow * 16 + vcol]),
                 vb + (size_t)(t0 + vrow) * EE + vcol);
        asm volatile("cp.async.commit_group;" ::: "memory");
    };

    issue_stage(0, 0);
    issue_stage(SSTEP, 1);

    float s0x = 0.f, s0y = 0.f, s1x = 0.f, s1y = 0.f;
    float s2x = 0.f, s2y = 0.f, s3x = 0.f, s3y = 0.f;

    for (int iter = 0; iter < NITER; ++iter) {
        const int buf = iter % NBUF;
        const int t0  = iter * SSTEP;
        const float* bQ = sQ + buf * SSTEP * 128;
        const float* bK = sK + buf * SSTEP * 128;
        const float* bV = sV + buf * SSTEP * 16;

        if (iter < NITER - 1)
            asm volatile("cp.async.wait_group 1;" ::: "memory");
        else
            asm volatile("cp.async.wait_group 0;" ::: "memory");
        __syncthreads();

        if (iter + 2 < NITER)
            issue_stage((iter + 2) * SSTEP, (iter + 2) % NBUF);

        float axs[SSTEP], ays[SSTEP];

#pragma unroll
        for (int u = 0; u < SSTEP; u++) {
            const float4 qc = *(const float4*)&bQ[u * 128 + lane * 4];
            const float4 kc = *(const float4*)&bK[u * 128 + lane * 4];
            const float2 vv = *(const float2*)&bV[u * 16 + warp * 2];

            const float c  = (u & 1) ? 1.0f : -1.0f;
            const float qs = c * 0.0625f;

            const float f0 = 1.0f - kc.x, f1 = 1.0f - kc.y;
            const float f2 = 1.0f - kc.z, f3 = 1.0f - kc.w;
            const float k0 = kc.x * c, k1 = kc.y * c;
            const float k2 = kc.z * c, k3 = kc.w * c;
            const float q0 = qc.x * qs, q1 = qc.y * qs;
            const float q2 = qc.z * qs, q3 = qc.w * qs;
            const float vx = vv.x, vy = vv.y;

            s0x = fmaf(f0, s0x, k0 * vx);  s0y = fmaf(f0, s0y, k0 * vy);
            s1x = fmaf(f1, s1x, k1 * vx);  s1y = fmaf(f1, s1y, k1 * vy);
            s2x = fmaf(f2, s2x, k2 * vx);  s2y = fmaf(f2, s2y, k2 * vy);
            s3x = fmaf(f3, s3x, k3 * vx);  s3y = fmaf(f3, s3y, k3 * vy);

            float ax = q0 * s0x; ax = fmaf(q1, s1x, ax);
            ax = fmaf(q2, s2x, ax); ax = fmaf(q3, s3x, ax);
            float ay = q0 * s0y; ay = fmaf(q1, s1y, ay);
            ay = fmaf(q2, s2y, ay); ay = fmaf(q3, s3y, ay);
            axs[u] = ax;
            ays[u] = ay;
        }

#pragma unroll
        for (int m = 16; m; m >>= 1) {
#pragma unroll
            for (int u = 0; u < SSTEP; u++) {
                axs[u] += __shfl_xor_sync(0xffffffffu, axs[u], m);
                ays[u] += __shfl_xor_sync(0xffffffffu, ays[u], m);
            }
        }

        if (lane == 0) {
#pragma unroll
            for (int u = 0; u < SSTEP; u++)
                *(float2*)(ob + (size_t)(t0 + u) * EE) = make_float2(axs[u], ays[u]);
        }
    }
}

// ---------------- gate multiply + layernorm -> bf16 hi/lo ----------------
__global__ void __launch_bounds__(256)
gate_ln_kernel(const float* __restrict__ att, const float* __restrict__ gate,
               const float* __restrict__ nw) {
    const int row = blockIdx.x;
    const int tid = threadIdx.x;
    const int lane = tid & 31, wid = tid >> 5;
    __shared__ float red[8];

    float4 a = ((const float4*)(att + (size_t)row * EE))[tid];
    float4 g = ((const float4*)(gate + (size_t)row * EE))[tid];
    float4 yv;
    yv.x = a.x * g.x; yv.y = a.y * g.y; yv.z = a.z * g.z; yv.w = a.w * g.w;

    float ssum = yv.x + yv.y + yv.z + yv.w;
#pragma unroll
    for (int m = 16; m; m >>= 1) ssum += __shfl_xor_sync(0xffffffffu, ssum, m);
    if (lane == 0) red[wid] = ssum;
    __syncthreads();
    float tot = 0.0f;
#pragma unroll
    for (int w = 0; w < 8; w++) tot += red[w];
    const float mean = tot * (1.0f / (float)EE);
    __syncthreads();

    float dx = yv.x - mean, dy = yv.y - mean, dz = yv.z - mean, dw = yv.w - mean;
    float ssq = dx * dx + dy * dy + dz * dz + dw * dw;
#pragma unroll
    for (int m = 16; m; m >>= 1) ssq += __shfl_xor_sync(0xffffffffu, ssq, m);
    if (lane == 0) red[wid] = ssq;
    __syncthreads();
    float totsq = 0.0f;
#pragma unroll
    for (int w = 0; w < 8; w++) totsq += red[w];
    const float rstd = rsqrtf(totsq * (1.0f / (float)EE) + 1e-5f);

    float4 w4 = ((const float4*)nw)[tid];
    float o0 = dx * rstd * w4.x;
    float o1 = dy * rstd * w4.y;
    float o2 = dz * rstd * w4.z;
    float o3 = dw * rstd * w4.w;

    const size_t base = (size_t)row * EE + tid * 4;
    bf16 h0 = __float2bfloat16(o0), h1 = __float2bfloat16(o1);
    bf16 h2 = __float2bfloat16(o2), h3 = __float2bfloat16(o3);
    *(__nv_bfloat162*)&g_yh[base]     = __nv_bfloat162(h0, h1);
    *(__nv_bfloat162*)&g_yh[base + 2] = __nv_bfloat162(h2, h3);
    *(__nv_bfloat162*)&g_yl[base] = __floats2bfloat162_rn(
        o0 - __bfloat162float(h0), o1 - __bfloat162float(h1));
    *(__nv_bfloat162*)&g_yl[base + 2] = __floats2bfloat162_rn(
        o2 - __bfloat162float(h2), o3 - __bfloat162float(h3));
}

// ---------------- launch ----------------
extern "C" void kernel_launch(void* const* d_in, const int* in_sizes, int n_in,
                              void* d_out, int out_size) {
    const float* x   = (const float*)d_in[0];
    const float* wq  = (const float*)d_in[1];
    const float* wk  = (const float*)d_in[2];
    const float* wv  = (const float*)d_in[3];
    const float* wo  = (const float*)d_in[4];
    const float* wg1 = (const float*)d_in[5];
    const float* wg2 = (const float*)d_in[6];
    const float* nw  = (const float*)d_in[7];
    float* out = (float*)d_out;

    void *pq, *pk, *pv, *patt, *pgate;
    cudaGetSymbolAddress(&pq, g_q);
    cudaGetSymbolAddress(&pk, g_k);
    cudaGetSymbolAddress(&pv, g_v);
    cudaGetSymbolAddress(&patt, g_att);
    cudaGetSymbolAddress(&pgate, g_gate);
    float* fq = (float*)pq;     float* fk = (float*)pk;   float* fv = (float*)pv;
    float* fatt = (float*)patt; float* fgate = (float*)pgate;

    void *pyh, *pyl, *pg1b, *pwoh, *pwol, *pwg2b;
    cudaGetSymbolAddress(&pyh, g_yh);
    cudaGetSymbolAddress(&pyl, g_yl);
    cudaGetSymbolAddress(&pg1b, g_g1b);
    cudaGetSymbolAddress(&pwoh, g_woh);
    cudaGetSymbolAddress(&pwol, g_wol);
    cudaGetSymbolAddress(&pwg2b, g_wg2b);

    // opt in to >48KB dynamic smem (idempotent, capture-safe)
    cudaFuncSetAttribute(scan_kernel,
                         cudaFuncAttributeMaxDynamicSharedMemorySize,
                         SCAN_SMEM_BYTES);
    cudaFuncSetAttribute(gemm_qkvg,
                         cudaFuncAttributeMaxDynamicSharedMemorySize,
                         SMEM_SPLIT1);
    cudaFuncSetAttribute((const void*)gemm_std<0, 0, 2>,
                         cudaFuncAttributeMaxDynamicSharedMemorySize,
                         SMEM_SPLIT0);
    cudaFuncSetAttribute((const void*)gemm_std<1, 0, 0>,
                         cudaFuncAttributeMaxDynamicSharedMemorySize,
                         SMEM_SPLIT1);

    // 1. pre-split weights and x into bf16 hi/lo
    split_weights<<<EE * EE / 256, 256>>>(wq, wk, wv, wo, wg1, wg2);
    split_x_kernel<<<MM * EE / 1024, 256>>>(x);

    // 2. fused q/k/v + g1 projections (grid 25x64)
    gemm_qkvg<<<dim3(25, MM / GBM), 256, SMEM_SPLIT1>>>(fq, fk, fv);

    // 3. GLA scan
    scan_kernel<<<dim3(8, HH, BB), 256, SCAN_SMEM_BYTES>>>(fq, fk, fv, fatt);

    // 4. gate = sigmoid(g1 @ wg2)  (plain bf16)
    gemm_std<0, 0, 2><<<dim3(EE / GBN, MM / GBM), 256, SMEM_SPLIT0>>>(
        (const bf16*)pg1b, nullptr, (const bf16*)pwg2b, nullptr,
        fgate, nullptr, EE, DD);

    // 5. gate * att + layernorm -> yh/yl
    gate_ln_kernel<<<MM, 256>>>(fatt, fgate, nw);

    // 6. out = y @ wo  (split bf16)
    gemm_std<1, 0, 0><<<dim3(EE / GBN, MM / GBM), 256, SMEM_SPLIT1>>>(
        (const bf16*)pyh, (const bf16*)pyl, (const bf16*)pwoh, (const bf16*)pwol,
        out, nullptr, EE, EE);
}

// round 12
// speedup vs baseline: 3.0503x; 1.0056x over previous
#include <cuda_runtime.h>
#include <cuda_bf16.h>
#include <cstdint>

// Problem constants
#define BB 4
#define TT 2048
#define EE 1024
#define DD 128
#define HH 8
#define MM (BB * TT)   // 8192 rows

typedef __nv_bfloat16 bf16;

// ---------------- scratch (static device memory; no allocation) ----------------
__device__ float g_q[MM * EE];
__device__ float g_k[MM * EE];
__device__ float g_v[MM * EE];
__device__ float g_att[MM * EE];
__device__ float g_gate[MM * EE];

__device__ __align__(16) bf16 g_xh[MM * EE];
__device__ __align__(16) bf16 g_xl[MM * EE];
__device__ __align__(16) bf16 g_yh[MM * EE];
__device__ __align__(16) bf16 g_yl[MM * EE];
__device__ __align__(16) bf16 g_g1b[MM * DD];

__device__ __align__(16) bf16 g_wqh[EE * EE];
__device__ __align__(16) bf16 g_wql[EE * EE];
__device__ __align__(16) bf16 g_wkh[EE * EE];
__device__ __align__(16) bf16 g_wkl[EE * EE];
__device__ __align__(16) bf16 g_wvh[EE * EE];
__device__ __align__(16) bf16 g_wvl[EE * EE];
__device__ __align__(16) bf16 g_woh[EE * EE];
__device__ __align__(16) bf16 g_wol[EE * EE];
__device__ __align__(16) bf16 g_wg1b[EE * DD];
__device__ __align__(16) bf16 g_wg2b[DD * EE];

// ---------------- common asm helpers ----------------
__device__ __forceinline__ void cp16(uint32_t s, const void* g) {
    asm volatile("cp.async.ca.shared.global [%0], [%1], 16;" :: "r"(s), "l"(g));
}
__device__ __forceinline__ void ldsm4(uint32_t& r0, uint32_t& r1, uint32_t& r2,
                                      uint32_t& r3, uint32_t a) {
    asm volatile("ldmatrix.sync.aligned.m8n8.x4.shared.b16 {%0,%1,%2,%3}, [%4];"
                 : "=r"(r0), "=r"(r1), "=r"(r2), "=r"(r3) : "r"(a));
}
__device__ __forceinline__ void ldsm4t(uint32_t& r0, uint32_t& r1, uint32_t& r2,
                                       uint32_t& r3, uint32_t a) {
    asm volatile("ldmatrix.sync.aligned.m8n8.x4.trans.shared.b16 {%0,%1,%2,%3}, [%4];"
                 : "=r"(r0), "=r"(r1), "=r"(r2), "=r"(r3) : "r"(a));
}
__device__ __forceinline__ void mma16816(float* d, const uint32_t* a, const uint32_t* b) {
    asm volatile("mma.sync.aligned.m16n8k16.row.col.f32.bf16.bf16.f32 "
                 "{%0,%1,%2,%3}, {%4,%5,%6,%7}, {%8,%9}, {%0,%1,%2,%3};"
                 : "+f"(d[0]), "+f"(d[1]), "+f"(d[2]), "+f"(d[3])
                 : "r"(a[0]), "r"(a[1]), "r"(a[2]), "r"(a[3]),
                   "r"(b[0]), "r"(b[1]));
}

__device__ __forceinline__ float actsel(float v, int act) {
    if (act == 1) return v / (1.0f + expf(-v));       // silu
    if (act == 2) return 1.0f / (1.0f + expf(-v));    // sigmoid
    return v;
}

// ---------------- pipelined bf16 GEMM ----------------
// C[M,N] = act(A @ B); A,B pre-split bf16 (hi[, lo]).
// CTA 128x128, GBK 32, 256 thr, warp tile 64x32, 3-stage cp.async pipeline.
// __launch_bounds__(256,2): 2 CTAs/SM (regs capped at 128; fragment liveness
// ordered so al/bl are never simultaneously live).
#define GBM 128
#define GBN 128
#define GBK 32
#define APAD 40
#define BPAD 136
#define AELEM (GBM * APAD)        // 5120 bf16
#define BELEM (GBK * BPAD)        // 4352 bf16
#define STG_ELEMS1 (2 * (AELEM + BELEM))   // split: 18944
#define STG_ELEMS0 (AELEM + BELEM)         // plain:  9472
#define SMEM_SPLIT1 (3 * STG_ELEMS1 * 2)   // 113664 B
#define SMEM_SPLIT0 (3 * STG_ELEMS0 * 2)   // 56832 B

extern __shared__ __align__(16) char dynsm[];

template <int SPLIT, int OBF>
__device__ __forceinline__ void gemm_pipe_body(
    const bf16* __restrict__ Ahg, const bf16* __restrict__ Alg,
    const bf16* __restrict__ Bhg, const bf16* __restrict__ Blg,
    float* __restrict__ C, bf16* __restrict__ Cb,
    int N, int K, int row0, int col0, int act)
{
    bf16* sm = (bf16*)dynsm;
    const int STG = SPLIT ? STG_ELEMS1 : STG_ELEMS0;

    const int tid = threadIdx.x;
    const int warp = tid >> 5, lane = tid & 31;
    const int wm = warp >> 2, wn = warp & 3;

    auto issue = [&](int itk, int buf) {
        const int k0 = itk * GBK;
        bf16* s   = sm + buf * STG;
        bf16* sAh = s;
        bf16* sAl = s + AELEM;                       // valid iff SPLIT
        bf16* sBh = s + (SPLIT ? 2 : 1) * AELEM;
        bf16* sBl = sBh + BELEM;                     // valid iff SPLIT
#pragma unroll
        for (int j = 0; j < 2; j++) {
            const int c = tid + j * 256;             // A chunk 0..511
            const int row = c >> 2, cc = (c & 3) * 8;
            const size_t g = (size_t)(row0 + row) * K + k0 + cc;
            cp16((uint32_t)__cvta_generic_to_shared(&sAh[row * APAD + cc]), Ahg + g);
            if (SPLIT)
                cp16((uint32_t)__cvta_generic_to_shared(&sAl[row * APAD + cc]), Alg + g);
        }
#pragma unroll
        for (int j = 0; j < 2; j++) {
            const int c = tid + j * 256;             // B chunk 0..511
            const int br = c >> 4, bc = (c & 15) * 8;
            const size_t g = (size_t)(k0 + br) * N + col0 + bc;
            cp16((uint32_t)__cvta_generic_to_shared(&sBh[br * BPAD + bc]), Bhg + g);
            if (SPLIT)
                cp16((uint32_t)__cvta_generic_to_shared(&sBl[br * BPAD + bc]), Blg + g);
        }
        asm volatile("cp.async.commit_group;" ::: "memory");
    };

    const int KIT = K / GBK;
    issue(0, 0);
    if (KIT > 1) issue(1, 1);

    float acc[4][4][4];
#pragma unroll
    for (int i = 0; i < 4; i++)
#pragma unroll
        for (int j = 0; j < 4; j++)
#pragma unroll
            for (int c = 0; c < 4; c++) acc[i][j][c] = 0.0f;

    const int laneRow = (lane & 7) + ((lane >> 3) & 1) * 8;
    const int laneCol = (lane >> 4) * 8;
    const uint32_t smBase = (uint32_t)__cvta_generic_to_shared(sm);

    for (int itk = 0; itk < KIT; ++itk) {
        const int buf = itk % 3;
        if (itk + 1 < KIT)
            asm volatile("cp.async.wait_group 1;" ::: "memory");
        else
            asm volatile("cp.async.wait_group 0;" ::: "memory");
        __syncthreads();
        if (itk + 2 < KIT) issue(itk + 2, (itk + 2) % 3);

        const uint32_t aH = smBase + buf * STG * 2;
        const uint32_t aL = aH + AELEM * 2;
        const uint32_t bH = aH + (SPLIT ? 2 : 1) * AELEM * 2;
        const uint32_t bL = bH + BELEM * 2;

#pragma unroll
        for (int ks = 0; ks < 2; ks++) {
            // hi fragments
            uint32_t ah[4][4];
#pragma unroll
            for (int mi = 0; mi < 4; mi++) {
                uint32_t off = (uint32_t)(((wm * 64 + mi * 16 + laneRow) * APAD
                                           + ks * 16 + laneCol) * 2);
                ldsm4(ah[mi][0], ah[mi][1], ah[mi][2], ah[mi][3], aH + off);
            }
            uint32_t bh[2][4];
#pragma unroll
            for (int p = 0; p < 2; p++) {
                uint32_t off = (uint32_t)(((ks * 16 + laneRow) * BPAD
                                           + wn * 32 + p * 16 + laneCol) * 2);
                ldsm4t(bh[p][0], bh[p][1], bh[p][2], bh[p][3], bH + off);
            }
            // hi*hi
#pragma unroll
            for (int mi = 0; mi < 4; mi++)
#pragma unroll
                for (int ni = 0; ni < 4; ni++)
                    mma16816(acc[mi][ni], ah[mi], &bh[ni >> 1][(ni & 1) * 2]);

            if (SPLIT) {
                // hi*lo: bl live, then dead before al loads
                {
                    uint32_t bl[2][4];
#pragma unroll
                    for (int p = 0; p < 2; p++) {
                        uint32_t off = (uint32_t)(((ks * 16 + laneRow) * BPAD
                                                   + wn * 32 + p * 16 + laneCol) * 2);
                        ldsm4t(bl[p][0], bl[p][1], bl[p][2], bl[p][3], bL + off);
                    }
#pragma unroll
                    for (int mi = 0; mi < 4; mi++)
#pragma unroll
                        for (int ni = 0; ni < 4; ni++)
                            mma16816(acc[mi][ni], ah[mi], &bl[ni >> 1][(ni & 1) * 2]);
                }
                // lo*hi: al reuses pressure freed by bl
                {
                    uint32_t al[4][4];
#pragma unroll
                    for (int mi = 0; mi < 4; mi++) {
                        uint32_t off = (uint32_t)(((wm * 64 + mi * 16 + laneRow) * APAD
                                                   + ks * 16 + laneCol) * 2);
                        ldsm4(al[mi][0], al[mi][1], al[mi][2], al[mi][3], aL + off);
                    }
#pragma unroll
                    for (int mi = 0; mi < 4; mi++)
#pragma unroll
                        for (int ni = 0; ni < 4; ni++)
                            mma16816(acc[mi][ni], al[mi], &bh[ni >> 1][(ni & 1) * 2]);
                }
            }
        }
    }

    // epilogue
#pragma unroll
    for (int mi = 0; mi < 4; mi++) {
#pragma unroll
        for (int ni = 0; ni < 4; ni++) {
            const int r = row0 + wm * 64 + mi * 16 + (lane >> 2);
            const int c = col0 + wn * 32 + ni * 8 + (lane & 3) * 2;
            float2 v0 = make_float2(actsel(acc[mi][ni][0], act),
                                    actsel(acc[mi][ni][1], act));
            float2 v1 = make_float2(actsel(acc[mi][ni][2], act),
                                    actsel(acc[mi][ni][3], act));
            if (OBF) {
                *(__nv_bfloat162*)&Cb[(size_t)r * N + c] =
                    __floats2bfloat162_rn(v0.x, v0.y);
                *(__nv_bfloat162*)&Cb[(size_t)(r + 8) * N + c] =
                    __floats2bfloat162_rn(v1.x, v1.y);
            } else {
                *(float2*)&C[(size_t)r * N + c]       = v0;
                *(float2*)&C[(size_t)(r + 8) * N + c] = v1;
            }
        }
    }
}

template <int SPLIT, int OBF, int ACT>
__global__ void __launch_bounds__(256, 2)
gemm_std(const bf16* __restrict__ Ah, const bf16* __restrict__ Al,
         const bf16* __restrict__ Bh, const bf16* __restrict__ Bl,
         float* __restrict__ C, bf16* __restrict__ Cb, int N, int K) {
    gemm_pipe_body<SPLIT, OBF>(Ah, Al, Bh, Bl, C, Cb, N, K,
                               blockIdx.y * GBM, blockIdx.x * GBN, ACT);
}

// Fused QKV + wg1: grid (25, 64).
__global__ void __launch_bounds__(256, 2)
gemm_qkvg(float* __restrict__ q, float* __restrict__ k, float* __restrict__ v) {
    const int bx = blockIdx.x;
    const int row0 = blockIdx.y * GBM;
    if (bx < 24) {
        const int wsel = bx >> 3;
        const bf16* Bh = (wsel == 0) ? g_wqh : (wsel == 1) ? g_wkh : g_wvh;
        const bf16* Bl = (wsel == 0) ? g_wql : (wsel == 1) ? g_wkl : g_wvl;
        float*      C  = (wsel == 0) ? q : (wsel == 1) ? k : v;
        const int act  = (wsel == 0) ? 1 : (wsel == 1) ? 2 : 0;
        gemm_pipe_body<1, 0>(g_xh, g_xl, Bh, Bl, C, nullptr,
                             EE, EE, row0, (bx & 7) * GBN, act);
    } else {
        // g1 = x @ wg1 in plain bf16 (gate path)
        gemm_pipe_body<0, 1>(g_xh, nullptr, g_wg1b, nullptr, nullptr, g_g1b,
                             DD, EE, row0, 0, 0);
    }
}

// ---------------- split kernels ----------------
__device__ __forceinline__ void split1g(bf16* hi, bf16* lo, int i, float x) {
    bf16 h = __float2bfloat16(x);
    hi[i] = h;
    lo[i] = __float2bfloat16(x - __bfloat162float(h));
}

__global__ void __launch_bounds__(256)
split_weights(const float* __restrict__ wq, const float* __restrict__ wk,
              const float* __restrict__ wv, const float* __restrict__ wo,
              const float* __restrict__ wg1, const float* __restrict__ wg2) {
    const int i = blockIdx.x * 256 + threadIdx.x;   // grid covers EE*EE
    split1g(g_wqh, g_wql, i, wq[i]);
    split1g(g_wkh, g_wkl, i, wk[i]);
    split1g(g_wvh, g_wvl, i, wv[i]);
    split1g(g_woh, g_wol, i, wo[i]);
    if (i < EE * DD) {
        g_wg1b[i] = __float2bfloat16(wg1[i]);
        g_wg2b[i] = __float2bfloat16(wg2[i]);
    }
}

__global__ void __launch_bounds__(256)
split_x_kernel(const float* __restrict__ x) {
    const int i = (blockIdx.x * 256 + threadIdx.x) * 4;
    float4 v = *(const float4*)&x[i];
    bf16 h0 = __float2bfloat16(v.x), h1 = __float2bfloat16(v.y);
    bf16 h2 = __float2bfloat16(v.z), h3 = __float2bfloat16(v.w);
    *(__nv_bfloat162*)&g_xh[i]     = __nv_bfloat162(h0, h1);
    *(__nv_bfloat162*)&g_xh[i + 2] = __nv_bfloat162(h2, h3);
    *(__nv_bfloat162*)&g_xl[i] = __floats2bfloat162_rn(
        v.x - __bfloat162float(h0), v.y - __bfloat162float(h1));
    *(__nv_bfloat162*)&g_xl[i + 2] = __floats2bfloat162_rn(
        v.z - __bfloat162float(h2), v.w - __bfloat162float(h3));
}

// ---------------- GLA scan v5: sign-folded recurrence ----------------
// S̃_t = c_t S_t  =>  S̃_t = (-f)∘S̃_{t-1} + k⊗v ;  o_t = (q_t/16)·S̃_t
// All (±1) multiplies vanish; 1/16 folded into the post-reduction store.
#define SSTEP 16
#define NBUF 3
#define NITER (TT / SSTEP)   // 128
#define SCAN_SMEM_BYTES ((NBUF * SSTEP * 128 * 2 + NBUF * SSTEP * 16) * 4)

__global__ void __launch_bounds__(256, 2)
scan_kernel(const float* __restrict__ q, const float* __restrict__ k,
            const float* __restrict__ v, float* __restrict__ att) {
    float* smem = (float*)dynsm;
    float* sQ = smem;
    float* sK = sQ + NBUF * SSTEP * 128;
    float* sV = sK + NBUF * SSTEP * 128;

    const int tid  = threadIdx.x;
    const int lane = tid & 31;
    const int warp = tid >> 5;
    const int dvb  = blockIdx.x;
    const int h    = blockIdx.y;
    const int b    = blockIdx.z;

    const size_t rowbase = (size_t)b * TT * EE + (size_t)h * DD;
    const float* qb = q + rowbase;
    const float* kb = k + rowbase;
    const float* vb = v + rowbase + dvb * 16;
    float*       ob = att + rowbase + dvb * 16 + warp * 2;

    const int r0row = tid >> 5,          r0col = (tid & 31) * 4;
    const int r1row = (tid + 256) >> 5,  r1col = r0col;
    const int vrow  = tid >> 2,          vcol  = (tid & 3) * 4;

    auto issue_stage = [&](int t0, int buf) {
        float* bQ = sQ + buf * SSTEP * 128;
        float* bK = sK + buf * SSTEP * 128;
        float* bV = sV + buf * SSTEP * 16;
        cp16((uint32_t)__cvta_generic_to_shared(&bQ[r0row * 128 + r0col]),
             qb + (size_t)(t0 + r0row) * EE + r0col);
        cp16((uint32_t)__cvta_generic_to_shared(&bQ[r1row * 128 + r1col]),
             qb + (size_t)(t0 + r1row) * EE + r1col);
        cp16((uint32_t)__cvta_generic_to_shared(&bK[r0row * 128 + r0col]),
             kb + (size_t)(t0 + r0row) * EE + r0col);
        cp16((uint32_t)__cvta_generic_to_shared(&bK[r1row * 128 + r1col]),
             kb + (size_t)(t0 + r1row) * EE + r1col);
        if (tid < 64)
            cp16((uint32_t)__cvta_generic_to_shared(&bV[vrow * 16 + vcol]),
                 vb + (size_t)(t0 + vrow) * EE + vcol);
        asm volatile("cp.async.commit_group;" ::: "memory");
    };

    issue_stage(0, 0);
    issue_stage(SSTEP, 1);

    float s0x = 0.f, s0y = 0.f, s1x = 0.f, s1y = 0.f;
    float s2x = 0.f, s2y = 0.f, s3x = 0.f, s3y = 0.f;

    for (int iter = 0; iter < NITER; ++iter) {
        const int buf = iter % NBUF;
        const int t0  = iter * SSTEP;
        const float* bQ = sQ + buf * SSTEP * 128;
        const float* bK = sK + buf * SSTEP * 128;
        const float* bV = sV + buf * SSTEP * 16;

        if (iter < NITER - 1)
            asm volatile("cp.async.wait_group 1;" ::: "memory");
        else
            asm volatile("cp.async.wait_group 0;" ::: "memory");
        __syncthreads();

        if (iter + 2 < NITER)
            issue_stage((iter + 2) * SSTEP, (iter + 2) % NBUF);

        float axs[SSTEP], ays[SSTEP];

#pragma unroll
        for (int u = 0; u < SSTEP; u++) {
            const float4 qc = *(const float4*)&bQ[u * 128 + lane * 4];
            const float4 kc = *(const float4*)&bK[u * 128 + lane * 4];
            const float2 vv = *(const float2*)&bV[u * 16 + warp * 2];

            // negated decay: f' = k - 1 = -(1-k)
            const float f0 = kc.x - 1.0f, f1 = kc.y - 1.0f;
            const float f2 = kc.z - 1.0f, f3 = kc.w - 1.0f;
            const float vx = vv.x, vy = vv.y;

            s0x = fmaf(f0, s0x, kc.x * vx);  s0y = fmaf(f0, s0y, kc.x * vy);
            s1x = fmaf(f1, s1x, kc.y * vx);  s1y = fmaf(f1, s1y, kc.y * vy);
            s2x = fmaf(f2, s2x, kc.z * vx);  s2y = fmaf(f2, s2y, kc.z * vy);
            s3x = fmaf(f3, s3x, kc.w * vx);  s3y = fmaf(f3, s3y, kc.w * vy);

            float ax = qc.x * s0x; ax = fmaf(qc.y, s1x, ax);
            ax = fmaf(qc.z, s2x, ax); ax = fmaf(qc.w, s3x, ax);
            float ay = qc.x * s0y; ay = fmaf(qc.y, s1y, ay);
            ay = fmaf(qc.z, s2y, ay); ay = fmaf(qc.w, s3y, ay);
            axs[u] = ax;
            ays[u] = ay;
        }

#pragma unroll
        for (int m = 16; m; m >>= 1) {
#pragma unroll
            for (int u = 0; u < SSTEP; u++) {
                axs[u] += __shfl_xor_sync(0xffffffffu, axs[u], m);
                ays[u] += __shfl_xor_sync(0xffffffffu, ays[u], m);
            }
        }

        if (lane == 0) {
#pragma unroll
            for (int u = 0; u < SSTEP; u++)
                *(float2*)(ob + (size_t)(t0 + u) * EE) =
                    make_float2(axs[u] * 0.0625f, ays[u] * 0.0625f);
        }
    }
}

// ---------------- gate multiply + layernorm -> bf16 hi/lo ----------------
__global__ void __launch_bounds__(256)
gate_ln_kernel(const float* __restrict__ att, const float* __restrict__ gate,
               const float* __restrict__ nw) {
    const int row = blockIdx.x;
    const int tid = threadIdx.x;
    const int lane = tid & 31, wid = tid >> 5;
    __shared__ float red[8];

    float4 a = ((const float4*)(att + (size_t)row * EE))[tid];
    float4 g = ((const float4*)(gate + (size_t)row * EE))[tid];
    float4 yv;
    yv.x = a.x * g.x; yv.y = a.y * g.y; yv.z = a.z * g.z; yv.w = a.w * g.w;

    float ssum = yv.x + yv.y + yv.z + yv.w;
#pragma unroll
    for (int m = 16; m; m >>= 1) ssum += __shfl_xor_sync(0xffffffffu, ssum, m);
    if (lane == 0) red[wid] = ssum;
    __syncthreads();
    float tot = 0.0f;
#pragma unroll
    for (int w = 0; w < 8; w++) tot += red[w];
    const float mean = tot * (1.0f / (float)EE);
    __syncthreads();

    float dx = yv.x - mean, dy = yv.y - mean, dz = yv.z - mean, dw = yv.w - mean;
    float ssq = dx * dx + dy * dy + dz * dz + dw * dw;
#pragma unroll
    for (int m = 16; m; m >>= 1) ssq += __shfl_xor_sync(0xffffffffu, ssq, m);
    if (lane == 0) red[wid] = ssq;
    __syncthreads();
    float totsq = 0.0f;
#pragma unroll
    for (int w = 0; w < 8; w++) totsq += red[w];
    const float rstd = rsqrtf(totsq * (1.0f / (float)EE) + 1e-5f);

    float4 w4 = ((const float4*)nw)[tid];
    float o0 = dx * rstd * w4.x;
    float o1 = dy * rstd * w4.y;
    float o2 = dz * rstd * w4.z;
    float o3 = dw * rstd * w4.w;

    const size_t base = (size_t)row * EE + tid * 4;
    bf16 h0 = __float2bfloat16(o0), h1 = __float2bfloat16(o1);
    bf16 h2 = __float2bfloat16(o2), h3 = __float2bfloat16(o3);
    *(__nv_bfloat162*)&g_yh[base]     = __nv_bfloat162(h0, h1);
    *(__nv_bfloat162*)&g_yh[base + 2] = __nv_bfloat162(h2, h3);
    *(__nv_bfloat162*)&g_yl[base] = __floats2bfloat162_rn(
        o0 - __bfloat162float(h0), o1 - __bfloat162float(h1));
    *(__nv_bfloat162*)&g_yl[base + 2] = __floats2bfloat162_rn(
        o2 - __bfloat162float(h2), o3 - __bfloat162float(h3));
}

// ---------------- launch ----------------
extern "C" void kernel_launch(void* const* d_in, const int* in_sizes, int n_in,
                              void* d_out, int out_size) {
    const float* x   = (const float*)d_in[0];
    const float* wq  = (const float*)d_in[1];
    const float* wk  = (const float*)d_in[2];
    const float* wv  = (const float*)d_in[3];
    const float* wo  = (const float*)d_in[4];
    const float* wg1 = (const float*)d_in[5];
    const float* wg2 = (const float*)d_in[6];
    const float* nw  = (const float*)d_in[7];
    float* out = (float*)d_out;

    void *pq, *pk, *pv, *patt, *pgate;
    cudaGetSymbolAddress(&pq, g_q);
    cudaGetSymbolAddress(&pk, g_k);
    cudaGetSymbolAddress(&pv, g_v);
    cudaGetSymbolAddress(&patt, g_att);
    cudaGetSymbolAddress(&pgate, g_gate);
    float* fq = (float*)pq;     float* fk = (float*)pk;   float* fv = (float*)pv;
    float* fatt = (float*)patt; float* fgate = (float*)pgate;

    void *pyh, *pyl, *pg1b, *pwoh, *pwol, *pwg2b;
    cudaGetSymbolAddress(&pyh, g_yh);
    cudaGetSymbolAddress(&pyl, g_yl);
    cudaGetSymbolAddress(&pg1b, g_g1b);
    cudaGetSymbolAddress(&pwoh, g_woh);
    cudaGetSymbolAddress(&pwol, g_wol);
    cudaGetSymbolAddress(&pwg2b, g_wg2b);

    // opt in to >48KB dynamic smem (idempotent, capture-safe)
    cudaFuncSetAttribute(scan_kernel,
                         cudaFuncAttributeMaxDynamicSharedMemorySize,
                         SCAN_SMEM_BYTES);
    cudaFuncSetAttribute(gemm_qkvg,
                         cudaFuncAttributeMaxDynamicSharedMemorySize,
                         SMEM_SPLIT1);
    cudaFuncSetAttribute((const void*)gemm_std<0, 0, 2>,
                         cudaFuncAttributeMaxDynamicSharedMemorySize,
                         SMEM_SPLIT0);
    cudaFuncSetAttribute((const void*)gemm_std<1, 0, 0>,
                         cudaFuncAttributeMaxDynamicSharedMemorySize,
                         SMEM_SPLIT1);

    // 1. pre-split weights and x into bf16 hi/lo
    split_weights<<<EE * EE / 256, 256>>>(wq, wk, wv, wo, wg1, wg2);
    split_x_kernel<<<MM * EE / 1024, 256>>>(x);

    // 2. fused q/k/v + g1 projections (grid 25x64)
    gemm_qkvg<<<dim3(25, MM / GBM), 256, SMEM_SPLIT1>>>(fq, fk, fv);

    // 3. GLA scan
    scan_kernel<<<dim3(8, HH, BB), 256, SCAN_SMEM_BYTES>>>(fq, fk, fv, fatt);

    // 4. gate = sigmoid(g1 @ wg2)  (plain bf16)
    gemm_std<0, 0, 2><<<dim3(EE / GBN, MM / GBM), 256, SMEM_SPLIT0>>>(
        (const bf16*)pg1b, nullptr, (const bf16*)pwg2b, nullptr,
        fgate, nullptr, EE, DD);

    // 5. gate * att + layernorm -> yh/yl
    gate_ln_kernel<<<MM, 256>>>(fatt, fgate, nw);

    // 6. out = y @ wo  (split bf16)
    gemm_std<1, 0, 0><<<dim3(EE / GBN, MM / GBM), 256, SMEM_SPLIT1>>>(
        (const bf16*)pyh, (const bf16*)pyl, (const bf16*)pwoh, (const bf16*)pwol,
        out, nullptr, EE, EE);
}

// round 15
// speedup vs baseline: 3.1225x; 1.0237x over previous
#include <cuda_runtime.h>
#include <cuda_bf16.h>
#include <cstdint>

// Problem constants
#define BB 4
#define TT 2048
#define EE 1024
#define DD 128
#define HH 8
#define MM (BB * TT)   // 8192 rows

typedef __nv_bfloat16 bf16;

// ---------------- scratch (static device memory; no allocation) ----------------
__device__ float g_q[MM * EE];
__device__ float g_k[MM * EE];
__device__ float g_v[MM * EE];
__device__ float g_att[MM * EE];
__device__ float g_gate[MM * EE];

__device__ __align__(16) bf16 g_xh[MM * EE];
__device__ __align__(16) bf16 g_xl[MM * EE];
__device__ __align__(16) bf16 g_yh[MM * EE];
__device__ __align__(16) bf16 g_yl[MM * EE];
__device__ __align__(16) bf16 g_g1b[MM * DD];

__device__ __align__(16) bf16 g_wqh[EE * EE];
__device__ __align__(16) bf16 g_wql[EE * EE];
__device__ __align__(16) bf16 g_wkh[EE * EE];
__device__ __align__(16) bf16 g_wkl[EE * EE];
__device__ __align__(16) bf16 g_wvh[EE * EE];
__device__ __align__(16) bf16 g_wvl[EE * EE];
__device__ __align__(16) bf16 g_woh[EE * EE];
__device__ __align__(16) bf16 g_wol[EE * EE];
__device__ __align__(16) bf16 g_wg1b[EE * DD];
__device__ __align__(16) bf16 g_wg2b[DD * EE];

// ---------------- common asm helpers ----------------
__device__ __forceinline__ void cp16(uint32_t s, const void* g) {
    asm volatile("cp.async.ca.shared.global [%0], [%1], 16;" :: "r"(s), "l"(g));
}
__device__ __forceinline__ void ldsm4(uint32_t& r0, uint32_t& r1, uint32_t& r2,
                                      uint32_t& r3, uint32_t a) {
    asm volatile("ldmatrix.sync.aligned.m8n8.x4.shared.b16 {%0,%1,%2,%3}, [%4];"
                 : "=r"(r0), "=r"(r1), "=r"(r2), "=r"(r3) : "r"(a));
}
__device__ __forceinline__ void ldsm4t(uint32_t& r0, uint32_t& r1, uint32_t& r2,
                                       uint32_t& r3, uint32_t a) {
    asm volatile("ldmatrix.sync.aligned.m8n8.x4.trans.shared.b16 {%0,%1,%2,%3}, [%4];"
                 : "=r"(r0), "=r"(r1), "=r"(r2), "=r"(r3) : "r"(a));
}
__device__ __forceinline__ void mma16816(float* d, const uint32_t* a, const uint32_t* b) {
    asm volatile("mma.sync.aligned.m16n8k16.row.col.f32.bf16.bf16.f32 "
                 "{%0,%1,%2,%3}, {%4,%5,%6,%7}, {%8,%9}, {%0,%1,%2,%3};"
                 : "+f"(d[0]), "+f"(d[1]), "+f"(d[2]), "+f"(d[3])
                 : "r"(a[0]), "r"(a[1]), "r"(a[2]), "r"(a[3]),
                   "r"(b[0]), "r"(b[1]));
}

// Fast activations: sigmoid = rcp(1+ex2(-x*log2e)) — ~4 instr + 2 MUFU
// vs ~20 instr for library expf + precise div. rel err ~2^-21, safe for the
// decay chain (accumulated ~3e-5 << 1e-3 budget).
__device__ __forceinline__ float actsel(float v, int act) {
    if (act == 1) {
        float s = __fdividef(1.0f, 1.0f + __expf(-v));   // silu
        return v * s;
    }
    if (act == 2) return __fdividef(1.0f, 1.0f + __expf(-v));  // sigmoid
    return v;
}

// ---------------- pipelined bf16 GEMM ----------------
#define GBM 128
#define GBN 128
#define GBK 32
#define APAD 40
#define BPAD 136
#define AELEM (GBM * APAD)        // 5120 bf16
#define BELEM (GBK * BPAD)        // 4352 bf16
#define STG_ELEMS1 (2 * (AELEM + BELEM))   // split: 18944
#define STG_ELEMS0 (AELEM + BELEM)         // plain:  9472
#define SMEM_SPLIT1 (3 * STG_ELEMS1 * 2)   // 113664 B
#define SMEM_SPLIT0 (3 * STG_ELEMS0 * 2)   // 56832 B

extern __shared__ __align__(16) char dynsm[];

template <int SPLIT, int OBF>
__device__ __forceinline__ void gemm_pipe_body(
    const bf16* __restrict__ Ahg, const bf16* __restrict__ Alg,
    const bf16* __restrict__ Bhg, const bf16* __restrict__ Blg,
    float* __restrict__ C, bf16* __restrict__ Cb,
    int N, int K, int row0, int col0, int act)
{
    bf16* sm = (bf16*)dynsm;
    const int STG = SPLIT ? STG_ELEMS1 : STG_ELEMS0;

    const int tid = threadIdx.x;
    const int warp = tid >> 5, lane = tid & 31;
    const int wm = warp >> 2, wn = warp & 3;

    auto issue = [&](int itk, int buf) {
        const int k0 = itk * GBK;
        bf16* s   = sm + buf * STG;
        bf16* sAh = s;
        bf16* sAl = s + AELEM;
        bf16* sBh = s + (SPLIT ? 2 : 1) * AELEM;
        bf16* sBl = sBh + BELEM;
#pragma unroll
        for (int j = 0; j < 2; j++) {
            const int c = tid + j * 256;
            const int row = c >> 2, cc = (c & 3) << 3;
            const size_t g = (size_t)(row0 + row) * K + k0 + cc;
            cp16((uint32_t)__cvta_generic_to_shared(&sAh[row * APAD + cc]), Ahg + g);
            if (SPLIT)
                cp16((uint32_t)__cvta_generic_to_shared(&sAl[row * APAD + cc]), Alg + g);
        }
#pragma unroll
        for (int j = 0; j < 2; j++) {
            const int c = tid + j * 256;
            const int br = c >> 4, bc = (c & 15) << 3;
            const size_t g = (size_t)(k0 + br) * N + col0 + bc;
            cp16((uint32_t)__cvta_generic_to_shared(&sBh[br * BPAD + bc]), Bhg + g);
            if (SPLIT)
                cp16((uint32_t)__cvta_generic_to_shared(&sBl[br * BPAD + bc]), Blg + g);
        }
        asm volatile("cp.async.commit_group;" ::: "memory");
    };

    const int KIT = K / GBK;
    issue(0, 0);
    if (KIT > 1) issue(1, 1);

    float acc[4][4][4];
#pragma unroll
    for (int i = 0; i < 4; i++)
#pragma unroll
        for (int j = 0; j < 4; j++)
#pragma unroll
            for (int c = 0; c < 4; c++) acc[i][j][c] = 0.0f;

    const int laneRow = (lane & 7) + ((lane >> 3) & 1) * 8;
    const int laneCol = (lane >> 4) * 8;
    const uint32_t smBase = (uint32_t)__cvta_generic_to_shared(sm);

    for (int itk = 0; itk < KIT; ++itk) {
        const int buf = itk % 3;
        if (itk + 1 < KIT)
            asm volatile("cp.async.wait_group 1;" ::: "memory");
        else
            asm volatile("cp.async.wait_group 0;" ::: "memory");
        __syncthreads();
        if (itk + 2 < KIT) issue(itk + 2, (itk + 2) % 3);

        const uint32_t aH = smBase + buf * STG * 2;
        const uint32_t aL = aH + AELEM * 2;
        const uint32_t bH = aH + (SPLIT ? 2 : 1) * AELEM * 2;
        const uint32_t bL = bH + BELEM * 2;

#pragma unroll
        for (int ks = 0; ks < 2; ks++) {
            uint32_t ah[4][4];
#pragma unroll
            for (int mi = 0; mi < 4; mi++) {
                uint32_t off = (uint32_t)(((wm * 64 + mi * 16 + laneRow) * APAD
                                           + ks * 16 + laneCol) * 2);
                ldsm4(ah[mi][0], ah[mi][1], ah[mi][2], ah[mi][3], aH + off);
            }
            uint32_t bh[2][4];
#pragma unroll
            for (int p = 0; p < 2; p++) {
                uint32_t off = (uint32_t)(((ks * 16 + laneRow) * BPAD
                                           + wn * 32 + p * 16 + laneCol) * 2);
                ldsm4t(bh[p][0], bh[p][1], bh[p][2], bh[p][3], bH + off);
            }
#pragma unroll
            for (int mi = 0; mi < 4; mi++)
#pragma unroll
                for (int ni = 0; ni < 4; ni++)
                    mma16816(acc[mi][ni], ah[mi], &bh[ni >> 1][(ni & 1) * 2]);

            if (SPLIT) {
                {
                    uint32_t bl[2][4];
#pragma unroll
                    for (int p = 0; p < 2; p++) {
                        uint32_t off = (uint32_t)(((ks * 16 + laneRow) * BPAD
                                                   + wn * 32 + p * 16 + laneCol) * 2);
                        ldsm4t(bl[p][0], bl[p][1], bl[p][2], bl[p][3], bL + off);
                    }
#pragma unroll
                    for (int mi = 0; mi < 4; mi++)
#pragma unroll
                        for (int ni = 0; ni < 4; ni++)
                            mma16816(acc[mi][ni], ah[mi], &bl[ni >> 1][(ni & 1) * 2]);
                }
                {
                    uint32_t al[4][4];
#pragma unroll
                    for (int mi = 0; mi < 4; mi++) {
                        uint32_t off = (uint32_t)(((wm * 64 + mi * 16 + laneRow) * APAD
                                                   + ks * 16 + laneCol) * 2);
                        ldsm4(al[mi][0], al[mi][1], al[mi][2], al[mi][3], aL + off);
                    }
#pragma unroll
                    for (int mi = 0; mi < 4; mi++)
#pragma unroll
                        for (int ni = 0; ni < 4; ni++)
                            mma16816(acc[mi][ni], al[mi], &bh[ni >> 1][(ni & 1) * 2]);
                }
            }
        }
    }

    // epilogue (fast activations)
#pragma unroll
    for (int mi = 0; mi < 4; mi++) {
#pragma unroll
        for (int ni = 0; ni < 4; ni++) {
            const int r = row0 + wm * 64 + mi * 16 + (lane >> 2);
            const int c = col0 + wn * 32 + ni * 8 + (lane & 3) * 2;
            float2 v0 = make_float2(actsel(acc[mi][ni][0], act),
                                    actsel(acc[mi][ni][1], act));
            float2 v1 = make_float2(actsel(acc[mi][ni][2], act),
                                    actsel(acc[mi][ni][3], act));
            if (OBF) {
                *(__nv_bfloat162*)&Cb[(size_t)r * N + c] =
                    __floats2bfloat162_rn(v0.x, v0.y);
                *(__nv_bfloat162*)&Cb[(size_t)(r + 8) * N + c] =
                    __floats2bfloat162_rn(v1.x, v1.y);
            } else {
                *(float2*)&C[(size_t)r * N + c]       = v0;
                *(float2*)&C[(size_t)(r + 8) * N + c] = v1;
            }
        }
    }
}

template <int SPLIT, int OBF, int ACT>
__global__ void __launch_bounds__(256, 2)
gemm_std(const bf16* __restrict__ Ah, const bf16* __restrict__ Al,
         const bf16* __restrict__ Bh, const bf16* __restrict__ Bl,
         float* __restrict__ C, bf16* __restrict__ Cb, int N, int K) {
    gemm_pipe_body<SPLIT, OBF>(Ah, Al, Bh, Bl, C, Cb, N, K,
                               blockIdx.y * GBM, blockIdx.x * GBN, ACT);
}

// Fused QKV + wg1: grid (25, 64).
__global__ void __launch_bounds__(256, 2)
gemm_qkvg(float* __restrict__ q, float* __restrict__ k, float* __restrict__ v) {
    const int bx = blockIdx.x;
    const int row0 = blockIdx.y * GBM;
    if (bx < 24) {
        const int wsel = bx >> 3;
        const bf16* Bh = (wsel == 0) ? g_wqh : (wsel == 1) ? g_wkh : g_wvh;
        const bf16* Bl = (wsel == 0) ? g_wql : (wsel == 1) ? g_wkl : g_wvl;
        float*      C  = (wsel == 0) ? q : (wsel == 1) ? k : v;
        const int act  = (wsel == 0) ? 1 : (wsel == 1) ? 2 : 0;
        gemm_pipe_body<1, 0>(g_xh, g_xl, Bh, Bl, C, nullptr,
                             EE, EE, row0, (bx & 7) * GBN, act);
    } else {
        gemm_pipe_body<0, 1>(g_xh, nullptr, g_wg1b, nullptr, nullptr, g_g1b,
                             DD, EE, row0, 0, 0);
    }
}

// ---------------- split kernels ----------------
__device__ __forceinline__ void split1g(bf16* hi, bf16* lo, int i, float x) {
    bf16 h = __float2bfloat16(x);
    hi[i] = h;
    lo[i] = __float2bfloat16(x - __bfloat162float(h));
}

__global__ void __launch_bounds__(256)
split_weights(const float* __restrict__ wq, const float* __restrict__ wk,
              const float* __restrict__ wv, const float* __restrict__ wo,
              const float* __restrict__ wg1, const float* __restrict__ wg2) {
    const int i = blockIdx.x * 256 + threadIdx.x;
    split1g(g_wqh, g_wql, i, wq[i]);
    split1g(g_wkh, g_wkl, i, wk[i]);
    split1g(g_wvh, g_wvl, i, wv[i]);
    split1g(g_woh, g_wol, i, wo[i]);
    if (i < EE * DD) {
        g_wg1b[i] = __float2bfloat16(wg1[i]);
        g_wg2b[i] = __float2bfloat16(wg2[i]);
    }
}

__global__ void __launch_bounds__(256)
split_x_kernel(const float* __restrict__ x) {
    const int i = (blockIdx.x * 256 + threadIdx.x) * 4;
    float4 v = *(const float4*)&x[i];
    bf16 h0 = __float2bfloat16(v.x), h1 = __float2bfloat16(v.y);
    bf16 h2 = __float2bfloat16(v.z), h3 = __float2bfloat16(v.w);
    *(__nv_bfloat162*)&g_xh[i]     = __nv_bfloat162(h0, h1);
    *(__nv_bfloat162*)&g_xh[i + 2] = __nv_bfloat162(h2, h3);
    *(__nv_bfloat162*)&g_xl[i] = __floats2bfloat162_rn(
        v.x - __bfloat162float(h0), v.y - __bfloat162float(h1));
    *(__nv_bfloat162*)&g_xl[i + 2] = __floats2bfloat162_rn(
        v.z - __bfloat162float(h2), v.w - __bfloat162float(h3));
}

// ---------------- GLA scan v5 (unchanged from R12) ----------------
#define SSTEP 16
#define NBUF 3
#define NITER (TT / SSTEP)   // 128
#define SCAN_SMEM_BYTES ((NBUF * SSTEP * 128 * 2 + NBUF * SSTEP * 16) * 4)

__global__ void __launch_bounds__(256, 2)
scan_kernel(const float* __restrict__ q, const float* __restrict__ k,
            const float* __restrict__ v, float* __restrict__ att) {
    float* smem = (float*)dynsm;
    float* sQ = smem;
    float* sK = sQ + NBUF * SSTEP * 128;
    float* sV = sK + NBUF * SSTEP * 128;

    const int tid  = threadIdx.x;
    const int lane = tid & 31;
    const int warp = tid >> 5;
    const int dvb  = blockIdx.x;
    const int h    = blockIdx.y;
    const int b    = blockIdx.z;

    const size_t rowbase = (size_t)b * TT * EE + (size_t)h * DD;
    const float* qb = q + rowbase;
    const float* kb = k + rowbase;
    const float* vb = v + rowbase + dvb * 16;
    float*       ob = att + rowbase + dvb * 16 + warp * 2;

    const int r0row = tid >> 5,          r0col = (tid & 31) * 4;
    const int r1row = (tid + 256) >> 5,  r1col = r0col;
    const int vrow  = tid >> 2,          vcol  = (tid & 3) * 4;

    auto issue_stage = [&](int t0, int buf) {
        float* bQ = sQ + buf * SSTEP * 128;
        float* bK = sK + buf * SSTEP * 128;
        float* bV = sV + buf * SSTEP * 16;
        cp16((uint32_t)__cvta_generic_to_shared(&bQ[r0row * 128 + r0col]),
             qb + (size_t)(t0 + r0row) * EE + r0col);
        cp16((uint32_t)__cvta_generic_to_shared(&bQ[r1row * 128 + r1col]),
             qb + (size_t)(t0 + r1row) * EE + r1col);
        cp16((uint32_t)__cvta_generic_to_shared(&bK[r0row * 128 + r0col]),
             kb + (size_t)(t0 + r0row) * EE + r0col);
        cp16((uint32_t)__cvta_generic_to_shared(&bK[r1row * 128 + r1col]),
             kb + (size_t)(t0 + r1row) * EE + r1col);
        if (tid < 64)
            cp16((uint32_t)__cvta_generic_to_shared(&bV[vrow * 16 + vcol]),
                 vb + (size_t)(t0 + vrow) * EE + vcol);
        asm volatile("cp.async.commit_group;" ::: "memory");
    };

    issue_stage(0, 0);
    issue_stage(SSTEP, 1);

    float s0x = 0.f, s0y = 0.f, s1x = 0.f, s1y = 0.f;
    float s2x = 0.f, s2y = 0.f, s3x = 0.f, s3y = 0.f;

    for (int iter = 0; iter < NITER; ++iter) {
        const int buf = iter % NBUF;
        const int t0  = iter * SSTEP;
        const float* bQ = sQ + buf * SSTEP * 128;
        const float* bK = sK + buf * SSTEP * 128;
        const float* bV = sV + buf * SSTEP * 16;

        if (iter < NITER - 1)
            asm volatile("cp.async.wait_group 1;" ::: "memory");
        else
            asm volatile("cp.async.wait_group 0;" ::: "memory");
        __syncthreads();

        if (iter + 2 < NITER)
            issue_stage((iter + 2) * SSTEP, (iter + 2) % NBUF);

        float axs[SSTEP], ays[SSTEP];

#pragma unroll
        for (int u = 0; u < SSTEP; u++) {
            const float4 qc = *(const float4*)&bQ[u * 128 + lane * 4];
            const float4 kc = *(const float4*)&bK[u * 128 + lane * 4];
            const float2 vv = *(const float2*)&bV[u * 16 + warp * 2];

            const float f0 = kc.x - 1.0f, f1 = kc.y - 1.0f;
            const float f2 = kc.z - 1.0f, f3 = kc.w - 1.0f;
            const float vx = vv.x, vy = vv.y;

            s0x = fmaf(f0, s0x, kc.x * vx);  s0y = fmaf(f0, s0y, kc.x * vy);
            s1x = fmaf(f1, s1x, kc.y * vx);  s1y = fmaf(f1, s1y, kc.y * vy);
            s2x = fmaf(f2, s2x, kc.z * vx);  s2y = fmaf(f2, s2y, kc.z * vy);
            s3x = fmaf(f3, s3x, kc.w * vx);  s3y = fmaf(f3, s3y, kc.w * vy);

            float ax = qc.x * s0x; ax = fmaf(qc.y, s1x, ax);
            ax = fmaf(qc.z, s2x, ax); ax = fmaf(qc.w, s3x, ax);
            float ay = qc.x * s0y; ay = fmaf(qc.y, s1y, ay);
            ay = fmaf(qc.z, s2y, ay); ay = fmaf(qc.w, s3y, ay);
            axs[u] = ax;
            ays[u] = ay;
        }

#pragma unroll
        for (int m = 16; m; m >>= 1) {
#pragma unroll
            for (int u = 0; u < SSTEP; u++) {
                axs[u] += __shfl_xor_sync(0xffffffffu, axs[u], m);
                ays[u] += __shfl_xor_sync(0xffffffffu, ays[u], m);
            }
        }

        if (lane == 0) {
#pragma unroll
            for (int u = 0; u < SSTEP; u++)
                *(float2*)(ob + (size_t)(t0 + u) * EE) =
                    make_float2(axs[u] * 0.0625f, ays[u] * 0.0625f);
        }
    }
}

// ---------------- gate multiply + layernorm -> bf16 hi/lo ----------------
__global__ void __launch_bounds__(256)
gate_ln_kernel(const float* __restrict__ att, const float* __restrict__ gate,
               const float* __restrict__ nw) {
    const int row = blockIdx.x;
    const int tid = threadIdx.x;
    const int lane = tid & 31, wid = tid >> 5;
    __shared__ float red[8];

    float4 a = ((const float4*)(att + (size_t)row * EE))[tid];
    float4 g = ((const float4*)(gate + (size_t)row * EE))[tid];
    float4 yv;
    yv.x = a.x * g.x; yv.y = a.y * g.y; yv.z = a.z * g.z; yv.w = a.w * g.w;

    float ssum = yv.x + yv.y + yv.z + yv.w;
#pragma unroll
    for (int m = 16; m; m >>= 1) ssum += __shfl_xor_sync(0xffffffffu, ssum, m);
    if (lane == 0) red[wid] = ssum;
    __syncthreads();
    float tot = 0.0f;
#pragma unroll
    for (int w = 0; w < 8; w++) tot += red[w];
    const float mean = tot * (1.0f / (float)EE);
    __syncthreads();

    float dx = yv.x - mean, dy = yv.y - mean, dz = yv.z - mean, dw = yv.w - mean;
    float ssq = dx * dx + dy * dy + dz * dz + dw * dw;
#pragma unroll
    for (int m = 16; m; m >>= 1) ssq += __shfl_xor_sync(0xffffffffu, ssq, m);
    if (lane == 0) red[wid] = ssq;
    __syncthreads();
    float totsq = 0.0f;
#pragma unroll
    for (int w = 0; w < 8; w++) totsq += red[w];
    const float rstd = rsqrtf(totsq * (1.0f / (float)EE) + 1e-5f);

    float4 w4 = ((const float4*)nw)[tid];
    float o0 = dx * rstd * w4.x;
    float o1 = dy * rstd * w4.y;
    float o2 = dz * rstd * w4.z;
    float o3 = dw * rstd * w4.w;

    const size_t base = (size_t)row * EE + tid * 4;
    bf16 h0 = __float2bfloat16(o0), h1 = __float2bfloat16(o1);
    bf16 h2 = __float2bfloat16(o2), h3 = __float2bfloat16(o3);
    *(__nv_bfloat162*)&g_yh[base]     = __nv_bfloat162(h0, h1);
    *(__nv_bfloat162*)&g_yh[base + 2] = __nv_bfloat162(h2, h3);
    *(__nv_bfloat162*)&g_yl[base] = __floats2bfloat162_rn(
        o0 - __bfloat162float(h0), o1 - __bfloat162float(h1));
    *(__nv_bfloat162*)&g_yl[base + 2] = __floats2bfloat162_rn(
        o2 - __bfloat162float(h2), o3 - __bfloat162float(h3));
}

// ---------------- launch ----------------
extern "C" void kernel_launch(void* const* d_in, const int* in_sizes, int n_in,
                              void* d_out, int out_size) {
    const float* x   = (const float*)d_in[0];
    const float* wq  = (const float*)d_in[1];
    const float* wk  = (const float*)d_in[2];
    const float* wv  = (const float*)d_in[3];
    const float* wo  = (const float*)d_in[4];
    const float* wg1 = (const float*)d_in[5];
    const float* wg2 = (const float*)d_in[6];
    const float* nw  = (const float*)d_in[7];
    float* out = (float*)d_out;

    void *pq, *pk, *pv, *patt, *pgate;
    cudaGetSymbolAddress(&pq, g_q);
    cudaGetSymbolAddress(&pk, g_k);
    cudaGetSymbolAddress(&pv, g_v);
    cudaGetSymbolAddress(&patt, g_att);
    cudaGetSymbolAddress(&pgate, g_gate);
    float* fq = (float*)pq;     float* fk = (float*)pk;   float* fv = (float*)pv;
    float* fatt = (float*)patt; float* fgate = (float*)pgate;

    void *pyh, *pyl, *pg1b, *pwoh, *pwol, *pwg2b;
    cudaGetSymbolAddress(&pyh, g_yh);
    cudaGetSymbolAddress(&pyl, g_yl);
    cudaGetSymbolAddress(&pg1b, g_g1b);
    cudaGetSymbolAddress(&pwoh, g_woh);
    cudaGetSymbolAddress(&pwol, g_wol);
    cudaGetSymbolAddress(&pwg2b, g_wg2b);

    cudaFuncSetAttribute(scan_kernel,
                         cudaFuncAttributeMaxDynamicSharedMemorySize,
                         SCAN_SMEM_BYTES);
    cudaFuncSetAttribute(gemm_qkvg,
                         cudaFuncAttributeMaxDynamicSharedMemorySize,
                         SMEM_SPLIT1);
    cudaFuncSetAttribute((const void*)gemm_std<0, 0, 2>,
                         cudaFuncAttributeMaxDynamicSharedMemorySize,
                         SMEM_SPLIT0);
    cudaFuncSetAttribute((const void*)gemm_std<1, 0, 0>,
                         cudaFuncAttributeMaxDynamicSharedMemorySize,
                         SMEM_SPLIT1);

    // 1. pre-split weights and x into bf16 hi/lo
    split_weights<<<EE * EE / 256, 256>>>(wq, wk, wv, wo, wg1, wg2);
    split_x_kernel<<<MM * EE / 1024, 256>>>(x);

    // 2. fused q/k/v + g1 projections (grid 25x64)
    gemm_qkvg<<<dim3(25, MM / GBM), 256, SMEM_SPLIT1>>>(fq, fk, fv);

    // 3. GLA scan
    scan_kernel<<<dim3(8, HH, BB), 256, SCAN_SMEM_BYTES>>>(fq, fk, fv, fatt);

    // 4. gate = sigmoid(g1 @ wg2)  (plain bf16)
    gemm_std<0, 0, 2><<<dim3(EE / GBN, MM / GBM), 256, SMEM_SPLIT0>>>(
        (const bf16*)pg1b, nullptr, (const bf16*)pwg2b, nullptr,
        fgate, nullptr, EE, DD);

    // 5. gate * att + layernorm -> yh/yl
    gate_ln_kernel<<<MM, 256>>>(fatt, fgate, nw);

    // 6. out = y @ wo  (split bf16)
    gemm_std<1, 0, 0><<<dim3(EE / GBN, MM / GBM), 256, SMEM_SPLIT1>>>(
        (const bf16*)pyh, (const bf16*)pyl, (const bf16*)pwoh, (const bf16*)pwol,
        out, nullptr, EE, EE);
}

// round 16
// speedup vs baseline: 3.6325x; 1.1633x over previous
#include <cuda_runtime.h>
#include <cuda_bf16.h>
#include <cstdint>

// Problem constants
#define BB 4
#define TT 2048
#define EE 1024
#define DD 128
#define HH 8
#define MM (BB * TT)   // 8192 rows

typedef __nv_bfloat16 bf16;

// ---------------- scratch (static device memory; no allocation) ----------------
__device__ float g_q[MM * EE];
__device__ float g_k[MM * EE];
__device__ float g_v[MM * EE];
__device__ float g_att[MM * EE];
__device__ float g_gate[MM * EE];

__device__ __align__(16) bf16 g_xh[MM * EE];
__device__ __align__(16) bf16 g_xl[MM * EE];
__device__ __align__(16) bf16 g_yh[MM * EE];
__device__ __align__(16) bf16 g_yl[MM * EE];
__device__ __align__(16) bf16 g_g1b[MM * DD];

__device__ __align__(16) bf16 g_wqh[EE * EE];
__device__ __align__(16) bf16 g_wql[EE * EE];
__device__ __align__(16) bf16 g_wkh[EE * EE];
__device__ __align__(16) bf16 g_wkl[EE * EE];
__device__ __align__(16) bf16 g_wvh[EE * EE];
__device__ __align__(16) bf16 g_wvl[EE * EE];
__device__ __align__(16) bf16 g_woh[EE * EE];
__device__ __align__(16) bf16 g_wol[EE * EE];
__device__ __align__(16) bf16 g_wg1b[EE * DD];
__device__ __align__(16) bf16 g_wg2b[DD * EE];

// ---------------- common asm helpers ----------------
__device__ __forceinline__ void cp16(uint32_t s, const void* g) {
    asm volatile("cp.async.ca.shared.global [%0], [%1], 16;" :: "r"(s), "l"(g));
}
__device__ __forceinline__ void ldsm4(uint32_t& r0, uint32_t& r1, uint32_t& r2,
                                      uint32_t& r3, uint32_t a) {
    asm volatile("ldmatrix.sync.aligned.m8n8.x4.shared.b16 {%0,%1,%2,%3}, [%4];"
                 : "=r"(r0), "=r"(r1), "=r"(r2), "=r"(r3) : "r"(a));
}
__device__ __forceinline__ void ldsm4t(uint32_t& r0, uint32_t& r1, uint32_t& r2,
                                       uint32_t& r3, uint32_t a) {
    asm volatile("ldmatrix.sync.aligned.m8n8.x4.trans.shared.b16 {%0,%1,%2,%3}, [%4];"
                 : "=r"(r0), "=r"(r1), "=r"(r2), "=r"(r3) : "r"(a));
}
__device__ __forceinline__ void mma16816(float* d, const uint32_t* a, const uint32_t* b) {
    asm volatile("mma.sync.aligned.m16n8k16.row.col.f32.bf16.bf16.f32 "
                 "{%0,%1,%2,%3}, {%4,%5,%6,%7}, {%8,%9}, {%0,%1,%2,%3};"
                 : "+f"(d[0]), "+f"(d[1]), "+f"(d[2]), "+f"(d[3])
                 : "r"(a[0]), "r"(a[1]), "r"(a[2]), "r"(a[3]),
                   "r"(b[0]), "r"(b[1]));
}

// Fast activations (kept from R15)
__device__ __forceinline__ float actsel(float v, int act) {
    if (act == 1) {
        float s = __fdividef(1.0f, 1.0f + __expf(-v));   // silu
        return v * s;
    }
    if (act == 2) return __fdividef(1.0f, 1.0f + __expf(-v));  // sigmoid
    return v;
}

// ---------------- pipelined bf16 GEMM (unchanged from R15) ----------------
#define GBM 128
#define GBN 128
#define GBK 32
#define APAD 40
#define BPAD 136
#define AELEM (GBM * APAD)
#define BELEM (GBK * BPAD)
#define STG_ELEMS1 (2 * (AELEM + BELEM))
#define STG_ELEMS0 (AELEM + BELEM)
#define SMEM_SPLIT1 (3 * STG_ELEMS1 * 2)
#define SMEM_SPLIT0 (3 * STG_ELEMS0 * 2)

extern __shared__ __align__(16) char dynsm[];

template <int SPLIT, int OBF>
__device__ __forceinline__ void gemm_pipe_body(
    const bf16* __restrict__ Ahg, const bf16* __restrict__ Alg,
    const bf16* __restrict__ Bhg, const bf16* __restrict__ Blg,
    float* __restrict__ C, bf16* __restrict__ Cb,
    int N, int K, int row0, int col0, int act)
{
    bf16* sm = (bf16*)dynsm;
    const int STG = SPLIT ? STG_ELEMS1 : STG_ELEMS0;

    const int tid = threadIdx.x;
    const int warp = tid >> 5, lane = tid & 31;
    const int wm = warp >> 2, wn = warp & 3;

    auto issue = [&](int itk, int buf) {
        const int k0 = itk * GBK;
        bf16* s   = sm + buf * STG;
        bf16* sAh = s;
        bf16* sAl = s + AELEM;
        bf16* sBh = s + (SPLIT ? 2 : 1) * AELEM;
        bf16* sBl = sBh + BELEM;
#pragma unroll
        for (int j = 0; j < 2; j++) {
            const int c = tid + j * 256;
            const int row = c >> 2, cc = (c & 3) << 3;
            const size_t g = (size_t)(row0 + row) * K + k0 + cc;
            cp16((uint32_t)__cvta_generic_to_shared(&sAh[row * APAD + cc]), Ahg + g);
            if (SPLIT)
                cp16((uint32_t)__cvta_generic_to_shared(&sAl[row * APAD + cc]), Alg + g);
        }
#pragma unroll
        for (int j = 0; j < 2; j++) {
            const int c = tid + j * 256;
            const int br = c >> 4, bc = (c & 15) << 3;
            const size_t g = (size_t)(k0 + br) * N + col0 + bc;
            cp16((uint32_t)__cvta_generic_to_shared(&sBh[br * BPAD + bc]), Bhg + g);
            if (SPLIT)
                cp16((uint32_t)__cvta_generic_to_shared(&sBl[br * BPAD + bc]), Blg + g);
        }
        asm volatile("cp.async.commit_group;" ::: "memory");
    };

    const int KIT = K / GBK;
    issue(0, 0);
    if (KIT > 1) issue(1, 1);

    float acc[4][4][4];
#pragma unroll
    for (int i = 0; i < 4; i++)
#pragma unroll
        for (int j = 0; j < 4; j++)
#pragma unroll
            for (int c = 0; c < 4; c++) acc[i][j][c] = 0.0f;

    const int laneRow = (lane & 7) + ((lane >> 3) & 1) * 8;
    const int laneCol = (lane >> 4) * 8;
    const uint32_t smBase = (uint32_t)__cvta_generic_to_shared(sm);

    for (int itk = 0; itk < KIT; ++itk) {
        const int buf = itk % 3;
        if (itk + 1 < KIT)
            asm volatile("cp.async.wait_group 1;" ::: "memory");
        else
            asm volatile("cp.async.wait_group 0;" ::: "memory");
        __syncthreads();
        if (itk + 2 < KIT) issue(itk + 2, (itk + 2) % 3);

        const uint32_t aH = smBase + buf * STG * 2;
        const uint32_t aL = aH + AELEM * 2;
        const uint32_t bH = aH + (SPLIT ? 2 : 1) * AELEM * 2;
        const uint32_t bL = bH + BELEM * 2;

#pragma unroll
        for (int ks = 0; ks < 2; ks++) {
            uint32_t ah[4][4];
#pragma unroll
            for (int mi = 0; mi < 4; mi++) {
                uint32_t off = (uint32_t)(((wm * 64 + mi * 16 + laneRow) * APAD
                                           + ks * 16 + laneCol) * 2);
                ldsm4(ah[mi][0], ah[mi][1], ah[mi][2], ah[mi][3], aH + off);
            }
            uint32_t bh[2][4];
#pragma unroll
            for (int p = 0; p < 2; p++) {
                uint32_t off = (uint32_t)(((ks * 16 + laneRow) * BPAD
                                           + wn * 32 + p * 16 + laneCol) * 2);
                ldsm4t(bh[p][0], bh[p][1], bh[p][2], bh[p][3], bH + off);
            }
#pragma unroll
            for (int mi = 0; mi < 4; mi++)
#pragma unroll
                for (int ni = 0; ni < 4; ni++)
                    mma16816(acc[mi][ni], ah[mi], &bh[ni >> 1][(ni & 1) * 2]);

            if (SPLIT) {
                {
                    uint32_t bl[2][4];
#pragma unroll
                    for (int p = 0; p < 2; p++) {
                        uint32_t off = (uint32_t)(((ks * 16 + laneRow) * BPAD
                                                   + wn * 32 + p * 16 + laneCol) * 2);
                        ldsm4t(bl[p][0], bl[p][1], bl[p][2], bl[p][3], bL + off);
                    }
#pragma unroll
                    for (int mi = 0; mi < 4; mi++)
#pragma unroll
                        for (int ni = 0; ni < 4; ni++)
                            mma16816(acc[mi][ni], ah[mi], &bl[ni >> 1][(ni & 1) * 2]);
                }
                {
                    uint32_t al[4][4];
#pragma unroll
                    for (int mi = 0; mi < 4; mi++) {
                        uint32_t off = (uint32_t)(((wm * 64 + mi * 16 + laneRow) * APAD
                                                   + ks * 16 + laneCol) * 2);
                        ldsm4(al[mi][0], al[mi][1], al[mi][2], al[mi][3], aL + off);
                    }
#pragma unroll
                    for (int mi = 0; mi < 4; mi++)
#pragma unroll
                        for (int ni = 0; ni < 4; ni++)
                            mma16816(acc[mi][ni], al[mi], &bh[ni >> 1][(ni & 1) * 2]);
                }
            }
        }
    }

#pragma unroll
    for (int mi = 0; mi < 4; mi++) {
#pragma unroll
        for (int ni = 0; ni < 4; ni++) {
            const int r = row0 + wm * 64 + mi * 16 + (lane >> 2);
            const int c = col0 + wn * 32 + ni * 8 + (lane & 3) * 2;
            float2 v0 = make_float2(actsel(acc[mi][ni][0], act),
                                    actsel(acc[mi][ni][1], act));
            float2 v1 = make_float2(actsel(acc[mi][ni][2], act),
                                    actsel(acc[mi][ni][3], act));
            if (OBF) {
                *(__nv_bfloat162*)&Cb[(size_t)r * N + c] =
                    __floats2bfloat162_rn(v0.x, v0.y);
                *(__nv_bfloat162*)&Cb[(size_t)(r + 8) * N + c] =
                    __floats2bfloat162_rn(v1.x, v1.y);
            } else {
                *(float2*)&C[(size_t)r * N + c]       = v0;
                *(float2*)&C[(size_t)(r + 8) * N + c] = v1;
            }
        }
    }
}

template <int SPLIT, int OBF, int ACT>
__global__ void __launch_bounds__(256, 2)
gemm_std(const bf16* __restrict__ Ah, const bf16* __restrict__ Al,
         const bf16* __restrict__ Bh, const bf16* __restrict__ Bl,
         float* __restrict__ C, bf16* __restrict__ Cb, int N, int K) {
    gemm_pipe_body<SPLIT, OBF>(Ah, Al, Bh, Bl, C, Cb, N, K,
                               blockIdx.y * GBM, blockIdx.x * GBN, ACT);
}

__global__ void __launch_bounds__(256, 2)
gemm_qkvg(float* __restrict__ q, float* __restrict__ k, float* __restrict__ v) {
    const int bx = blockIdx.x;
    const int row0 = blockIdx.y * GBM;
    if (bx < 24) {
        const int wsel = bx >> 3;
        const bf16* Bh = (wsel == 0) ? g_wqh : (wsel == 1) ? g_wkh : g_wvh;
        const bf16* Bl = (wsel == 0) ? g_wql : (wsel == 1) ? g_wkl : g_wvl;
        float*      C  = (wsel == 0) ? q : (wsel == 1) ? k : v;
        const int act  = (wsel == 0) ? 1 : (wsel == 1) ? 2 : 0;
        gemm_pipe_body<1, 0>(g_xh, g_xl, Bh, Bl, C, nullptr,
                             EE, EE, row0, (bx & 7) * GBN, act);
    } else {
        gemm_pipe_body<0, 1>(g_xh, nullptr, g_wg1b, nullptr, nullptr, g_g1b,
                             DD, EE, row0, 0, 0);
    }
}

// ---------------- split kernels (unchanged) ----------------
__device__ __forceinline__ void split1g(bf16* hi, bf16* lo, int i, float x) {
    bf16 h = __float2bfloat16(x);
    hi[i] = h;
    lo[i] = __float2bfloat16(x - __bfloat162float(h));
}

__global__ void __launch_bounds__(256)
split_weights(const float* __restrict__ wq, const float* __restrict__ wk,
              const float* __restrict__ wv, const float* __restrict__ wo,
              const float* __restrict__ wg1, const float* __restrict__ wg2) {
    const int i = blockIdx.x * 256 + threadIdx.x;
    split1g(g_wqh, g_wql, i, wq[i]);
    split1g(g_wkh, g_wkl, i, wk[i]);
    split1g(g_wvh, g_wvl, i, wv[i]);
    split1g(g_woh, g_wol, i, wo[i]);
    if (i < EE * DD) {
        g_wg1b[i] = __float2bfloat16(wg1[i]);
        g_wg2b[i] = __float2bfloat16(wg2[i]);
    }
}

__global__ void __launch_bounds__(256)
split_x_kernel(const float* __restrict__ x) {
    const int i = (blockIdx.x * 256 + threadIdx.x) * 4;
    float4 v = *(const float4*)&x[i];
    bf16 h0 = __float2bfloat16(v.x), h1 = __float2bfloat16(v.y);
    bf16 h2 = __float2bfloat16(v.z), h3 = __float2bfloat16(v.w);
    *(__nv_bfloat162*)&g_xh[i]     = __nv_bfloat162(h0, h1);
    *(__nv_bfloat162*)&g_xh[i + 2] = __nv_bfloat162(h2, h3);
    *(__nv_bfloat162*)&g_xl[i] = __floats2bfloat162_rn(
        v.x - __bfloat162float(h0), v.y - __bfloat162float(h1));
    *(__nv_bfloat162*)&g_xl[i + 2] = __floats2bfloat162_rn(
        v.z - __bfloat162float(h2), v.w - __bfloat162float(h3));
}

// ---------------- GLA scan v6: 4 warps x 4 dv, transpose-reduce ----------------
// grid (8 dvb, H, B), 128 threads (4 warps). Warp w owns dv [dvb*16+w*4, +4).
// Lane owns dk rows {4*lane..4*lane+3}. Sign-folded recurrence (v5 math).
// Reduction: per 8-step half, smem transpose (32x33 pad) instead of shfl trees.
#define SSTEP 16
#define NBUF 3
#define NITER (TT / SSTEP)   // 128
#define RED_ELEMS (4 * 32 * 33)
#define SCAN_SMEM_BYTES ((NBUF * SSTEP * 128 * 2 + NBUF * SSTEP * 16 + RED_ELEMS) * 4)

__global__ void __launch_bounds__(128, 2)
scan_kernel(const float* __restrict__ q, const float* __restrict__ k,
            const float* __restrict__ v, float* __restrict__ att) {
    float* smem = (float*)dynsm;
    float* sQ = smem;
    float* sK = sQ + NBUF * SSTEP * 128;
    float* sV = sK + NBUF * SSTEP * 128;
    float* sR = sV + NBUF * SSTEP * 16;

    const int tid  = threadIdx.x;
    const int lane = tid & 31;
    const int warp = tid >> 5;      // 0..3
    const int dvb  = blockIdx.x;
    const int h    = blockIdx.y;
    const int b    = blockIdx.z;

    const size_t rowbase = (size_t)b * TT * EE + (size_t)h * DD;
    const float* qb = q + rowbase;
    const float* kb = k + rowbase;
    const float* vb = v + rowbase + dvb * 16;
    float*       ob = att + rowbase + dvb * 16 + warp * 4;

    // staging: q/k 512 float4 per stage -> 4/thread; v 64 float4 -> tid<64.
    auto issue_stage = [&](int t0, int buf) {
        float* bQ = sQ + buf * SSTEP * 128;
        float* bK = sK + buf * SSTEP * 128;
        float* bV = sV + buf * SSTEP * 16;
#pragma unroll
        for (int j = 0; j < 4; j++) {
            const int c = tid + j * 128;           // 0..511
            const int row = c >> 5, col = (c & 31) * 4;
            cp16((uint32_t)__cvta_generic_to_shared(&bQ[row * 128 + col]),
                 qb + (size_t)(t0 + row) * EE + col);
            cp16((uint32_t)__cvta_generic_to_shared(&bK[row * 128 + col]),
                 kb + (size_t)(t0 + row) * EE + col);
        }
        if (tid < 64)
            cp16((uint32_t)__cvta_generic_to_shared(&bV[(tid >> 2) * 16 + (tid & 3) * 4]),
                 vb + (size_t)(t0 + (tid >> 2)) * EE + (tid & 3) * 4);
        asm volatile("cp.async.commit_group;" ::: "memory");
    };

    issue_stage(0, 0);
    issue_stage(SSTEP, 1);

    // state: s[dk 0..3][dv 0..3]
    float s00 = 0.f, s01 = 0.f, s02 = 0.f, s03 = 0.f;
    float s10 = 0.f, s11 = 0.f, s12 = 0.f, s13 = 0.f;
    float s20 = 0.f, s21 = 0.f, s22 = 0.f, s23 = 0.f;
    float s30 = 0.f, s31 = 0.f, s32 = 0.f, s33 = 0.f;

    float* wr = sR + warp * (32 * 33);

    for (int iter = 0; iter < NITER; ++iter) {
        const int buf = iter % NBUF;
        const int t0  = iter * SSTEP;
        const float* bQ = sQ + buf * SSTEP * 128;
        const float* bK = sK + buf * SSTEP * 128;
        const float* bV = sV + buf * SSTEP * 16;

        if (iter < NITER - 1)
            asm volatile("cp.async.wait_group 1;" ::: "memory");
        else
            asm volatile("cp.async.wait_group 0;" ::: "memory");
        __syncthreads();

        if (iter + 2 < NITER)
            issue_stage((iter + 2) * SSTEP, (iter + 2) % NBUF);

#pragma unroll
        for (int half = 0; half < 2; half++) {
            float p[32];
#pragma unroll
            for (int uu = 0; uu < 8; uu++) {
                const int u = half * 8 + uu;
                const float4 qc = *(const float4*)&bQ[u * 128 + lane * 4];
                const float4 kc = *(const float4*)&bK[u * 128 + lane * 4];
                const float4 vv = *(const float4*)&bV[u * 16 + warp * 4]; // broadcast

                const float f0 = kc.x - 1.0f, f1 = kc.y - 1.0f;
                const float f2 = kc.z - 1.0f, f3 = kc.w - 1.0f;

                s00 = fmaf(f0, s00, kc.x * vv.x);  s01 = fmaf(f0, s01, kc.x * vv.y);
                s02 = fmaf(f0, s02, kc.x * vv.z);  s03 = fmaf(f0, s03, kc.x * vv.w);
                s10 = fmaf(f1, s10, kc.y * vv.x);  s11 = fmaf(f1, s11, kc.y * vv.y);
                s12 = fmaf(f1, s12, kc.y * vv.z);  s13 = fmaf(f1, s13, kc.y * vv.w);
                s20 = fmaf(f2, s20, kc.z * vv.x);  s21 = fmaf(f2, s21, kc.z * vv.y);
                s22 = fmaf(f2, s22, kc.z * vv.z);  s23 = fmaf(f2, s23, kc.z * vv.w);
                s30 = fmaf(f3, s30, kc.w * vv.x);  s31 = fmaf(f3, s31, kc.w * vv.y);
                s32 = fmaf(f3, s32, kc.w * vv.z);  s33 = fmaf(f3, s33, kc.w * vv.w);

                float o0 = qc.x * s00; o0 = fmaf(qc.y, s10, o0);
                o0 = fmaf(qc.z, s20, o0); o0 = fmaf(qc.w, s30, o0);
                float o1 = qc.x * s01; o1 = fmaf(qc.y, s11, o1);
                o1 = fmaf(qc.z, s21, o1); o1 = fmaf(qc.w, s31, o1);
                float o2 = qc.x * s02; o2 = fmaf(qc.y, s12, o2);
                o2 = fmaf(qc.z, s22, o2); o2 = fmaf(qc.w, s32, o2);
                float o3 = qc.x * s03; o3 = fmaf(qc.y, s13, o3);
                o3 = fmaf(qc.z, s23, o3); o3 = fmaf(qc.w, s33, o3);

                p[uu * 4 + 0] = o0;  p[uu * 4 + 1] = o1;
                p[uu * 4 + 2] = o2;  p[uu * 4 + 3] = o3;
            }

            // transpose-reduce over the 32 lanes (per-warp buffer, pad 33)
            __syncwarp();
#pragma unroll
            for (int vI = 0; vI < 32; vI++)
                wr[lane * 33 + vI] = p[vI];
            __syncwarp();
            float a0 = 0.f, a1 = 0.f, a2 = 0.f, a3 = 0.f;
#pragma unroll
            for (int i = 0; i < 32; i += 4) {
                a0 += wr[(i + 0) * 33 + lane];
                a1 += wr[(i + 1) * 33 + lane];
                a2 += wr[(i + 2) * 33 + lane];
                a3 += wr[(i + 3) * 33 + lane];
            }
            const float tot = (a0 + a1) + (a2 + a3);

            // lane L owns output (uu = L>>2, j = L&3) of this half
            const int uo = lane >> 2, jo = lane & 3;
            ob[(size_t)(t0 + half * 8 + uo) * EE + jo] = tot * 0.0625f;
        }
    }
}

// ---------------- gate multiply + layernorm -> bf16 hi/lo (unchanged) --------
__global__ void __launch_bounds__(256)
gate_ln_kernel(const float* __restrict__ att, const float* __restrict__ gate,
               const float* __restrict__ nw) {
    const int row = blockIdx.x;
    const int tid = threadIdx.x;
    const int lane = tid & 31, wid = tid >> 5;
    __shared__ float red[8];

    float4 a = ((const float4*)(att + (size_t)row * EE))[tid];
    float4 g = ((const float4*)(gate + (size_t)row * EE))[tid];
    float4 yv;
    yv.x = a.x * g.x; yv.y = a.y * g.y; yv.z = a.z * g.z; yv.w = a.w * g.w;

    float ssum = yv.x + yv.y + yv.z + yv.w;
#pragma unroll
    for (int m = 16; m; m >>= 1) ssum += __shfl_xor_sync(0xffffffffu, ssum, m);
    if (lane == 0) red[wid] = ssum;
    __syncthreads();
    float tot = 0.0f;
#pragma unroll
    for (int w = 0; w < 8; w++) tot += red[w];
    const float mean = tot * (1.0f / (float)EE);
    __syncthreads();

    float dx = yv.x - mean, dy = yv.y - mean, dz = yv.z - mean, dw = yv.w - mean;
    float ssq = dx * dx + dy * dy + dz * dz + dw * dw;
#pragma unroll
    for (int m = 16; m; m >>= 1) ssq += __shfl_xor_sync(0xffffffffu, ssq, m);
    if (lane == 0) red[wid] = ssq;
    __syncthreads();
    float totsq = 0.0f;
#pragma unroll
    for (int w = 0; w < 8; w++) totsq += red[w];
    const float rstd = rsqrtf(totsq * (1.0f / (float)EE) + 1e-5f);

    float4 w4 = ((const float4*)nw)[tid];
    float o0 = dx * rstd * w4.x;
    float o1 = dy * rstd * w4.y;
    float o2 = dz * rstd * w4.z;
    float o3 = dw * rstd * w4.w;

    const size_t base = (size_t)row * EE + tid * 4;
    bf16 h0 = __float2bfloat16(o0), h1 = __float2bfloat16(o1);
    bf16 h2 = __float2bfloat16(o2), h3 = __float2bfloat16(o3);
    *(__nv_bfloat162*)&g_yh[base]     = __nv_bfloat162(h0, h1);
    *(__nv_bfloat162*)&g_yh[base + 2] = __nv_bfloat162(h2, h3);
    *(__nv_bfloat162*)&g_yl[base] = __floats2bfloat162_rn(
        o0 - __bfloat162float(h0), o1 - __bfloat162float(h1));
    *(__nv_bfloat162*)&g_yl[base + 2] = __floats2bfloat162_rn(
        o2 - __bfloat162float(h2), o3 - __bfloat162float(h3));
}

// ---------------- launch ----------------
extern "C" void kernel_launch(void* const* d_in, const int* in_sizes, int n_in,
                              void* d_out, int out_size) {
    const float* x   = (const float*)d_in[0];
    const float* wq  = (const float*)d_in[1];
    const float* wk  = (const float*)d_in[2];
    const float* wv  = (const float*)d_in[3];
    const float* wo  = (const float*)d_in[4];
    const float* wg1 = (const float*)d_in[5];
    const float* wg2 = (const float*)d_in[6];
    const float* nw  = (const float*)d_in[7];
    float* out = (float*)d_out;

    void *pq, *pk, *pv, *patt, *pgate;
    cudaGetSymbolAddress(&pq, g_q);
    cudaGetSymbolAddress(&pk, g_k);
    cudaGetSymbolAddress(&pv, g_v);
    cudaGetSymbolAddress(&patt, g_att);
    cudaGetSymbolAddress(&pgate, g_gate);
    float* fq = (float*)pq;     float* fk = (float*)pk;   float* fv = (float*)pv;
    float* fatt = (float*)patt; float* fgate = (float*)pgate;

    void *pyh, *pyl, *pg1b, *pwoh, *pwol, *pwg2b;
    cudaGetSymbolAddress(&pyh, g_yh);
    cudaGetSymbolAddress(&pyl, g_yl);
    cudaGetSymbolAddress(&pg1b, g_g1b);
    cudaGetSymbolAddress(&pwoh, g_woh);
    cudaGetSymbolAddress(&pwol, g_wol);
    cudaGetSymbolAddress(&pwg2b, g_wg2b);

    cudaFuncSetAttribute(scan_kernel,
                         cudaFuncAttributeMaxDynamicSharedMemorySize,
                         SCAN_SMEM_BYTES);
    cudaFuncSetAttribute(gemm_qkvg,
                         cudaFuncAttributeMaxDynamicSharedMemorySize,
                         SMEM_SPLIT1);
    cudaFuncSetAttribute((const void*)gemm_std<0, 0, 2>,
                         cudaFuncAttributeMaxDynamicSharedMemorySize,
                         SMEM_SPLIT0);
    cudaFuncSetAttribute((const void*)gemm_std<1, 0, 0>,
                         cudaFuncAttributeMaxDynamicSharedMemorySize,
                         SMEM_SPLIT1);

    // 1. pre-split weights and x into bf16 hi/lo
    split_weights<<<EE * EE / 256, 256>>>(wq, wk, wv, wo, wg1, wg2);
    split_x_kernel<<<MM * EE / 1024, 256>>>(x);

    // 2. fused q/k/v + g1 projections (grid 25x64)
    gemm_qkvg<<<dim3(25, MM / GBM), 256, SMEM_SPLIT1>>>(fq, fk, fv);

    // 3. GLA scan v6 (128 threads)
    scan_kernel<<<dim3(8, HH, BB), 128, SCAN_SMEM_BYTES>>>(fq, fk, fv, fatt);

    // 4. gate = sigmoid(g1 @ wg2)  (plain bf16)
    gemm_std<0, 0, 2><<<dim3(EE / GBN, MM / GBM), 256, SMEM_SPLIT0>>>(
        (const bf16*)pg1b, nullptr, (const bf16*)pwg2b, nullptr,
        fgate, nullptr, EE, DD);

    // 5. gate * att + layernorm -> yh/yl
    gate_ln_kernel<<<MM, 256>>>(fatt, fgate, nw);

    // 6. out = y @ wo  (split bf16)
    gemm_std<1, 0, 0><<<dim3(EE / GBN, MM / GBM), 256, SMEM_SPLIT1>>>(
        (const bf16*)pyh, (const bf16*)pyl, (const bf16*)pwoh, (const bf16*)pwol,
        out, nullptr, EE, EE);
}

// round 17
// speedup vs baseline: 3.7406x; 1.0297x over previous
#include <cuda_runtime.h>
#include <cuda_bf16.h>
#include <cstdint>

// Problem constants
#define BB 4
#define TT 2048
#define EE 1024
#define DD 128
#define HH 8
#define MM (BB * TT)   // 8192 rows

typedef __nv_bfloat16 bf16;

// ---------------- scratch (static device memory; no allocation) ----------------
__device__ float g_q[MM * EE];
__device__ float g_k[MM * EE];
__device__ float g_v[MM * EE];
__device__ float g_att[MM * EE];
__device__ float g_gate[MM * EE];

__device__ __align__(16) bf16 g_xh[MM * EE];
__device__ __align__(16) bf16 g_xl[MM * EE];
__device__ __align__(16) bf16 g_yh[MM * EE];
__device__ __align__(16) bf16 g_yl[MM * EE];
__device__ __align__(16) bf16 g_g1b[MM * DD];

__device__ __align__(16) bf16 g_wqh[EE * EE];
__device__ __align__(16) bf16 g_wql[EE * EE];
__device__ __align__(16) bf16 g_wkh[EE * EE];
__device__ __align__(16) bf16 g_wkl[EE * EE];
__device__ __align__(16) bf16 g_wvh[EE * EE];
__device__ __align__(16) bf16 g_wvl[EE * EE];
__device__ __align__(16) bf16 g_woh[EE * EE];
__device__ __align__(16) bf16 g_wol[EE * EE];
__device__ __align__(16) bf16 g_wg1b[EE * DD];
__device__ __align__(16) bf16 g_wg2b[DD * EE];

// ---------------- common asm helpers ----------------
__device__ __forceinline__ void cp16(uint32_t s, const void* g) {
    asm volatile("cp.async.ca.shared.global [%0], [%1], 16;" :: "r"(s), "l"(g));
}
__device__ __forceinline__ void ldsm4(uint32_t& r0, uint32_t& r1, uint32_t& r2,
                                      uint32_t& r3, uint32_t a) {
    asm volatile("ldmatrix.sync.aligned.m8n8.x4.shared.b16 {%0,%1,%2,%3}, [%4];"
                 : "=r"(r0), "=r"(r1), "=r"(r2), "=r"(r3) : "r"(a));
}
__device__ __forceinline__ void ldsm4t(uint32_t& r0, uint32_t& r1, uint32_t& r2,
                                       uint32_t& r3, uint32_t a) {
    asm volatile("ldmatrix.sync.aligned.m8n8.x4.trans.shared.b16 {%0,%1,%2,%3}, [%4];"
                 : "=r"(r0), "=r"(r1), "=r"(r2), "=r"(r3) : "r"(a));
}
__device__ __forceinline__ void mma16816(float* d, const uint32_t* a, const uint32_t* b) {
    asm volatile("mma.sync.aligned.m16n8k16.row.col.f32.bf16.bf16.f32 "
                 "{%0,%1,%2,%3}, {%4,%5,%6,%7}, {%8,%9}, {%0,%1,%2,%3};"
                 : "+f"(d[0]), "+f"(d[1]), "+f"(d[2]), "+f"(d[3])
                 : "r"(a[0]), "r"(a[1]), "r"(a[2]), "r"(a[3]),
                   "r"(b[0]), "r"(b[1]));
}

// Fast activations (kept from R15)
__device__ __forceinline__ float actsel(float v, int act) {
    if (act == 1) {
        float s = __fdividef(1.0f, 1.0f + __expf(-v));   // silu
        return v * s;
    }
    if (act == 2) return __fdividef(1.0f, 1.0f + __expf(-v));  // sigmoid
    return v;
}

// ---------------- pipelined bf16 GEMM (unchanged from R16) ----------------
#define GBM 128
#define GBN 128
#define GBK 32
#define APAD 40
#define BPAD 136
#define AELEM (GBM * APAD)
#define BELEM (GBK * BPAD)
#define STG_ELEMS1 (2 * (AELEM + BELEM))
#define STG_ELEMS0 (AELEM + BELEM)
#define SMEM_SPLIT1 (3 * STG_ELEMS1 * 2)
#define SMEM_SPLIT0 (3 * STG_ELEMS0 * 2)

extern __shared__ __align__(16) char dynsm[];

template <int SPLIT, int OBF>
__device__ __forceinline__ void gemm_pipe_body(
    const bf16* __restrict__ Ahg, const bf16* __restrict__ Alg,
    const bf16* __restrict__ Bhg, const bf16* __restrict__ Blg,
    float* __restrict__ C, bf16* __restrict__ Cb,
    int N, int K, int row0, int col0, int act)
{
    bf16* sm = (bf16*)dynsm;
    const int STG = SPLIT ? STG_ELEMS1 : STG_ELEMS0;

    const int tid = threadIdx.x;
    const int warp = tid >> 5, lane = tid & 31;
    const int wm = warp >> 2, wn = warp & 3;

    auto issue = [&](int itk, int buf) {
        const int k0 = itk * GBK;
        bf16* s   = sm + buf * STG;
        bf16* sAh = s;
        bf16* sAl = s + AELEM;
        bf16* sBh = s + (SPLIT ? 2 : 1) * AELEM;
        bf16* sBl = sBh + BELEM;
#pragma unroll
        for (int j = 0; j < 2; j++) {
            const int c = tid + j * 256;
            const int row = c >> 2, cc = (c & 3) << 3;
            const size_t g = (size_t)(row0 + row) * K + k0 + cc;
            cp16((uint32_t)__cvta_generic_to_shared(&sAh[row * APAD + cc]), Ahg + g);
            if (SPLIT)
                cp16((uint32_t)__cvta_generic_to_shared(&sAl[row * APAD + cc]), Alg + g);
        }
#pragma unroll
        for (int j = 0; j < 2; j++) {
            const int c = tid + j * 256;
            const int br = c >> 4, bc = (c & 15) << 3;
            const size_t g = (size_t)(k0 + br) * N + col0 + bc;
            cp16((uint32_t)__cvta_generic_to_shared(&sBh[br * BPAD + bc]), Bhg + g);
            if (SPLIT)
                cp16((uint32_t)__cvta_generic_to_shared(&sBl[br * BPAD + bc]), Blg + g);
        }
        asm volatile("cp.async.commit_group;" ::: "memory");
    };

    const int KIT = K / GBK;
    issue(0, 0);
    if (KIT > 1) issue(1, 1);

    float acc[4][4][4];
#pragma unroll
    for (int i = 0; i < 4; i++)
#pragma unroll
        for (int j = 0; j < 4; j++)
#pragma unroll
            for (int c = 0; c < 4; c++) acc[i][j][c] = 0.0f;

    const int laneRow = (lane & 7) + ((lane >> 3) & 1) * 8;
    const int laneCol = (lane >> 4) * 8;
    const uint32_t smBase = (uint32_t)__cvta_generic_to_shared(sm);

    for (int itk = 0; itk < KIT; ++itk) {
        const int buf = itk % 3;
        if (itk + 1 < KIT)
            asm volatile("cp.async.wait_group 1;" ::: "memory");
        else
            asm volatile("cp.async.wait_group 0;" ::: "memory");
        __syncthreads();
        if (itk + 2 < KIT) issue(itk + 2, (itk + 2) % 3);

        const uint32_t aH = smBase + buf * STG * 2;
        const uint32_t aL = aH + AELEM * 2;
        const uint32_t bH = aH + (SPLIT ? 2 : 1) * AELEM * 2;
        const uint32_t bL = bH + BELEM * 2;

#pragma unroll
        for (int ks = 0; ks < 2; ks++) {
            uint32_t ah[4][4];
#pragma unroll
            for (int mi = 0; mi < 4; mi++) {
                uint32_t off = (uint32_t)(((wm * 64 + mi * 16 + laneRow) * APAD
                                           + ks * 16 + laneCol) * 2);
                ldsm4(ah[mi][0], ah[mi][1], ah[mi][2], ah[mi][3], aH + off);
            }
            uint32_t bh[2][4];
#pragma unroll
            for (int p = 0; p < 2; p++) {
                uint32_t off = (uint32_t)(((ks * 16 + laneRow) * BPAD
                                           + wn * 32 + p * 16 + laneCol) * 2);
                ldsm4t(bh[p][0], bh[p][1], bh[p][2], bh[p][3], bH + off);
            }
#pragma unroll
            for (int mi = 0; mi < 4; mi++)
#pragma unroll
                for (int ni = 0; ni < 4; ni++)
                    mma16816(acc[mi][ni], ah[mi], &bh[ni >> 1][(ni & 1) * 2]);

            if (SPLIT) {
                {
                    uint32_t bl[2][4];
#pragma unroll
                    for (int p = 0; p < 2; p++) {
                        uint32_t off = (uint32_t)(((ks * 16 + laneRow) * BPAD
                                                   + wn * 32 + p * 16 + laneCol) * 2);
                        ldsm4t(bl[p][0], bl[p][1], bl[p][2], bl[p][3], bL + off);
                    }
#pragma unroll
                    for (int mi = 0; mi < 4; mi++)
#pragma unroll
                        for (int ni = 0; ni < 4; ni++)
                            mma16816(acc[mi][ni], ah[mi], &bl[ni >> 1][(ni & 1) * 2]);
                }
                {
                    uint32_t al[4][4];
#pragma unroll
                    for (int mi = 0; mi < 4; mi++) {
                        uint32_t off = (uint32_t)(((wm * 64 + mi * 16 + laneRow) * APAD
                                                   + ks * 16 + laneCol) * 2);
                        ldsm4(al[mi][0], al[mi][1], al[mi][2], al[mi][3], aL + off);
                    }
#pragma unroll
                    for (int mi = 0; mi < 4; mi++)
#pragma unroll
                        for (int ni = 0; ni < 4; ni++)
                            mma16816(acc[mi][ni], al[mi], &bh[ni >> 1][(ni & 1) * 2]);
                }
            }
        }
    }

#pragma unroll
    for (int mi = 0; mi < 4; mi++) {
#pragma unroll
        for (int ni = 0; ni < 4; ni++) {
            const int r = row0 + wm * 64 + mi * 16 + (lane >> 2);
            const int c = col0 + wn * 32 + ni * 8 + (lane & 3) * 2;
            float2 v0 = make_float2(actsel(acc[mi][ni][0], act),
                                    actsel(acc[mi][ni][1], act));
            float2 v1 = make_float2(actsel(acc[mi][ni][2], act),
                                    actsel(acc[mi][ni][3], act));
            if (OBF) {
                *(__nv_bfloat162*)&Cb[(size_t)r * N + c] =
                    __floats2bfloat162_rn(v0.x, v0.y);
                *(__nv_bfloat162*)&Cb[(size_t)(r + 8) * N + c] =
                    __floats2bfloat162_rn(v1.x, v1.y);
            } else {
                *(float2*)&C[(size_t)r * N + c]       = v0;
                *(float2*)&C[(size_t)(r + 8) * N + c] = v1;
            }
        }
    }
}

template <int SPLIT, int OBF, int ACT>
__global__ void __launch_bounds__(256, 2)
gemm_std(const bf16* __restrict__ Ah, const bf16* __restrict__ Al,
         const bf16* __restrict__ Bh, const bf16* __restrict__ Bl,
         float* __restrict__ C, bf16* __restrict__ Cb, int N, int K) {
    gemm_pipe_body<SPLIT, OBF>(Ah, Al, Bh, Bl, C, Cb, N, K,
                               blockIdx.y * GBM, blockIdx.x * GBN, ACT);
}

__global__ void __launch_bounds__(256, 2)
gemm_qkvg(float* __restrict__ q, float* __restrict__ k, float* __restrict__ v) {
    const int bx = blockIdx.x;
    const int row0 = blockIdx.y * GBM;
    if (bx < 24) {
        const int wsel = bx >> 3;
        const bf16* Bh = (wsel == 0) ? g_wqh : (wsel == 1) ? g_wkh : g_wvh;
        const bf16* Bl = (wsel == 0) ? g_wql : (wsel == 1) ? g_wkl : g_wvl;
        float*      C  = (wsel == 0) ? q : (wsel == 1) ? k : v;
        const int act  = (wsel == 0) ? 1 : (wsel == 1) ? 2 : 0;
        gemm_pipe_body<1, 0>(g_xh, g_xl, Bh, Bl, C, nullptr,
                             EE, EE, row0, (bx & 7) * GBN, act);
    } else {
        gemm_pipe_body<0, 1>(g_xh, nullptr, g_wg1b, nullptr, nullptr, g_g1b,
                             DD, EE, row0, 0, 0);
    }
}

// ---------------- split kernels (unchanged) ----------------
__device__ __forceinline__ void split1g(bf16* hi, bf16* lo, int i, float x) {
    bf16 h = __float2bfloat16(x);
    hi[i] = h;
    lo[i] = __float2bfloat16(x - __bfloat162float(h));
}

__global__ void __launch_bounds__(256)
split_weights(const float* __restrict__ wq, const float* __restrict__ wk,
              const float* __restrict__ wv, const float* __restrict__ wo,
              const float* __restrict__ wg1, const float* __restrict__ wg2) {
    const int i = blockIdx.x * 256 + threadIdx.x;
    split1g(g_wqh, g_wql, i, wq[i]);
    split1g(g_wkh, g_wkl, i, wk[i]);
    split1g(g_wvh, g_wvl, i, wv[i]);
    split1g(g_woh, g_wol, i, wo[i]);
    if (i < EE * DD) {
        g_wg1b[i] = __float2bfloat16(wg1[i]);
        g_wg2b[i] = __float2bfloat16(wg2[i]);
    }
}

__global__ void __launch_bounds__(256)
split_x_kernel(const float* __restrict__ x) {
    const int i = (blockIdx.x * 256 + threadIdx.x) * 4;
    float4 v = *(const float4*)&x[i];
    bf16 h0 = __float2bfloat16(v.x), h1 = __float2bfloat16(v.y);
    bf16 h2 = __float2bfloat16(v.z), h3 = __float2bfloat16(v.w);
    *(__nv_bfloat162*)&g_xh[i]     = __nv_bfloat162(h0, h1);
    *(__nv_bfloat162*)&g_xh[i + 2] = __nv_bfloat162(h2, h3);
    *(__nv_bfloat162*)&g_xl[i] = __floats2bfloat162_rn(
        v.x - __bfloat162float(h0), v.y - __bfloat162float(h1));
    *(__nv_bfloat162*)&g_xl[i + 2] = __floats2bfloat162_rn(
        v.z - __bfloat162float(h2), v.w - __bfloat162float(h3));
}

// ---------------- GLA scan v7: one-wave grid (128 CTAs), 8 warps x 4 dv -------
// grid (4 dvb2, H, B) = 128 blocks, 256 threads (8 warps).
// CTA covers 32 dv columns [dvb2*32, +32); warp w owns dv [dvb2*32 + w*4, +4).
// Lane owns dk rows {4*lane..4*lane+3}. Sign-folded recurrence (v5 math).
// Per-warp transpose-reduce in smem (32x33 pad) — bit-identical to v6.
#define SSTEP 16
#define NBUF 3
#define NITER (TT / SSTEP)   // 128
#define DVW 32               // dv columns per CTA
#define RED_ELEMS (8 * 32 * 33)
#define SCAN_SMEM_BYTES ((NBUF * SSTEP * 128 * 2 + NBUF * SSTEP * DVW + RED_ELEMS) * 4)

__global__ void __launch_bounds__(256, 1)
scan_kernel(const float* __restrict__ q, const float* __restrict__ k,
            const float* __restrict__ v, float* __restrict__ att) {
    float* smem = (float*)dynsm;
    float* sQ = smem;
    float* sK = sQ + NBUF * SSTEP * 128;
    float* sV = sK + NBUF * SSTEP * 128;
    float* sR = sV + NBUF * SSTEP * DVW;

    const int tid  = threadIdx.x;
    const int lane = tid & 31;
    const int warp = tid >> 5;      // 0..7
    const int dvb  = blockIdx.x;    // 0..3
    const int h    = blockIdx.y;
    const int b    = blockIdx.z;

    const size_t rowbase = (size_t)b * TT * EE + (size_t)h * DD;
    const float* qb = q + rowbase;
    const float* kb = k + rowbase;
    const float* vb = v + rowbase + dvb * DVW;
    float*       ob = att + rowbase + dvb * DVW + warp * 4;

    // staging: q/k 512 float4 per stage -> 2/thread; v 128 float4 -> tid<128.
    auto issue_stage = [&](int t0, int buf) {
        float* bQ = sQ + buf * SSTEP * 128;
        float* bK = sK + buf * SSTEP * 128;
        float* bV = sV + buf * SSTEP * DVW;
#pragma unroll
        for (int j = 0; j < 2; j++) {
            const int c = tid + j * 256;           // 0..511
            const int row = c >> 5, col = (c & 31) * 4;
            cp16((uint32_t)__cvta_generic_to_shared(&bQ[row * 128 + col]),
                 qb + (size_t)(t0 + row) * EE + col);
            cp16((uint32_t)__cvta_generic_to_shared(&bK[row * 128 + col]),
                 kb + (size_t)(t0 + row) * EE + col);
        }
        if (tid < 128)
            cp16((uint32_t)__cvta_generic_to_shared(
                     &bV[(tid >> 3) * DVW + (tid & 7) * 4]),
                 vb + (size_t)(t0 + (tid >> 3)) * EE + (tid & 7) * 4);
        asm volatile("cp.async.commit_group;" ::: "memory");
    };

    issue_stage(0, 0);
    issue_stage(SSTEP, 1);

    // state: s[dk 0..3][dv 0..3]
    float s00 = 0.f, s01 = 0.f, s02 = 0.f, s03 = 0.f;
    float s10 = 0.f, s11 = 0.f, s12 = 0.f, s13 = 0.f;
    float s20 = 0.f, s21 = 0.f, s22 = 0.f, s23 = 0.f;
    float s30 = 0.f, s31 = 0.f, s32 = 0.f, s33 = 0.f;

    float* wr = sR + warp * (32 * 33);

    for (int iter = 0; iter < NITER; ++iter) {
        const int buf = iter % NBUF;
        const int t0  = iter * SSTEP;
        const float* bQ = sQ + buf * SSTEP * 128;
        const float* bK = sK + buf * SSTEP * 128;
        const float* bV = sV + buf * SSTEP * DVW;

        if (iter < NITER - 1)
            asm volatile("cp.async.wait_group 1;" ::: "memory");
        else
            asm volatile("cp.async.wait_group 0;" ::: "memory");
        __syncthreads();

        if (iter + 2 < NITER)
            issue_stage((iter + 2) * SSTEP, (iter + 2) % NBUF);

#pragma unroll
        for (int half = 0; half < 2; half++) {
            float p[32];
#pragma unroll
            for (int uu = 0; uu < 8; uu++) {
                const int u = half * 8 + uu;
                const float4 qc = *(const float4*)&bQ[u * 128 + lane * 4];
                const float4 kc = *(const float4*)&bK[u * 128 + lane * 4];
                const float4 vv = *(const float4*)&bV[u * DVW + warp * 4]; // bcast

                const float f0 = kc.x - 1.0f, f1 = kc.y - 1.0f;
                const float f2 = kc.z - 1.0f, f3 = kc.w - 1.0f;

                s00 = fmaf(f0, s00, kc.x * vv.x);  s01 = fmaf(f0, s01, kc.x * vv.y);
                s02 = fmaf(f0, s02, kc.x * vv.z);  s03 = fmaf(f0, s03, kc.x * vv.w);
                s10 = fmaf(f1, s10, kc.y * vv.x);  s11 = fmaf(f1, s11, kc.y * vv.y);
                s12 = fmaf(f1, s12, kc.y * vv.z);  s13 = fmaf(f1, s13, kc.y * vv.w);
                s20 = fmaf(f2, s20, kc.z * vv.x);  s21 = fmaf(f2, s21, kc.z * vv.y);
                s22 = fmaf(f2, s22, kc.z * vv.z);  s23 = fmaf(f2, s23, kc.z * vv.w);
                s30 = fmaf(f3, s30, kc.w * vv.x);  s31 = fmaf(f3, s31, kc.w * vv.y);
                s32 = fmaf(f3, s32, kc.w * vv.z);  s33 = fmaf(f3, s33, kc.w * vv.w);

                float o0 = qc.x * s00; o0 = fmaf(qc.y, s10, o0);
                o0 = fmaf(qc.z, s20, o0); o0 = fmaf(qc.w, s30, o0);
                float o1 = qc.x * s01; o1 = fmaf(qc.y, s11, o1);
                o1 = fmaf(qc.z, s21, o1); o1 = fmaf(qc.w, s31, o1);
                float o2 = qc.x * s02; o2 = fmaf(qc.y, s12, o2);
                o2 = fmaf(qc.z, s22, o2); o2 = fmaf(qc.w, s32, o2);
                float o3 = qc.x * s03; o3 = fmaf(qc.y, s13, o3);
                o3 = fmaf(qc.z, s23, o3); o3 = fmaf(qc.w, s33, o3);

                p[uu * 4 + 0] = o0;  p[uu * 4 + 1] = o1;
                p[uu * 4 + 2] = o2;  p[uu * 4 + 3] = o3;
            }

            // transpose-reduce over the 32 lanes (per-warp buffer, pad 33)
            __syncwarp();
#pragma unroll
            for (int vI = 0; vI < 32; vI++)
                wr[lane * 33 + vI] = p[vI];
            __syncwarp();
            float a0 = 0.f, a1 = 0.f, a2 = 0.f, a3 = 0.f;
#pragma unroll
            for (int i = 0; i < 32; i += 4) {
                a0 += wr[(i + 0) * 33 + lane];
                a1 += wr[(i + 1) * 33 + lane];
                a2 += wr[(i + 2) * 33 + lane];
                a3 += wr[(i + 3) * 33 + lane];
            }
            const float tot = (a0 + a1) + (a2 + a3);

            // lane L owns output (uu = L>>2, j = L&3) of this half
            const int uo = lane >> 2, jo = lane & 3;
            ob[(size_t)(t0 + half * 8 + uo) * EE + jo] = tot * 0.0625f;
        }
    }
}

// ---------------- gate multiply + layernorm -> bf16 hi/lo (unchanged) --------
__global__ void __launch_bounds__(256)
gate_ln_kernel(const float* __restrict__ att, const float* __restrict__ gate,
               const float* __restrict__ nw) {
    const int row = blockIdx.x;
    const int tid = threadIdx.x;
    const int lane = tid & 31, wid = tid >> 5;
    __shared__ float red[8];

    float4 a = ((const float4*)(att + (size_t)row * EE))[tid];
    float4 g = ((const float4*)(gate + (size_t)row * EE))[tid];
    float4 yv;
    yv.x = a.x * g.x; yv.y = a.y * g.y; yv.z = a.z * g.z; yv.w = a.w * g.w;

    float ssum = yv.x + yv.y + yv.z + yv.w;
#pragma unroll
    for (int m = 16; m; m >>= 1) ssum += __shfl_xor_sync(0xffffffffu, ssum, m);
    if (lane == 0) red[wid] = ssum;
    __syncthreads();
    float tot = 0.0f;
#pragma unroll
    for (int w = 0; w < 8; w++) tot += red[w];
    const float mean = tot * (1.0f / (float)EE);
    __syncthreads();

    float dx = yv.x - mean, dy = yv.y - mean, dz = yv.z - mean, dw = yv.w - mean;
    float ssq = dx * dx + dy * dy + dz * dz + dw * dw;
#pragma unroll
    for (int m = 16; m; m >>= 1) ssq += __shfl_xor_sync(0xffffffffu, ssq, m);
    if (lane == 0) red[wid] = ssq;
    __syncthreads();
    float totsq = 0.0f;
#pragma unroll
    for (int w = 0; w < 8; w++) totsq += red[w];
    const float rstd = rsqrtf(totsq * (1.0f / (float)EE) + 1e-5f);

    float4 w4 = ((const float4*)nw)[tid];
    float o0 = dx * rstd * w4.x;
    float o1 = dy * rstd * w4.y;
    float o2 = dz * rstd * w4.z;
    float o3 = dw * rstd * w4.w;

    const size_t base = (size_t)row * EE + tid * 4;
    bf16 h0 = __float2bfloat16(o0), h1 = __float2bfloat16(o1);
    bf16 h2 = __float2bfloat16(o2), h3 = __float2bfloat16(o3);
    *(__nv_bfloat162*)&g_yh[base]     = __nv_bfloat162(h0, h1);
    *(__nv_bfloat162*)&g_yh[base + 2] = __nv_bfloat162(h2, h3);
    *(__nv_bfloat162*)&g_yl[base] = __floats2bfloat162_rn(
        o0 - __bfloat162float(h0), o1 - __bfloat162float(h1));
    *(__nv_bfloat162*)&g_yl[base + 2] = __floats2bfloat162_rn(
        o2 - __bfloat162float(h2), o3 - __bfloat162float(h3));
}

// ---------------- launch ----------------
extern "C" void kernel_launch(void* const* d_in, const int* in_sizes, int n_in,
                              void* d_out, int out_size) {
    const float* x   = (const float*)d_in[0];
    const float* wq  = (const float*)d_in[1];
    const float* wk  = (const float*)d_in[2];
    const float* wv  = (const float*)d_in[3];
    const float* wo  = (const float*)d_in[4];
    const float* wg1 = (const float*)d_in[5];
    const float* wg2 = (const float*)d_in[6];
    const float* nw  = (const float*)d_in[7];
    float* out = (float*)d_out;

    void *pq, *pk, *pv, *patt, *pgate;
    cudaGetSymbolAddress(&pq, g_q);
    cudaGetSymbolAddress(&pk, g_k);
    cudaGetSymbolAddress(&pv, g_v);
    cudaGetSymbolAddress(&patt, g_att);
    cudaGetSymbolAddress(&pgate, g_gate);
    float* fq = (float*)pq;     float* fk = (float*)pk;   float* fv = (float*)pv;
    float* fatt = (float*)patt; float* fgate = (float*)pgate;

    void *pyh, *pyl, *pg1b, *pwoh, *pwol, *pwg2b;
    cudaGetSymbolAddress(&pyh, g_yh);
    cudaGetSymbolAddress(&pyl, g_yl);
    cudaGetSymbolAddress(&pg1b, g_g1b);
    cudaGetSymbolAddress(&pwoh, g_woh);
    cudaGetSymbolAddress(&pwol, g_wol);
    cudaGetSymbolAddress(&pwg2b, g_wg2b);

    cudaFuncSetAttribute(scan_kernel,
                         cudaFuncAttributeMaxDynamicSharedMemorySize,
                         SCAN_SMEM_BYTES);
    cudaFuncSetAttribute(gemm_qkvg,
                         cudaFuncAttributeMaxDynamicSharedMemorySize,
                         SMEM_SPLIT1);
    cudaFuncSetAttribute((const void*)gemm_std<0, 0, 2>,
                         cudaFuncAttributeMaxDynamicSharedMemorySize,
                         SMEM_SPLIT0);
    cudaFuncSetAttribute((const void*)gemm_std<1, 0, 0>,
                         cudaFuncAttributeMaxDynamicSharedMemorySize,
                         SMEM_SPLIT1);

    // 1. pre-split weights and x into bf16 hi/lo
    split_weights<<<EE * EE / 256, 256>>>(wq, wk, wv, wo, wg1, wg2);
    split_x_kernel<<<MM * EE / 1024, 256>>>(x);

    // 2. fused q/k/v + g1 projections (grid 25x64)
    gemm_qkvg<<<dim3(25, MM / GBM), 256, SMEM_SPLIT1>>>(fq, fk, fv);

    // 3. GLA scan v7 (one wave: 128 CTAs, 256 threads)
    scan_kernel<<<dim3(4, HH, BB), 256, SCAN_SMEM_BYTES>>>(fq, fk, fv, fatt);

    // 4. gate = sigmoid(g1 @ wg2)  (plain bf16)
    gemm_std<0, 0, 2><<<dim3(EE / GBN, MM / GBM), 256, SMEM_SPLIT0>>>(
        (const bf16*)pg1b, nullptr, (const bf16*)pwg2b, nullptr,
        fgate, nullptr, EE, DD);

    // 5. gate * att + layernorm -> yh/yl
    gate_ln_kernel<<<MM, 256>>>(fatt, fgate, nw);

    // 6. out = y @ wo  (split bf16)
    gemm_std<1, 0, 0><<<dim3(EE / GBN, MM / GBM), 256, SMEM_SPLIT1>>>(
        (const bf16*)pyh, (const bf16*)pyl, (const bf16*)pwoh, (const bf16*)pwol,
        out, nullptr, EE, EE);
}